// round 1
// baseline (speedup 1.0000x reference)
#include <cuda_runtime.h>
#include <cstddef>

// Problem constants
#define B_  4
#define S_  1024
#define D_  1024
#define F_  4096
#define M_  512
#define H_  16
#define HD_ 64
#define L_  2
#define N_  (B_ * S_)   // 4096 tokens

// ---------------------------------------------------------------------------
// Scratch buffers (static device globals; no allocation at runtime)
// ---------------------------------------------------------------------------
__device__ float g_g [N_ * D_];        // residual stream
__device__ float g_q [N_ * D_];
__device__ float g_k [N_ * D_];
__device__ float g_v [N_ * D_];
__device__ float g_ao[N_ * D_];        // attention output (pre-Wo)
__device__ float g_ff[N_ * F_];        // FFN hidden
__device__ float g_xs[(N_/2) * D_];    // gathered xs for local branches
__device__ float g_mid[(N_/2) * M_];
__device__ float g_mo[(N_/2) * D_];
__device__ float g_y2[(N_/2) * D_];
__device__ float g_y4[(N_/4) * D_];
__device__ float g_os[N_ * D_];        // output = g + local(2) + local(4)
__device__ float g_h [N_ * D_];

// ---------------------------------------------------------------------------
// Elementwise copy (float4)
// ---------------------------------------------------------------------------
__global__ __launch_bounds__(256) void copy4_kernel(const float4* __restrict__ in,
                                                    float4* __restrict__ out, int n4) {
    int i = blockIdx.x * 256 + threadIdx.x;
    if (i < n4) out[i] = in[i];
}

// ---------------------------------------------------------------------------
// SGEMM: C[M,N] = A[M,K] @ W[K,N] + bias[N], optional ReLU.
// BM=BN=128, BK=8, 8x8 per thread, 256 threads. All dims divisible (checked).
// ---------------------------------------------------------------------------
template <bool RELU>
__global__ __launch_bounds__(256) void sgemm_kernel(const float* __restrict__ A,
                                                    const float* __restrict__ W,
                                                    const float* __restrict__ bias,
                                                    float* __restrict__ C,
                                                    int M, int N, int K) {
    const int BM = 128, BN = 128, BK = 8;
    __shared__ float As[BK][BM];   // transposed A tile
    __shared__ float Ws[BK][BN];

    int tid = threadIdx.x;
    int bx = blockIdx.x;   // N tile
    int by = blockIdx.y;   // M tile

    const float* Ab = A + (size_t)by * BM * K;
    const float* Wb = W + (size_t)bx * BN;

    int arow = tid >> 1;           // 0..127
    int acol = (tid & 1) * 4;      // 0 or 4
    int wrow = tid >> 5;           // 0..7
    int wcol = (tid & 31) * 4;     // 0..124

    int m0 = (tid >> 4) * 8;       // 0..120
    int n0 = (tid & 15) * 8;       // 0..120

    float acc[8][8];
#pragma unroll
    for (int i = 0; i < 8; i++)
#pragma unroll
        for (int j = 0; j < 8; j++) acc[i][j] = 0.f;

    for (int kt = 0; kt < K; kt += BK) {
        float4 av = *(const float4*)(Ab + (size_t)arow * K + kt + acol);
        As[acol + 0][arow] = av.x;
        As[acol + 1][arow] = av.y;
        As[acol + 2][arow] = av.z;
        As[acol + 3][arow] = av.w;
        *(float4*)&Ws[wrow][wcol] = *(const float4*)(Wb + (size_t)(kt + wrow) * N + wcol);
        __syncthreads();

#pragma unroll
        for (int k = 0; k < BK; k++) {
            float ra[8], rb[8];
            *(float4*)(ra)     = *(const float4*)&As[k][m0];
            *(float4*)(ra + 4) = *(const float4*)&As[k][m0 + 4];
            *(float4*)(rb)     = *(const float4*)&Ws[k][n0];
            *(float4*)(rb + 4) = *(const float4*)&Ws[k][n0 + 4];
#pragma unroll
            for (int i = 0; i < 8; i++)
#pragma unroll
                for (int j = 0; j < 8; j++) acc[i][j] += ra[i] * rb[j];
        }
        __syncthreads();
    }

#pragma unroll
    for (int i = 0; i < 8; i++) {
        size_t crow = (size_t)(by * BM + m0 + i) * N + bx * BN + n0;
#pragma unroll
        for (int j = 0; j < 8; j += 4) {
            float4 bv = *(const float4*)(bias + bx * BN + n0 + j);
            float4 o;
            o.x = acc[i][j + 0] + bv.x;
            o.y = acc[i][j + 1] + bv.y;
            o.z = acc[i][j + 2] + bv.z;
            o.w = acc[i][j + 3] + bv.w;
            if (RELU) {
                o.x = fmaxf(o.x, 0.f); o.y = fmaxf(o.y, 0.f);
                o.z = fmaxf(o.z, 0.f); o.w = fmaxf(o.w, 0.f);
            }
            *(float4*)(C + crow + j) = o;
        }
    }
}

// ---------------------------------------------------------------------------
// Flash attention, fp32. Grid: (B*H, S/64), 256 threads.
// Q/K/V/O layout: [N, D] rows = token, head h at column offset h*64.
// Shared (dynamic): Qs[64][65], KVs[64][65], Ps[64][65], m/l/alpha[64].
// ---------------------------------------------------------------------------
#define ATTN_STRIDE 65
#define ATTN_SMEM_FLOATS (3 * 64 * ATTN_STRIDE + 3 * 64)

__device__ __forceinline__ void attn_load_tile(const float* __restrict__ src, size_t base,
                                               float* __restrict__ dst, int tid) {
#pragma unroll
    for (int r = 0; r < 4; r++) {
        int idx = tid + r * 256;        // 0..1023 float4 slots
        int row = idx >> 4;             // 0..63
        int col = (idx & 15) << 2;      // 0..60
        float4 v = *(const float4*)(src + base + (size_t)row * D_ + col);
        float* d = dst + row * ATTN_STRIDE + col;
        d[0] = v.x; d[1] = v.y; d[2] = v.z; d[3] = v.w;
    }
}

__global__ __launch_bounds__(256) void attn_kernel(const float* __restrict__ Q,
                                                   const float* __restrict__ Kp,
                                                   const float* __restrict__ Vp,
                                                   float* __restrict__ O) {
    extern __shared__ float sm[];
    float* Qs  = sm;
    float* KVs = sm + 64 * ATTN_STRIDE;
    float* Ps  = sm + 2 * 64 * ATTN_STRIDE;
    float* m_s = sm + 3 * 64 * ATTN_STRIDE;
    float* l_s = m_s + 64;
    float* a_s = l_s + 64;

    int tid = threadIdx.x;
    int b = blockIdx.x >> 4;
    int h = blockIdx.x & 15;
    int q0 = blockIdx.y * 64;

    size_t base_q = ((size_t)(b * S_ + q0)) * D_ + h * HD_;
    attn_load_tile(Q, base_q, Qs, tid);
    if (tid < 64) { m_s[tid] = -1e30f; l_s[tid] = 0.f; }

    int ty = tid >> 4, tx = tid & 15;
    int i0 = ty * 4, j0 = tx * 4;
    float o[4][4];
#pragma unroll
    for (int i = 0; i < 4; i++)
#pragma unroll
        for (int j = 0; j < 4; j++) o[i][j] = 0.f;

    for (int kt = 0; kt < 16; kt++) {
        size_t base_kv = ((size_t)(b * S_ + kt * 64)) * D_ + h * HD_;
        attn_load_tile(Kp, base_kv, KVs, tid);
        __syncthreads();

        // S = Q . K^T (scaled)
        float s4[4][4];
#pragma unroll
        for (int i = 0; i < 4; i++)
#pragma unroll
            for (int j = 0; j < 4; j++) s4[i][j] = 0.f;
#pragma unroll
        for (int k = 0; k < 64; k++) {
            float ra[4], rb[4];
#pragma unroll
            for (int i = 0; i < 4; i++) ra[i] = Qs[(i0 + i) * ATTN_STRIDE + k];
#pragma unroll
            for (int j = 0; j < 4; j++) rb[j] = KVs[(j0 + j) * ATTN_STRIDE + k];
#pragma unroll
            for (int i = 0; i < 4; i++)
#pragma unroll
                for (int j = 0; j < 4; j++) s4[i][j] += ra[i] * rb[j];
        }
#pragma unroll
        for (int i = 0; i < 4; i++)
#pragma unroll
            for (int j = 0; j < 4; j++)
                Ps[(i0 + i) * ATTN_STRIDE + j0 + j] = s4[i][j] * 0.125f;
        __syncthreads();

        // load V into KVs (K no longer needed); softmax bookkeeping on Ps
        attn_load_tile(Vp, base_kv, KVs, tid);
        if (tid < 64) {
            int r = tid;
            float mx = m_s[r];
#pragma unroll 8
            for (int j = 0; j < 64; j++) mx = fmaxf(mx, Ps[r * ATTN_STRIDE + j]);
            float al = __expf(m_s[r] - mx);
            float sum = 0.f;
#pragma unroll 8
            for (int j = 0; j < 64; j++) {
                float e = __expf(Ps[r * ATTN_STRIDE + j] - mx);
                Ps[r * ATTN_STRIDE + j] = e;
                sum += e;
            }
            l_s[r] = l_s[r] * al + sum;
            m_s[r] = mx;
            a_s[r] = al;
        }
        __syncthreads();

        // O = O*alpha + P.V
        float al_i[4];
#pragma unroll
        for (int i = 0; i < 4; i++) al_i[i] = a_s[i0 + i];
#pragma unroll
        for (int i = 0; i < 4; i++)
#pragma unroll
            for (int j = 0; j < 4; j++) o[i][j] *= al_i[i];
#pragma unroll
        for (int k = 0; k < 64; k++) {
            float ra[4], rb[4];
#pragma unroll
            for (int i = 0; i < 4; i++) ra[i] = Ps[(i0 + i) * ATTN_STRIDE + k];
#pragma unroll
            for (int j = 0; j < 4; j++) rb[j] = KVs[k * ATTN_STRIDE + j0 + j];
#pragma unroll
            for (int i = 0; i < 4; i++)
#pragma unroll
                for (int j = 0; j < 4; j++) o[i][j] += ra[i] * rb[j];
        }
        __syncthreads();
    }

    float inv[4];
#pragma unroll
    for (int i = 0; i < 4; i++) inv[i] = 1.f / l_s[i0 + i];
#pragma unroll
    for (int i = 0; i < 4; i++)
#pragma unroll
        for (int j = 0; j < 4; j++)
            O[base_q + (size_t)(i0 + i) * D_ + j0 + j] = o[i][j] * inv[i];
}

// ---------------------------------------------------------------------------
// Fused residual + LayerNorm: out = LN(res + delta) * gamma + beta
// One block (256 threads) per row of D_=1024. In-place safe (out == res ok).
// ---------------------------------------------------------------------------
__global__ __launch_bounds__(256) void ln_kernel(const float* __restrict__ res,
                                                 const float* __restrict__ delta,
                                                 const float* __restrict__ gamma,
                                                 const float* __restrict__ beta,
                                                 float* __restrict__ out) {
    int row = blockIdx.x, tid = threadIdx.x;
    size_t base = (size_t)row * D_;
    float4 rv = *(const float4*)(res + base + tid * 4);
    float4 dv = *(const float4*)(delta + base + tid * 4);
    float v0 = rv.x + dv.x, v1 = rv.y + dv.y, v2 = rv.z + dv.z, v3 = rv.w + dv.w;
    float s = v0 + v1 + v2 + v3;
    float q = v0 * v0 + v1 * v1 + v2 * v2 + v3 * v3;
#pragma unroll
    for (int o2 = 16; o2 > 0; o2 >>= 1) {
        s += __shfl_xor_sync(0xffffffffu, s, o2);
        q += __shfl_xor_sync(0xffffffffu, q, o2);
    }
    __shared__ float ss[8], qs[8];
    __shared__ float mean_s, rstd_s;
    if ((tid & 31) == 0) { ss[tid >> 5] = s; qs[tid >> 5] = q; }
    __syncthreads();
    if (tid == 0) {
        float S2 = 0.f, Q2 = 0.f;
#pragma unroll
        for (int w = 0; w < 8; w++) { S2 += ss[w]; Q2 += qs[w]; }
        float mean = S2 * (1.0f / D_);
        float var = Q2 * (1.0f / D_) - mean * mean;
        mean_s = mean;
        rstd_s = rsqrtf(var + 1e-5f);
    }
    __syncthreads();
    float mean = mean_s, rstd = rstd_s;
    float4 gv = *(const float4*)(gamma + tid * 4);
    float4 bv = *(const float4*)(beta + tid * 4);
    float4 ov;
    ov.x = (v0 - mean) * rstd * gv.x + bv.x;
    ov.y = (v1 - mean) * rstd * gv.y + bv.y;
    ov.z = (v2 - mean) * rstd * gv.z + bv.z;
    ov.w = (v3 - mean) * rstd * gv.w + bv.w;
    *(float4*)(out + base + tid * 4) = ov;
}

// ---------------------------------------------------------------------------
// Gather last `st` tokens per batch from x into contiguous xs [B*st, D]
// ---------------------------------------------------------------------------
__global__ __launch_bounds__(256) void gather_kernel(const float* __restrict__ x,
                                                     float* __restrict__ xs, int st) {
    int i = blockIdx.x * 256 + threadIdx.x;   // float4 index
    int row = i >> 8;                          // D/4 = 256 float4 per row
    int c = i & 255;
    int b = row / st, sl = row % st;
    size_t src = ((size_t)(b * S_ + (S_ - st) + sl) << 8) + c;
    *(float4*)(xs) = *(float4*)(xs);           // no-op guard removed below
    ((float4*)xs)[i] = ((const float4*)x)[src];
}

// ---------------------------------------------------------------------------
// output = g + pad(local2) + pad(local4)
// ---------------------------------------------------------------------------
__global__ __launch_bounds__(256) void combine_kernel(const float* __restrict__ g,
                                                      const float* __restrict__ y2,
                                                      const float* __restrict__ y4,
                                                      float* __restrict__ out) {
    int i = blockIdx.x * 256 + threadIdx.x;   // float4 index over N_*D_/4
    int row = i >> 8;
    int c = i & 255;
    int b = row >> 10;
    int s = row & 1023;
    float4 v = ((const float4*)g)[i];
    if (s >= 512) {
        float4 a = ((const float4*)y2)[((size_t)(b * 512 + (s - 512)) << 8) + c];
        v.x += a.x; v.y += a.y; v.z += a.z; v.w += a.w;
    }
    if (s >= 768) {
        float4 a = ((const float4*)y4)[((size_t)(b * 256 + (s - 768)) << 8) + c];
        v.x += a.x; v.y += a.y; v.z += a.z; v.w += a.w;
    }
    ((float4*)out)[i] = v;
}

// ---------------------------------------------------------------------------
// Host orchestration
// ---------------------------------------------------------------------------
static void launch_gemm(const float* A, const float* W, const float* bias, float* C,
                        int M, int N, int K, bool relu) {
    dim3 grid(N / 128, M / 128);
    if (relu) sgemm_kernel<true><<<grid, 256>>>(A, W, bias, C, M, N, K);
    else      sgemm_kernel<false><<<grid, 256>>>(A, W, bias, C, M, N, K);
}

extern "C" void kernel_launch(void* const* d_in, const int* in_sizes, int n_in,
                              void* d_out, int out_size) {
    (void)in_sizes; (void)n_in; (void)out_size;
    const float* x    = (const float*)d_in[0];
    const float* Wq   = (const float*)d_in[1];
    const float* bq   = (const float*)d_in[2];
    const float* Wk   = (const float*)d_in[3];
    const float* bk   = (const float*)d_in[4];
    const float* Wv   = (const float*)d_in[5];
    const float* bv   = (const float*)d_in[6];
    const float* Wo   = (const float*)d_in[7];
    const float* bo   = (const float*)d_in[8];
    const float* W1   = (const float*)d_in[9];
    const float* b1   = (const float*)d_in[10];
    const float* W2   = (const float*)d_in[11];
    const float* b2   = (const float*)d_in[12];
    const float* n1s  = (const float*)d_in[13];
    const float* n1b  = (const float*)d_in[14];
    const float* n2s  = (const float*)d_in[15];
    const float* n2b  = (const float*)d_in[16];
    const float* ln1s = (const float*)d_in[17];
    const float* ln1b = (const float*)d_in[18];
    const float* ln2s = (const float*)d_in[19];
    const float* ln2b = (const float*)d_in[20];
    const float* ln3s = (const float*)d_in[21];
    const float* ln3b = (const float*)d_in[22];
    const float* Wb   = (const float*)d_in[23];
    const float* bb   = (const float*)d_in[24];
    const float* Wm   = (const float*)d_in[25];
    const float* bm   = (const float*)d_in[26];
    const float* Wf1  = (const float*)d_in[27];
    const float* bf1  = (const float*)d_in[28];
    const float* Wf2  = (const float*)d_in[29];
    const float* bf2  = (const float*)d_in[30];
    float* out = (float*)d_out;

    float *g, *q, *k, *v, *ao, *ff, *xs, *mid, *mo, *y2, *y4, *os, *h;
    cudaGetSymbolAddress((void**)&g,  g_g);
    cudaGetSymbolAddress((void**)&q,  g_q);
    cudaGetSymbolAddress((void**)&k,  g_k);
    cudaGetSymbolAddress((void**)&v,  g_v);
    cudaGetSymbolAddress((void**)&ao, g_ao);
    cudaGetSymbolAddress((void**)&ff, g_ff);
    cudaGetSymbolAddress((void**)&xs, g_xs);
    cudaGetSymbolAddress((void**)&mid, g_mid);
    cudaGetSymbolAddress((void**)&mo, g_mo);
    cudaGetSymbolAddress((void**)&y2, g_y2);
    cudaGetSymbolAddress((void**)&y4, g_y4);
    cudaGetSymbolAddress((void**)&os, g_os);
    cudaGetSymbolAddress((void**)&h,  g_h);

    const int ATTN_SMEM = ATTN_SMEM_FLOATS * (int)sizeof(float);
    cudaFuncSetAttribute(attn_kernel, cudaFuncAttributeMaxDynamicSharedMemorySize, ATTN_SMEM);

    // g = x
    copy4_kernel<<<(N_ * D_ / 4 + 255) / 256, 256>>>((const float4*)x, (float4*)g, N_ * D_ / 4);

    const int DD = D_ * D_;
    const int DF = D_ * F_;
    for (int i = 0; i < L_; i++) {
        // Q, K, V projections
        launch_gemm(g, Wq + (size_t)i * DD, bq + i * D_, q, N_, D_, D_, false);
        launch_gemm(g, Wk + (size_t)i * DD, bk + i * D_, k, N_, D_, D_, false);
        launch_gemm(g, Wv + (size_t)i * DD, bv + i * D_, v, N_, D_, D_, false);
        // attention
        attn_kernel<<<dim3(B_ * H_, S_ / 64), 256, ATTN_SMEM>>>(q, k, v, ao);
        // output projection -> q (scratch)
        launch_gemm(ao, Wo + (size_t)i * DD, bo + i * D_, q, N_, D_, D_, false);
        // g = LN(g + attn)
        ln_kernel<<<N_, 256>>>(g, q, n1s + i * D_, n1b + i * D_, g);
        // FFN
        launch_gemm(g, W1 + (size_t)i * DF, b1 + i * F_, ff, N_, F_, D_, true);
        launch_gemm(ff, W2 + (size_t)i * DF, b2 + i * D_, q, N_, D_, F_, false);
        // g = LN(g + ff)
        ln_kernel<<<N_, 256>>>(g, q, n2s + i * D_, n2b + i * D_, g);
    }

    // local(2): st = 512
    {
        const int st = 512, R = B_ * st;                    // 2048 rows
        gather_kernel<<<R * 256 / 256, 256>>>(x, xs, st);
        launch_gemm(xs, Wb, bb, mid, R, M_, D_, false);
        launch_gemm(mid, Wm, bm, mo, R, D_, M_, false);
        ln_kernel<<<R, 256>>>(xs, mo, ln1s, ln1b, y2);
    }
    // local(4): st = 256
    {
        const int st = 256, R = B_ * st;                    // 1024 rows
        gather_kernel<<<R * 256 / 256, 256>>>(x, xs, st);
        launch_gemm(xs, Wb, bb, mid, R, M_, D_, false);
        launch_gemm(mid, Wm, bm, mo, R, D_, M_, false);
        ln_kernel<<<R, 256>>>(xs, mo, ln1s, ln1b, y4);
    }

    // output = g + pad(y2) + pad(y4)
    combine_kernel<<<N_ * D_ / 4 / 256, 256>>>(g, y2, y4, os);
    // h = LN(output + x)
    ln_kernel<<<N_, 256>>>(os, x, ln2s, ln2b, h);
    // ff = relu(output @ Wf1 + bf1) @ Wf2 + bf2  -> q (scratch)
    launch_gemm(os, Wf1, bf1, ff, N_, F_, D_, true);
    launch_gemm(ff, Wf2, bf2, q, N_, D_, F_, false);
    // out = LN(h + ff)
    ln_kernel<<<N_, 256>>>(h, q, ln3s, ln3b, out);
}

// round 2
// speedup vs baseline: 1.2402x; 1.2402x over previous
#include <cuda_runtime.h>
#include <cstdint>
#include <cstddef>

// Problem constants
#define B_  4
#define S_  1024
#define D_  1024
#define F_  4096
#define M_  512
#define H_  16
#define HD_ 64
#define L_  2
#define N_  (B_ * S_)   // 4096 tokens

// ---------------------------------------------------------------------------
// Scratch buffers (static device globals; no allocation at runtime)
// ---------------------------------------------------------------------------
__device__ float g_g [N_ * D_];
__device__ float g_q [N_ * D_];
__device__ float g_k [N_ * D_];
__device__ float g_v [N_ * D_];
__device__ float g_ao[N_ * D_];
__device__ float g_ff[N_ * F_];
__device__ float g_xs[(N_/2) * D_];
__device__ float g_mid[(N_/2) * M_];
__device__ float g_mo[(N_/2) * D_];
__device__ float g_y2[(N_/2) * D_];
__device__ float g_y4[(N_/4) * D_];
__device__ float g_os[N_ * D_];
__device__ float g_h [N_ * D_];

// ---------------------------------------------------------------------------
// Elementwise copy (float4)
// ---------------------------------------------------------------------------
__global__ __launch_bounds__(256) void copy4_kernel(const float4* __restrict__ in,
                                                    float4* __restrict__ out, int n4) {
    int i = blockIdx.x * 256 + threadIdx.x;
    if (i < n4) out[i] = in[i];
}

// ---------------------------------------------------------------------------
// TF32 tensor-core GEMM: C[M,N] = A[M,K] @ W[K,N] + bias[N], optional ReLU.
// CTA tile 128x128x16, 256 threads = 8 warps (2 m x 4 n), warp tile 64x32.
// mma.sync.aligned.m16n8k8 tf32, fp32 accumulate.
// Permuted smem layouts: each fragment group = one LDS.128.
// ---------------------------------------------------------------------------
__device__ __forceinline__ uint32_t f2tf32(float f) {
    uint32_t r;
    asm("cvt.rna.tf32.f32 %0, %1;" : "=r"(r) : "f"(f));
    return r;
}

// A-element (row m in 0..127, k_local in 0..15) -> word index in 2048-word buffer
__device__ __forceinline__ int a_addr(int k_local, int row) {
    int k8 = k_local >> 3, t4 = k_local & 3, hik = (k_local >> 2) & 1;
    int mg = row >> 4, r = row & 15, gg = r & 7, him = r >> 3;
    return (((k8 * 8 + mg) * 32) + (t4 * 8 + gg)) * 4 + him + 2 * hik;
}
// W-element (k_local 0..15, n_local 0..127) -> word index in 2048-word buffer
__device__ __forceinline__ int w_addr(int k_local, int n_local) {
    int k8 = k_local >> 3, t4 = k_local & 3, hik = (k_local >> 2) & 1;
    int ng = n_local >> 4, cc = n_local & 15, jj2 = cc >> 3, gg = cc & 7;
    return (((k8 * 8 + ng) * 32) + (t4 * 8 + gg)) * 4 + hik + 2 * jj2;
}

__device__ __forceinline__ void mma_tf32(float* c, uint32_t a0, uint32_t a1,
                                         uint32_t a2, uint32_t a3,
                                         uint32_t b0, uint32_t b1) {
    asm volatile(
        "mma.sync.aligned.m16n8k8.row.col.f32.tf32.tf32.f32 "
        "{%0,%1,%2,%3}, {%4,%5,%6,%7}, {%8,%9}, {%0,%1,%2,%3};"
        : "+f"(c[0]), "+f"(c[1]), "+f"(c[2]), "+f"(c[3])
        : "r"(a0), "r"(a1), "r"(a2), "r"(a3), "r"(b0), "r"(b1));
}

template <bool RELU>
__global__ __launch_bounds__(256, 2) void mma_gemm_kernel(const float* __restrict__ A,
                                                          const float* __restrict__ W,
                                                          const float* __restrict__ bias,
                                                          float* __restrict__ C,
                                                          int M, int N, int K) {
    __shared__ uint32_t sm[8192];   // 2 stages x (2048 A + 2048 W) words = 32KB

    int tid = threadIdx.x;
    int bx = blockIdx.x, by = blockIdx.y;
    int wid = tid >> 5, lane = tid & 31;
    int warp_m = wid >> 2;          // 0..1 -> 64 rows each
    int warp_n = wid & 3;           // 0..3 -> 32 cols each
    int g = lane >> 2, t4 = lane & 3;
    int p = t4 * 8 + g;             // permuted lane slot

    // ---- global loader addressing ----
    int ar = tid >> 1;              // A row 0..127
    int ak = (tid & 1) * 8;         // A k-offset 0 or 8
    const float* Aptr = A + (size_t)(by * 128 + ar) * K + ak;

    int kr0 = tid >> 5;             // W chunk 0: k-row 0..7
    int n40 = (tid & 31) << 2;
    int kr1 = (tid + 256) >> 5;     // W chunk 1: k-row 8..15
    int n41 = n40;
    const float* Wg = W + (size_t)bx * 128;

    // precomputed scatter addresses (compile-time folded per thread)
    int aw[8], ww0[4], ww1[4];
#pragma unroll
    for (int i = 0; i < 8; i++) aw[i] = a_addr(ak + i, ar);
#pragma unroll
    for (int j = 0; j < 4; j++) { ww0[j] = w_addr(kr0, n40 + j); ww1[j] = w_addr(kr1, n41 + j); }

    float4 ra0, ra1, rw0, rw1;

    auto load_tile = [&](int kt) {
        ra0 = *(const float4*)(Aptr + kt);
        ra1 = *(const float4*)(Aptr + kt + 4);
        rw0 = *(const float4*)(Wg + (size_t)(kt + kr0) * N + n40);
        rw1 = *(const float4*)(Wg + (size_t)(kt + kr1) * N + n41);
    };
    auto store_tile = [&](int s) {
        uint32_t* dA = sm + s * 4096;
        uint32_t* dB = dA + 2048;
        dA[aw[0]] = f2tf32(ra0.x); dA[aw[1]] = f2tf32(ra0.y);
        dA[aw[2]] = f2tf32(ra0.z); dA[aw[3]] = f2tf32(ra0.w);
        dA[aw[4]] = f2tf32(ra1.x); dA[aw[5]] = f2tf32(ra1.y);
        dA[aw[6]] = f2tf32(ra1.z); dA[aw[7]] = f2tf32(ra1.w);
        dB[ww0[0]] = f2tf32(rw0.x); dB[ww0[1]] = f2tf32(rw0.y);
        dB[ww0[2]] = f2tf32(rw0.z); dB[ww0[3]] = f2tf32(rw0.w);
        dB[ww1[0]] = f2tf32(rw1.x); dB[ww1[1]] = f2tf32(rw1.y);
        dB[ww1[2]] = f2tf32(rw1.z); dB[ww1[3]] = f2tf32(rw1.w);
    };

    float acc[4][4][4];
#pragma unroll
    for (int mi = 0; mi < 4; mi++)
#pragma unroll
        for (int jj = 0; jj < 4; jj++)
#pragma unroll
            for (int e = 0; e < 4; e++) acc[mi][jj][e] = 0.f;

    int nk = K >> 4;
    load_tile(0);
    store_tile(0);
    __syncthreads();

    for (int t = 0; t < nk; t++) {
        if (t + 1 < nk) load_tile((t + 1) << 4);

        uint32_t* smA = sm + (t & 1) * 4096;
        uint32_t* smB = smA + 2048;
#pragma unroll
        for (int k8 = 0; k8 < 2; k8++) {
            uint4 af[4], bf[2];
#pragma unroll
            for (int mi = 0; mi < 4; mi++)
                af[mi] = *(const uint4*)&smA[(((k8 * 8) + warp_m * 4 + mi) * 32 + p) * 4];
#pragma unroll
            for (int np = 0; np < 2; np++)
                bf[np] = *(const uint4*)&smB[(((k8 * 8) + warp_n * 2 + np) * 32 + p) * 4];
#pragma unroll
            for (int mi = 0; mi < 4; mi++) {
                mma_tf32(acc[mi][0], af[mi].x, af[mi].y, af[mi].z, af[mi].w, bf[0].x, bf[0].y);
                mma_tf32(acc[mi][1], af[mi].x, af[mi].y, af[mi].z, af[mi].w, bf[0].z, bf[0].w);
                mma_tf32(acc[mi][2], af[mi].x, af[mi].y, af[mi].z, af[mi].w, bf[1].x, bf[1].y);
                mma_tf32(acc[mi][3], af[mi].x, af[mi].y, af[mi].z, af[mi].w, bf[1].z, bf[1].w);
            }
        }

        if (t + 1 < nk) {
            store_tile((t + 1) & 1);
            __syncthreads();
        }
    }

    // epilogue
    int row0 = by * 128 + warp_m * 64;
    int col0 = bx * 128 + warp_n * 32;
#pragma unroll
    for (int jj = 0; jj < 4; jj++) {
        int cc = col0 + jj * 8 + t4 * 2;
        float b0 = bias[cc], b1 = bias[cc + 1];
#pragma unroll
        for (int mi = 0; mi < 4; mi++) {
            int r = row0 + mi * 16 + g;
            float2 v0 = make_float2(acc[mi][jj][0] + b0, acc[mi][jj][1] + b1);
            float2 v1 = make_float2(acc[mi][jj][2] + b0, acc[mi][jj][3] + b1);
            if (RELU) {
                v0.x = fmaxf(v0.x, 0.f); v0.y = fmaxf(v0.y, 0.f);
                v1.x = fmaxf(v1.x, 0.f); v1.y = fmaxf(v1.y, 0.f);
            }
            *(float2*)(C + (size_t)r * N + cc) = v0;
            *(float2*)(C + (size_t)(r + 8) * N + cc) = v1;
        }
    }
}

// ---------------------------------------------------------------------------
// Flash attention, fp32. Grid: (B*H, S/64), 256 threads.
// ---------------------------------------------------------------------------
#define ATTN_STRIDE 65
#define ATTN_SMEM_FLOATS (3 * 64 * ATTN_STRIDE + 3 * 64)

__device__ __forceinline__ void attn_load_tile(const float* __restrict__ src, size_t base,
                                               float* __restrict__ dst, int tid) {
#pragma unroll
    for (int r = 0; r < 4; r++) {
        int idx = tid + r * 256;
        int row = idx >> 4;
        int col = (idx & 15) << 2;
        float4 v = *(const float4*)(src + base + (size_t)row * D_ + col);
        float* d = dst + row * ATTN_STRIDE + col;
        d[0] = v.x; d[1] = v.y; d[2] = v.z; d[3] = v.w;
    }
}

__global__ __launch_bounds__(256) void attn_kernel(const float* __restrict__ Q,
                                                   const float* __restrict__ Kp,
                                                   const float* __restrict__ Vp,
                                                   float* __restrict__ O) {
    extern __shared__ float smf[];
    float* Qs  = smf;
    float* KVs = smf + 64 * ATTN_STRIDE;
    float* Ps  = smf + 2 * 64 * ATTN_STRIDE;
    float* m_s = smf + 3 * 64 * ATTN_STRIDE;
    float* l_s = m_s + 64;
    float* a_s = l_s + 64;

    int tid = threadIdx.x;
    int b = blockIdx.x >> 4;
    int h = blockIdx.x & 15;
    int q0 = blockIdx.y * 64;

    size_t base_q = ((size_t)(b * S_ + q0)) * D_ + h * HD_;
    attn_load_tile(Q, base_q, Qs, tid);
    if (tid < 64) { m_s[tid] = -1e30f; l_s[tid] = 0.f; }

    int ty = tid >> 4, tx = tid & 15;
    int i0 = ty * 4, j0 = tx * 4;
    float o[4][4];
#pragma unroll
    for (int i = 0; i < 4; i++)
#pragma unroll
        for (int j = 0; j < 4; j++) o[i][j] = 0.f;

    for (int kt = 0; kt < 16; kt++) {
        size_t base_kv = ((size_t)(b * S_ + kt * 64)) * D_ + h * HD_;
        attn_load_tile(Kp, base_kv, KVs, tid);
        __syncthreads();

        float s4[4][4];
#pragma unroll
        for (int i = 0; i < 4; i++)
#pragma unroll
            for (int j = 0; j < 4; j++) s4[i][j] = 0.f;
#pragma unroll
        for (int k = 0; k < 64; k++) {
            float ra[4], rb[4];
#pragma unroll
            for (int i = 0; i < 4; i++) ra[i] = Qs[(i0 + i) * ATTN_STRIDE + k];
#pragma unroll
            for (int j = 0; j < 4; j++) rb[j] = KVs[(j0 + j) * ATTN_STRIDE + k];
#pragma unroll
            for (int i = 0; i < 4; i++)
#pragma unroll
                for (int j = 0; j < 4; j++) s4[i][j] += ra[i] * rb[j];
        }
#pragma unroll
        for (int i = 0; i < 4; i++)
#pragma unroll
            for (int j = 0; j < 4; j++)
                Ps[(i0 + i) * ATTN_STRIDE + j0 + j] = s4[i][j] * 0.125f;
        __syncthreads();

        attn_load_tile(Vp, base_kv, KVs, tid);
        if (tid < 64) {
            int r = tid;
            float mx = m_s[r];
#pragma unroll 8
            for (int j = 0; j < 64; j++) mx = fmaxf(mx, Ps[r * ATTN_STRIDE + j]);
            float al = __expf(m_s[r] - mx);
            float sum = 0.f;
#pragma unroll 8
            for (int j = 0; j < 64; j++) {
                float e = __expf(Ps[r * ATTN_STRIDE + j] - mx);
                Ps[r * ATTN_STRIDE + j] = e;
                sum += e;
            }
            l_s[r] = l_s[r] * al + sum;
            m_s[r] = mx;
            a_s[r] = al;
        }
        __syncthreads();

        float al_i[4];
#pragma unroll
        for (int i = 0; i < 4; i++) al_i[i] = a_s[i0 + i];
#pragma unroll
        for (int i = 0; i < 4; i++)
#pragma unroll
            for (int j = 0; j < 4; j++) o[i][j] *= al_i[i];
#pragma unroll
        for (int k = 0; k < 64; k++) {
            float ra[4], rb[4];
#pragma unroll
            for (int i = 0; i < 4; i++) ra[i] = Ps[(i0 + i) * ATTN_STRIDE + k];
#pragma unroll
            for (int j = 0; j < 4; j++) rb[j] = KVs[k * ATTN_STRIDE + j0 + j];
#pragma unroll
            for (int i = 0; i < 4; i++)
#pragma unroll
                for (int j = 0; j < 4; j++) o[i][j] += ra[i] * rb[j];
        }
        __syncthreads();
    }

    float inv[4];
#pragma unroll
    for (int i = 0; i < 4; i++) inv[i] = 1.f / l_s[i0 + i];
#pragma unroll
    for (int i = 0; i < 4; i++)
#pragma unroll
        for (int j = 0; j < 4; j++)
            O[base_q + (size_t)(i0 + i) * D_ + j0 + j] = o[i][j] * inv[i];
}

// ---------------------------------------------------------------------------
// Fused residual + LayerNorm: out = LN(res + delta) * gamma + beta
// ---------------------------------------------------------------------------
__global__ __launch_bounds__(256) void ln_kernel(const float* __restrict__ res,
                                                 const float* __restrict__ delta,
                                                 const float* __restrict__ gamma,
                                                 const float* __restrict__ beta,
                                                 float* __restrict__ out) {
    int row = blockIdx.x, tid = threadIdx.x;
    size_t base = (size_t)row * D_;
    float4 rv = *(const float4*)(res + base + tid * 4);
    float4 dv = *(const float4*)(delta + base + tid * 4);
    float v0 = rv.x + dv.x, v1 = rv.y + dv.y, v2 = rv.z + dv.z, v3 = rv.w + dv.w;
    float s = v0 + v1 + v2 + v3;
    float q = v0 * v0 + v1 * v1 + v2 * v2 + v3 * v3;
#pragma unroll
    for (int o2 = 16; o2 > 0; o2 >>= 1) {
        s += __shfl_xor_sync(0xffffffffu, s, o2);
        q += __shfl_xor_sync(0xffffffffu, q, o2);
    }
    __shared__ float ss[8], qs[8];
    __shared__ float mean_s, rstd_s;
    if ((tid & 31) == 0) { ss[tid >> 5] = s; qs[tid >> 5] = q; }
    __syncthreads();
    if (tid == 0) {
        float S2 = 0.f, Q2 = 0.f;
#pragma unroll
        for (int w = 0; w < 8; w++) { S2 += ss[w]; Q2 += qs[w]; }
        float mean = S2 * (1.0f / D_);
        float var = Q2 * (1.0f / D_) - mean * mean;
        mean_s = mean;
        rstd_s = rsqrtf(var + 1e-5f);
    }
    __syncthreads();
    float mean = mean_s, rstd = rstd_s;
    float4 gv = *(const float4*)(gamma + tid * 4);
    float4 bv = *(const float4*)(beta + tid * 4);
    float4 ov;
    ov.x = (v0 - mean) * rstd * gv.x + bv.x;
    ov.y = (v1 - mean) * rstd * gv.y + bv.y;
    ov.z = (v2 - mean) * rstd * gv.z + bv.z;
    ov.w = (v3 - mean) * rstd * gv.w + bv.w;
    *(float4*)(out + base + tid * 4) = ov;
}

// ---------------------------------------------------------------------------
// Gather last `st` tokens per batch from x into contiguous xs [B*st, D]
// ---------------------------------------------------------------------------
__global__ __launch_bounds__(256) void gather_kernel(const float* __restrict__ x,
                                                     float* __restrict__ xs, int st) {
    int i = blockIdx.x * 256 + threadIdx.x;
    int row = i >> 8;
    int c = i & 255;
    int b = row / st, sl = row % st;
    size_t src = ((size_t)(b * S_ + (S_ - st) + sl) << 8) + c;
    ((float4*)xs)[i] = ((const float4*)x)[src];
}

// ---------------------------------------------------------------------------
// output = g + pad(local2) + pad(local4)
// ---------------------------------------------------------------------------
__global__ __launch_bounds__(256) void combine_kernel(const float* __restrict__ g,
                                                      const float* __restrict__ y2,
                                                      const float* __restrict__ y4,
                                                      float* __restrict__ out) {
    int i = blockIdx.x * 256 + threadIdx.x;
    int row = i >> 8;
    int c = i & 255;
    int b = row >> 10;
    int s = row & 1023;
    float4 v = ((const float4*)g)[i];
    if (s >= 512) {
        float4 a = ((const float4*)y2)[((size_t)(b * 512 + (s - 512)) << 8) + c];
        v.x += a.x; v.y += a.y; v.z += a.z; v.w += a.w;
    }
    if (s >= 768) {
        float4 a = ((const float4*)y4)[((size_t)(b * 256 + (s - 768)) << 8) + c];
        v.x += a.x; v.y += a.y; v.z += a.z; v.w += a.w;
    }
    ((float4*)out)[i] = v;
}

// ---------------------------------------------------------------------------
// Host orchestration
// ---------------------------------------------------------------------------
static void launch_gemm(const float* A, const float* W, const float* bias, float* C,
                        int M, int N, int K, bool relu) {
    dim3 grid(N / 128, M / 128);
    if (relu) mma_gemm_kernel<true><<<grid, 256>>>(A, W, bias, C, M, N, K);
    else      mma_gemm_kernel<false><<<grid, 256>>>(A, W, bias, C, M, N, K);
}

extern "C" void kernel_launch(void* const* d_in, const int* in_sizes, int n_in,
                              void* d_out, int out_size) {
    (void)in_sizes; (void)n_in; (void)out_size;
    const float* x    = (const float*)d_in[0];
    const float* Wq   = (const float*)d_in[1];
    const float* bq   = (const float*)d_in[2];
    const float* Wk   = (const float*)d_in[3];
    const float* bk   = (const float*)d_in[4];
    const float* Wv   = (const float*)d_in[5];
    const float* bv   = (const float*)d_in[6];
    const float* Wo   = (const float*)d_in[7];
    const float* bo   = (const float*)d_in[8];
    const float* W1   = (const float*)d_in[9];
    const float* b1   = (const float*)d_in[10];
    const float* W2   = (const float*)d_in[11];
    const float* b2   = (const float*)d_in[12];
    const float* n1s  = (const float*)d_in[13];
    const float* n1b  = (const float*)d_in[14];
    const float* n2s  = (const float*)d_in[15];
    const float* n2b  = (const float*)d_in[16];
    const float* ln1s = (const float*)d_in[17];
    const float* ln1b = (const float*)d_in[18];
    const float* ln2s = (const float*)d_in[19];
    const float* ln2b = (const float*)d_in[20];
    const float* ln3s = (const float*)d_in[21];
    const float* ln3b = (const float*)d_in[22];
    const float* Wb   = (const float*)d_in[23];
    const float* bb   = (const float*)d_in[24];
    const float* Wm   = (const float*)d_in[25];
    const float* bm   = (const float*)d_in[26];
    const float* Wf1  = (const float*)d_in[27];
    const float* bf1  = (const float*)d_in[28];
    const float* Wf2  = (const float*)d_in[29];
    const float* bf2  = (const float*)d_in[30];
    float* out = (float*)d_out;

    float *g, *q, *k, *v, *ao, *ff, *xs, *mid, *mo, *y2, *y4, *os, *h;
    cudaGetSymbolAddress((void**)&g,  g_g);
    cudaGetSymbolAddress((void**)&q,  g_q);
    cudaGetSymbolAddress((void**)&k,  g_k);
    cudaGetSymbolAddress((void**)&v,  g_v);
    cudaGetSymbolAddress((void**)&ao, g_ao);
    cudaGetSymbolAddress((void**)&ff, g_ff);
    cudaGetSymbolAddress((void**)&xs, g_xs);
    cudaGetSymbolAddress((void**)&mid, g_mid);
    cudaGetSymbolAddress((void**)&mo, g_mo);
    cudaGetSymbolAddress((void**)&y2, g_y2);
    cudaGetSymbolAddress((void**)&y4, g_y4);
    cudaGetSymbolAddress((void**)&os, g_os);
    cudaGetSymbolAddress((void**)&h,  g_h);

    const int ATTN_SMEM = ATTN_SMEM_FLOATS * (int)sizeof(float);
    cudaFuncSetAttribute(attn_kernel, cudaFuncAttributeMaxDynamicSharedMemorySize, ATTN_SMEM);

    // g = x
    copy4_kernel<<<(N_ * D_ / 4 + 255) / 256, 256>>>((const float4*)x, (float4*)g, N_ * D_ / 4);

    const int DD = D_ * D_;
    const int DF = D_ * F_;
    for (int i = 0; i < L_; i++) {
        launch_gemm(g, Wq + (size_t)i * DD, bq + i * D_, q, N_, D_, D_, false);
        launch_gemm(g, Wk + (size_t)i * DD, bk + i * D_, k, N_, D_, D_, false);
        launch_gemm(g, Wv + (size_t)i * DD, bv + i * D_, v, N_, D_, D_, false);
        attn_kernel<<<dim3(B_ * H_, S_ / 64), 256, ATTN_SMEM>>>(q, k, v, ao);
        launch_gemm(ao, Wo + (size_t)i * DD, bo + i * D_, q, N_, D_, D_, false);
        ln_kernel<<<N_, 256>>>(g, q, n1s + i * D_, n1b + i * D_, g);
        launch_gemm(g, W1 + (size_t)i * DF, b1 + i * F_, ff, N_, F_, D_, true);
        launch_gemm(ff, W2 + (size_t)i * DF, b2 + i * D_, q, N_, D_, F_, false);
        ln_kernel<<<N_, 256>>>(g, q, n2s + i * D_, n2b + i * D_, g);
    }

    // local(2): st = 512
    {
        const int st = 512, R = B_ * st;
        gather_kernel<<<R, 256>>>(x, xs, st);
        launch_gemm(xs, Wb, bb, mid, R, M_, D_, false);
        launch_gemm(mid, Wm, bm, mo, R, D_, M_, false);
        ln_kernel<<<R, 256>>>(xs, mo, ln1s, ln1b, y2);
    }
    // local(4): st = 256
    {
        const int st = 256, R = B_ * st;
        gather_kernel<<<R, 256>>>(x, xs, st);
        launch_gemm(xs, Wb, bb, mid, R, M_, D_, false);
        launch_gemm(mid, Wm, bm, mo, R, D_, M_, false);
        ln_kernel<<<R, 256>>>(xs, mo, ln1s, ln1b, y4);
    }

    combine_kernel<<<N_ * D_ / 4 / 256, 256>>>(g, y2, y4, os);
    ln_kernel<<<N_, 256>>>(os, x, ln2s, ln2b, h);
    launch_gemm(os, Wf1, bf1, ff, N_, F_, D_, true);
    launch_gemm(ff, Wf2, bf2, q, N_, D_, F_, false);
    ln_kernel<<<N_, 256>>>(h, q, ln3s, ln3b, out);
}

// round 3
// speedup vs baseline: 1.5025x; 1.2115x over previous
#include <cuda_runtime.h>
#include <cstdint>
#include <cstddef>

// Problem constants
#define B_  4
#define S_  1024
#define D_  1024
#define F_  4096
#define M_  512
#define H_  16
#define HD_ 64
#define L_  2
#define N_  (B_ * S_)   // 4096 tokens

// ---------------------------------------------------------------------------
// Scratch buffers
// ---------------------------------------------------------------------------
__device__ float g_g [N_ * D_];
__device__ float g_q [N_ * D_];
__device__ float g_k [N_ * D_];
__device__ float g_v [N_ * D_];
__device__ float g_ao[N_ * D_];
__device__ float g_ff[N_ * F_];
__device__ float g_xs[(N_/2) * D_];
__device__ float g_mid[(N_/2) * M_];
__device__ float g_mo[(N_/2) * D_];
__device__ float g_y2[(N_/2) * D_];
__device__ float g_y4[(N_/4) * D_];
__device__ float g_os[N_ * D_];
__device__ float g_h [N_ * D_];

// ---------------------------------------------------------------------------
__global__ __launch_bounds__(256) void copy4_kernel(const float4* __restrict__ in,
                                                    float4* __restrict__ out, int n4) {
    int i = blockIdx.x * 256 + threadIdx.x;
    if (i < n4) out[i] = in[i];
}

// ---------------------------------------------------------------------------
// TF32 tensor-core GEMM: C[M,N] = A[M,K] @ W[K,N] + bias[N], optional ReLU.
// CTA tile 128x256x16, 256 threads = 8 warps (2 m x 4 n), warp tile 64x64.
// ---------------------------------------------------------------------------
__device__ __forceinline__ uint32_t f2tf32(float f) {
    uint32_t r;
    asm("cvt.rna.tf32.f32 %0, %1;" : "=r"(r) : "f"(f));
    return r;
}

// A-element (k_local 0..15, row 0..127) -> word index in 2048-word buffer
__device__ __forceinline__ int a_addr(int k_local, int row) {
    int k8 = k_local >> 3, t4 = k_local & 3, hik = (k_local >> 2) & 1;
    int mg = row >> 4, r = row & 15, gg = r & 7, him = r >> 3;
    return (((k8 * 8 + mg) * 32) + (t4 * 8 + gg)) * 4 + him + 2 * hik;
}
// W-element (k_local 0..15, n_local 0..255) -> word index in 4096-word buffer
__device__ __forceinline__ int w_addr(int k_local, int n_local) {
    int k8 = k_local >> 3, t4 = k_local & 3, hik = (k_local >> 2) & 1;
    int ng = n_local >> 4, cc = n_local & 15, jj2 = cc >> 3, gg = cc & 7;
    return (((k8 * 16 + ng) * 32) + (t4 * 8 + gg)) * 4 + hik + 2 * jj2;
}

__device__ __forceinline__ void mma_tf32(float* c, uint32_t a0, uint32_t a1,
                                         uint32_t a2, uint32_t a3,
                                         uint32_t b0, uint32_t b1) {
    asm volatile(
        "mma.sync.aligned.m16n8k8.row.col.f32.tf32.tf32.f32 "
        "{%0,%1,%2,%3}, {%4,%5,%6,%7}, {%8,%9}, {%0,%1,%2,%3};"
        : "+f"(c[0]), "+f"(c[1]), "+f"(c[2]), "+f"(c[3])
        : "r"(a0), "r"(a1), "r"(a2), "r"(a3), "r"(b0), "r"(b1));
}

template <bool RELU>
__global__ __launch_bounds__(256, 1) void mma_gemm_kernel(const float* __restrict__ A,
                                                          const float* __restrict__ W,
                                                          const float* __restrict__ bias,
                                                          float* __restrict__ C,
                                                          int M, int N, int K) {
    // 2 stages x (2048 A + 4096 W) words = 49152 bytes (exactly 48KB static)
    __shared__ uint32_t sm[12288];

    int tid = threadIdx.x;
    int bx = blockIdx.x, by = blockIdx.y;
    int wid = tid >> 5, lane = tid & 31;
    int warp_m = wid >> 2;          // 0..1 -> 64 rows
    int warp_n = wid & 3;           // 0..3 -> 64 cols
    int g = lane >> 2, t4 = lane & 3;
    int p = t4 * 8 + g;

    // ---- global loader addressing ----
    int ar = tid >> 1;              // A row 0..127
    int ak = (tid & 1) * 8;         // A k-offset 0 or 8
    const float* Aptr = A + (size_t)(by * 128 + ar) * K + ak;

    int kr0 = tid >> 5;             // W k-rows 0..7 and 8..15
    int kr1 = kr0 + 8;
    int n4 = (lane) << 2;           // 0..124 (col within 128-chunk)
    const float* Wg = W + (size_t)bx * 256;

    int aw[8], ww[4][4];
#pragma unroll
    for (int i = 0; i < 8; i++) aw[i] = a_addr(ak + i, ar);
#pragma unroll
    for (int j = 0; j < 4; j++) {
        ww[0][j] = w_addr(kr0, n4 + j);
        ww[1][j] = w_addr(kr0, n4 + 128 + j);
        ww[2][j] = w_addr(kr1, n4 + j);
        ww[3][j] = w_addr(kr1, n4 + 128 + j);
    }

    float4 ra0, ra1, rw[4];

    auto load_tile = [&](int kt) {
        ra0 = *(const float4*)(Aptr + kt);
        ra1 = *(const float4*)(Aptr + kt + 4);
        rw[0] = *(const float4*)(Wg + (size_t)(kt + kr0) * N + n4);
        rw[1] = *(const float4*)(Wg + (size_t)(kt + kr0) * N + n4 + 128);
        rw[2] = *(const float4*)(Wg + (size_t)(kt + kr1) * N + n4);
        rw[3] = *(const float4*)(Wg + (size_t)(kt + kr1) * N + n4 + 128);
    };
    auto store_tile = [&](int s) {
        uint32_t* dA = sm + s * 6144;
        uint32_t* dB = dA + 2048;
        dA[aw[0]] = f2tf32(ra0.x); dA[aw[1]] = f2tf32(ra0.y);
        dA[aw[2]] = f2tf32(ra0.z); dA[aw[3]] = f2tf32(ra0.w);
        dA[aw[4]] = f2tf32(ra1.x); dA[aw[5]] = f2tf32(ra1.y);
        dA[aw[6]] = f2tf32(ra1.z); dA[aw[7]] = f2tf32(ra1.w);
#pragma unroll
        for (int c = 0; c < 4; c++) {
            dB[ww[c][0]] = f2tf32(rw[c].x); dB[ww[c][1]] = f2tf32(rw[c].y);
            dB[ww[c][2]] = f2tf32(rw[c].z); dB[ww[c][3]] = f2tf32(rw[c].w);
        }
    };

    float acc[4][8][4];
#pragma unroll
    for (int mi = 0; mi < 4; mi++)
#pragma unroll
        for (int nj = 0; nj < 8; nj++)
#pragma unroll
            for (int e = 0; e < 4; e++) acc[mi][nj][e] = 0.f;

    int nk = K >> 4;
    load_tile(0);
    store_tile(0);
    __syncthreads();

    for (int t = 0; t < nk; t++) {
        if (t + 1 < nk) load_tile((t + 1) << 4);

        uint32_t* smA = sm + (t & 1) * 6144;
        uint32_t* smB = smA + 2048;
#pragma unroll
        for (int k8 = 0; k8 < 2; k8++) {
            uint4 af[4], bf[4];
#pragma unroll
            for (int mi = 0; mi < 4; mi++)
                af[mi] = *(const uint4*)&smA[(((k8 * 8) + warp_m * 4 + mi) * 32 + p) * 4];
#pragma unroll
            for (int nq = 0; nq < 4; nq++)
                bf[nq] = *(const uint4*)&smB[(((k8 * 16) + warp_n * 4 + nq) * 32 + p) * 4];
#pragma unroll
            for (int mi = 0; mi < 4; mi++) {
#pragma unroll
                for (int nq = 0; nq < 4; nq++) {
                    mma_tf32(acc[mi][2 * nq],     af[mi].x, af[mi].y, af[mi].z, af[mi].w, bf[nq].x, bf[nq].y);
                    mma_tf32(acc[mi][2 * nq + 1], af[mi].x, af[mi].y, af[mi].z, af[mi].w, bf[nq].z, bf[nq].w);
                }
            }
        }

        if (t + 1 < nk) {
            store_tile((t + 1) & 1);
            __syncthreads();
        }
    }

    // epilogue
    int row0 = by * 128 + warp_m * 64;
    int col0 = bx * 256 + warp_n * 64;
#pragma unroll
    for (int nj = 0; nj < 8; nj++) {
        int cc = col0 + nj * 8 + t4 * 2;
        float b0 = bias[cc], b1 = bias[cc + 1];
#pragma unroll
        for (int mi = 0; mi < 4; mi++) {
            int r = row0 + mi * 16 + g;
            float2 v0 = make_float2(acc[mi][nj][0] + b0, acc[mi][nj][1] + b1);
            float2 v1 = make_float2(acc[mi][nj][2] + b0, acc[mi][nj][3] + b1);
            if (RELU) {
                v0.x = fmaxf(v0.x, 0.f); v0.y = fmaxf(v0.y, 0.f);
                v1.x = fmaxf(v1.x, 0.f); v1.y = fmaxf(v1.y, 0.f);
            }
            *(float2*)(C + (size_t)r * N + cc) = v0;
            *(float2*)(C + (size_t)(r + 8) * N + cc) = v1;
        }
    }
}

// ---------------------------------------------------------------------------
// Flash attention, fp32. Grid: (B*H, S/64), 256 threads.
// ---------------------------------------------------------------------------
#define ATTN_STRIDE 65
#define ATTN_SMEM_FLOATS (3 * 64 * ATTN_STRIDE + 3 * 64)

__device__ __forceinline__ void attn_load_tile(const float* __restrict__ src, size_t base,
                                               float* __restrict__ dst, int tid) {
#pragma unroll
    for (int r = 0; r < 4; r++) {
        int idx = tid + r * 256;
        int row = idx >> 4;
        int col = (idx & 15) << 2;
        float4 v = *(const float4*)(src + base + (size_t)row * D_ + col);
        float* d = dst + row * ATTN_STRIDE + col;
        d[0] = v.x; d[1] = v.y; d[2] = v.z; d[3] = v.w;
    }
}

__global__ __launch_bounds__(256) void attn_kernel(const float* __restrict__ Q,
                                                   const float* __restrict__ Kp,
                                                   const float* __restrict__ Vp,
                                                   float* __restrict__ O) {
    extern __shared__ float smf[];
    float* Qs  = smf;
    float* KVs = smf + 64 * ATTN_STRIDE;
    float* Ps  = smf + 2 * 64 * ATTN_STRIDE;
    float* m_s = smf + 3 * 64 * ATTN_STRIDE;
    float* l_s = m_s + 64;
    float* a_s = l_s + 64;

    int tid = threadIdx.x;
    int b = blockIdx.x >> 4;
    int h = blockIdx.x & 15;
    int q0 = blockIdx.y * 64;

    size_t base_q = ((size_t)(b * S_ + q0)) * D_ + h * HD_;
    attn_load_tile(Q, base_q, Qs, tid);
    if (tid < 64) { m_s[tid] = -1e30f; l_s[tid] = 0.f; }

    int ty = tid >> 4, tx = tid & 15;
    int i0 = ty * 4, j0 = tx * 4;
    float o[4][4];
#pragma unroll
    for (int i = 0; i < 4; i++)
#pragma unroll
        for (int j = 0; j < 4; j++) o[i][j] = 0.f;

    for (int kt = 0; kt < 16; kt++) {
        size_t base_kv = ((size_t)(b * S_ + kt * 64)) * D_ + h * HD_;
        attn_load_tile(Kp, base_kv, KVs, tid);
        __syncthreads();

        float s4[4][4];
#pragma unroll
        for (int i = 0; i < 4; i++)
#pragma unroll
            for (int j = 0; j < 4; j++) s4[i][j] = 0.f;
#pragma unroll
        for (int k = 0; k < 64; k++) {
            float ra[4], rb[4];
#pragma unroll
            for (int i = 0; i < 4; i++) ra[i] = Qs[(i0 + i) * ATTN_STRIDE + k];
#pragma unroll
            for (int j = 0; j < 4; j++) rb[j] = KVs[(j0 + j) * ATTN_STRIDE + k];
#pragma unroll
            for (int i = 0; i < 4; i++)
#pragma unroll
                for (int j = 0; j < 4; j++) s4[i][j] += ra[i] * rb[j];
        }
#pragma unroll
        for (int i = 0; i < 4; i++)
#pragma unroll
            for (int j = 0; j < 4; j++)
                Ps[(i0 + i) * ATTN_STRIDE + j0 + j] = s4[i][j] * 0.125f;
        __syncthreads();

        attn_load_tile(Vp, base_kv, KVs, tid);
        // parallel softmax: 4 lanes per row, 16 cols each
        {
            int r = tid >> 2;
            int qd = tid & 3;
            float* Pr = Ps + r * ATTN_STRIDE + qd * 16;
            float mx = -1e30f;
#pragma unroll
            for (int j = 0; j < 16; j++) mx = fmaxf(mx, Pr[j]);
            mx = fmaxf(mx, __shfl_xor_sync(0xffffffffu, mx, 1));
            mx = fmaxf(mx, __shfl_xor_sync(0xffffffffu, mx, 2));
            float mold = m_s[r];
            mx = fmaxf(mx, mold);
            float sum = 0.f;
#pragma unroll
            for (int j = 0; j < 16; j++) {
                float e = __expf(Pr[j] - mx);
                Pr[j] = e;
                sum += e;
            }
            sum += __shfl_xor_sync(0xffffffffu, sum, 1);
            sum += __shfl_xor_sync(0xffffffffu, sum, 2);
            if (qd == 0) {
                float al = __expf(mold - mx);
                l_s[r] = l_s[r] * al + sum;
                m_s[r] = mx;
                a_s[r] = al;
            }
        }
        __syncthreads();

        float al_i[4];
#pragma unroll
        for (int i = 0; i < 4; i++) al_i[i] = a_s[i0 + i];
#pragma unroll
        for (int i = 0; i < 4; i++)
#pragma unroll
            for (int j = 0; j < 4; j++) o[i][j] *= al_i[i];
#pragma unroll
        for (int k = 0; k < 64; k++) {
            float ra[4], rb[4];
#pragma unroll
            for (int i = 0; i < 4; i++) ra[i] = Ps[(i0 + i) * ATTN_STRIDE + k];
#pragma unroll
            for (int j = 0; j < 4; j++) rb[j] = KVs[k * ATTN_STRIDE + j0 + j];
#pragma unroll
            for (int i = 0; i < 4; i++)
#pragma unroll
                for (int j = 0; j < 4; j++) o[i][j] += ra[i] * rb[j];
        }
        __syncthreads();
    }

    float inv[4];
#pragma unroll
    for (int i = 0; i < 4; i++) inv[i] = 1.f / l_s[i0 + i];
#pragma unroll
    for (int i = 0; i < 4; i++)
#pragma unroll
        for (int j = 0; j < 4; j++)
            O[base_q + (size_t)(i0 + i) * D_ + j0 + j] = o[i][j] * inv[i];
}

// ---------------------------------------------------------------------------
// Fused residual + LayerNorm
// ---------------------------------------------------------------------------
__global__ __launch_bounds__(256) void ln_kernel(const float* __restrict__ res,
                                                 const float* __restrict__ delta,
                                                 const float* __restrict__ gamma,
                                                 const float* __restrict__ beta,
                                                 float* __restrict__ out) {
    int row = blockIdx.x, tid = threadIdx.x;
    size_t base = (size_t)row * D_;
    float4 rv = *(const float4*)(res + base + tid * 4);
    float4 dv = *(const float4*)(delta + base + tid * 4);
    float v0 = rv.x + dv.x, v1 = rv.y + dv.y, v2 = rv.z + dv.z, v3 = rv.w + dv.w;
    float s = v0 + v1 + v2 + v3;
    float q = v0 * v0 + v1 * v1 + v2 * v2 + v3 * v3;
#pragma unroll
    for (int o2 = 16; o2 > 0; o2 >>= 1) {
        s += __shfl_xor_sync(0xffffffffu, s, o2);
        q += __shfl_xor_sync(0xffffffffu, q, o2);
    }
    __shared__ float ss[8], qs[8];
    __shared__ float mean_s, rstd_s;
    if ((tid & 31) == 0) { ss[tid >> 5] = s; qs[tid >> 5] = q; }
    __syncthreads();
    if (tid == 0) {
        float S2 = 0.f, Q2 = 0.f;
#pragma unroll
        for (int w = 0; w < 8; w++) { S2 += ss[w]; Q2 += qs[w]; }
        float mean = S2 * (1.0f / D_);
        float var = Q2 * (1.0f / D_) - mean * mean;
        mean_s = mean;
        rstd_s = rsqrtf(var + 1e-5f);
    }
    __syncthreads();
    float mean = mean_s, rstd = rstd_s;
    float4 gv = *(const float4*)(gamma + tid * 4);
    float4 bv = *(const float4*)(beta + tid * 4);
    float4 ov;
    ov.x = (v0 - mean) * rstd * gv.x + bv.x;
    ov.y = (v1 - mean) * rstd * gv.y + bv.y;
    ov.z = (v2 - mean) * rstd * gv.z + bv.z;
    ov.w = (v3 - mean) * rstd * gv.w + bv.w;
    *(float4*)(out + base + tid * 4) = ov;
}

// ---------------------------------------------------------------------------
__global__ __launch_bounds__(256) void gather_kernel(const float* __restrict__ x,
                                                     float* __restrict__ xs, int st) {
    int i = blockIdx.x * 256 + threadIdx.x;
    int row = i >> 8;
    int c = i & 255;
    int b = row / st, sl = row % st;
    size_t src = ((size_t)(b * S_ + (S_ - st) + sl) << 8) + c;
    ((float4*)xs)[i] = ((const float4*)x)[src];
}

__global__ __launch_bounds__(256) void combine_kernel(const float* __restrict__ g,
                                                      const float* __restrict__ y2,
                                                      const float* __restrict__ y4,
                                                      float* __restrict__ out) {
    int i = blockIdx.x * 256 + threadIdx.x;
    int row = i >> 8;
    int c = i & 255;
    int b = row >> 10;
    int s = row & 1023;
    float4 v = ((const float4*)g)[i];
    if (s >= 512) {
        float4 a = ((const float4*)y2)[((size_t)(b * 512 + (s - 512)) << 8) + c];
        v.x += a.x; v.y += a.y; v.z += a.z; v.w += a.w;
    }
    if (s >= 768) {
        float4 a = ((const float4*)y4)[((size_t)(b * 256 + (s - 768)) << 8) + c];
        v.x += a.x; v.y += a.y; v.z += a.z; v.w += a.w;
    }
    ((float4*)out)[i] = v;
}

// ---------------------------------------------------------------------------
// Host orchestration
// ---------------------------------------------------------------------------
static void launch_gemm(const float* A, const float* W, const float* bias, float* C,
                        int M, int N, int K, bool relu) {
    dim3 grid(N / 256, M / 128);
    if (relu) mma_gemm_kernel<true><<<grid, 256>>>(A, W, bias, C, M, N, K);
    else      mma_gemm_kernel<false><<<grid, 256>>>(A, W, bias, C, M, N, K);
}

extern "C" void kernel_launch(void* const* d_in, const int* in_sizes, int n_in,
                              void* d_out, int out_size) {
    (void)in_sizes; (void)n_in; (void)out_size;
    const float* x    = (const float*)d_in[0];
    const float* Wq   = (const float*)d_in[1];
    const float* bq   = (const float*)d_in[2];
    const float* Wk   = (const float*)d_in[3];
    const float* bk   = (const float*)d_in[4];
    const float* Wv   = (const float*)d_in[5];
    const float* bv   = (const float*)d_in[6];
    const float* Wo   = (const float*)d_in[7];
    const float* bo   = (const float*)d_in[8];
    const float* W1   = (const float*)d_in[9];
    const float* b1   = (const float*)d_in[10];
    const float* W2   = (const float*)d_in[11];
    const float* b2   = (const float*)d_in[12];
    const float* n1s  = (const float*)d_in[13];
    const float* n1b  = (const float*)d_in[14];
    const float* n2s  = (const float*)d_in[15];
    const float* n2b  = (const float*)d_in[16];
    const float* ln1s = (const float*)d_in[17];
    const float* ln1b = (const float*)d_in[18];
    const float* ln2s = (const float*)d_in[19];
    const float* ln2b = (const float*)d_in[20];
    const float* ln3s = (const float*)d_in[21];
    const float* ln3b = (const float*)d_in[22];
    const float* Wb   = (const float*)d_in[23];
    const float* bb   = (const float*)d_in[24];
    const float* Wm   = (const float*)d_in[25];
    const float* bm   = (const float*)d_in[26];
    const float* Wf1  = (const float*)d_in[27];
    const float* bf1  = (const float*)d_in[28];
    const float* Wf2  = (const float*)d_in[29];
    const float* bf2  = (const float*)d_in[30];
    float* out = (float*)d_out;

    float *g, *q, *k, *v, *ao, *ff, *xs, *mid, *mo, *y2, *y4, *os, *h;
    cudaGetSymbolAddress((void**)&g,  g_g);
    cudaGetSymbolAddress((void**)&q,  g_q);
    cudaGetSymbolAddress((void**)&k,  g_k);
    cudaGetSymbolAddress((void**)&v,  g_v);
    cudaGetSymbolAddress((void**)&ao, g_ao);
    cudaGetSymbolAddress((void**)&ff, g_ff);
    cudaGetSymbolAddress((void**)&xs, g_xs);
    cudaGetSymbolAddress((void**)&mid, g_mid);
    cudaGetSymbolAddress((void**)&mo, g_mo);
    cudaGetSymbolAddress((void**)&y2, g_y2);
    cudaGetSymbolAddress((void**)&y4, g_y4);
    cudaGetSymbolAddress((void**)&os, g_os);
    cudaGetSymbolAddress((void**)&h,  g_h);

    const int ATTN_SMEM = ATTN_SMEM_FLOATS * (int)sizeof(float);
    cudaFuncSetAttribute(attn_kernel, cudaFuncAttributeMaxDynamicSharedMemorySize, ATTN_SMEM);

    copy4_kernel<<<(N_ * D_ / 4 + 255) / 256, 256>>>((const float4*)x, (float4*)g, N_ * D_ / 4);

    const int DD = D_ * D_;
    const int DF = D_ * F_;
    for (int i = 0; i < L_; i++) {
        launch_gemm(g, Wq + (size_t)i * DD, bq + i * D_, q, N_, D_, D_, false);
        launch_gemm(g, Wk + (size_t)i * DD, bk + i * D_, k, N_, D_, D_, false);
        launch_gemm(g, Wv + (size_t)i * DD, bv + i * D_, v, N_, D_, D_, false);
        attn_kernel<<<dim3(B_ * H_, S_ / 64), 256, ATTN_SMEM>>>(q, k, v, ao);
        launch_gemm(ao, Wo + (size_t)i * DD, bo + i * D_, q, N_, D_, D_, false);
        ln_kernel<<<N_, 256>>>(g, q, n1s + i * D_, n1b + i * D_, g);
        launch_gemm(g, W1 + (size_t)i * DF, b1 + i * F_, ff, N_, F_, D_, true);
        launch_gemm(ff, W2 + (size_t)i * DF, b2 + i * D_, q, N_, D_, F_, false);
        ln_kernel<<<N_, 256>>>(g, q, n2s + i * D_, n2b + i * D_, g);
    }

    // local(2): st = 512
    {
        const int st = 512, R = B_ * st;
        gather_kernel<<<R, 256>>>(x, xs, st);
        launch_gemm(xs, Wb, bb, mid, R, M_, D_, false);
        launch_gemm(mid, Wm, bm, mo, R, D_, M_, false);
        ln_kernel<<<R, 256>>>(xs, mo, ln1s, ln1b, y2);
    }
    // local(4): st = 256
    {
        const int st = 256, R = B_ * st;
        gather_kernel<<<R, 256>>>(x, xs, st);
        launch_gemm(xs, Wb, bb, mid, R, M_, D_, false);
        launch_gemm(mid, Wm, bm, mo, R, D_, M_, false);
        ln_kernel<<<R, 256>>>(xs, mo, ln1s, ln1b, y4);
    }

    combine_kernel<<<N_ * D_ / 4 / 256, 256>>>(g, y2, y4, os);
    ln_kernel<<<N_, 256>>>(os, x, ln2s, ln2b, h);
    launch_gemm(os, Wf1, bf1, ff, N_, F_, D_, true);
    launch_gemm(ff, Wf2, bf2, q, N_, D_, F_, false);
    ln_kernel<<<N_, 256>>>(h, q, ln3s, ln3b, out);
}

// round 7
// speedup vs baseline: 2.3862x; 1.5881x over previous
#include <cuda_runtime.h>
#include <cstdint>
#include <cstddef>

// Problem constants
#define B_  4
#define S_  1024
#define D_  1024
#define F_  4096
#define M_  512
#define H_  16
#define HD_ 64
#define L_  2
#define N_  (B_ * S_)   // 4096 tokens

// ---------------------------------------------------------------------------
// Scratch buffers (static device globals; no runtime allocation)
// ---------------------------------------------------------------------------
// fp32 working buffers
__device__ float g_g [N_ * D_];
__device__ float g_q [N_ * D_];
__device__ float g_k [N_ * D_];
__device__ float g_v [N_ * D_];
__device__ float g_xs[(N_/2) * D_];
__device__ float g_mo[(N_/2) * D_];
__device__ float g_y2[(N_/2) * D_];
__device__ float g_y4[(N_/4) * D_];
__device__ float g_os[N_ * D_];
__device__ float g_h [N_ * D_];
// tf32 shadow buffers (activations consumed by GEMMs)
__device__ uint32_t t_g  [N_ * D_];
__device__ uint32_t t_os [N_ * D_];
__device__ uint32_t t_ao [N_ * D_];
__device__ uint32_t t_xs [(N_/2) * D_];
__device__ uint32_t t_mid[(N_/2) * M_];
__device__ uint32_t t_ff [N_ * F_];
// tf32 weight copies
__device__ uint32_t t_Wq [L_ * D_ * D_];
__device__ uint32_t t_Wk [L_ * D_ * D_];
__device__ uint32_t t_Wv [L_ * D_ * D_];
__device__ uint32_t t_Wo [L_ * D_ * D_];
__device__ uint32_t t_W1 [L_ * D_ * F_];
__device__ uint32_t t_W2 [L_ * F_ * D_];
__device__ uint32_t t_Wb [D_ * M_];
__device__ uint32_t t_Wm [M_ * D_];
__device__ uint32_t t_Wf1[D_ * F_];
__device__ uint32_t t_Wf2[F_ * D_];

// ---------------------------------------------------------------------------
__device__ __forceinline__ uint32_t f2tf32(float f) {
    uint32_t r;
    asm("cvt.rna.tf32.f32 %0, %1;" : "=r"(r) : "f"(f));
    return r;
}

// Weight fp32 -> tf32 conversion (grid-strided not needed; exact sizes)
__global__ __launch_bounds__(256) void cvtw_kernel(const float4* __restrict__ in,
                                                   uint4* __restrict__ out, int n4) {
    int i = blockIdx.x * 256 + threadIdx.x;
    if (i < n4) {
        float4 v = in[i];
        uint4 o;
        o.x = f2tf32(v.x); o.y = f2tf32(v.y); o.z = f2tf32(v.z); o.w = f2tf32(v.w);
        out[i] = o;
    }
}

// x -> g (fp32) + t_g (tf32)
__global__ __launch_bounds__(256) void copyx_kernel(const float4* __restrict__ in,
                                                    float4* __restrict__ out,
                                                    uint4* __restrict__ out32, int n4) {
    int i = blockIdx.x * 256 + threadIdx.x;
    if (i < n4) {
        float4 v = in[i];
        out[i] = v;
        uint4 o;
        o.x = f2tf32(v.x); o.y = f2tf32(v.y); o.z = f2tf32(v.z); o.w = f2tf32(v.w);
        out32[i] = o;
    }
}

// ---------------------------------------------------------------------------
// TF32 tensor-core GEMM with cp.async pipeline.
// C[M,N] = A[M,K] @ W[K,N] + bias[N]. A, W already tf32 (uint32 payload).
// CTA 128x256x16, 3 stages, 256 threads = 8 warps (2m x 4n), warp tile 64x64.
// ---------------------------------------------------------------------------
#define BM 128
#define BN 256
#define BK 16
#define STAGES 3
#define A_STRIDE 20                         // words per A row (16 data + 4 pad)
#define B_STRIDE 264                        // words per B k-row (256 data + 8 pad)
#define A_WORDS (BM * A_STRIDE)             // 2560
#define B_WORDS (BK * B_STRIDE)             // 4224
#define STAGE_WORDS (A_WORDS + B_WORDS)     // 6784
#define GEMM_SMEM_BYTES (STAGES * STAGE_WORDS * 4)   // 81408

__device__ __forceinline__ void cp16(uint32_t dst_smem, const void* src) {
    asm volatile("cp.async.cg.shared.global [%0], [%1], 16;\n" :: "r"(dst_smem), "l"(src));
}

__device__ __forceinline__ void mma_tf32(float* c, uint32_t a0, uint32_t a1,
                                         uint32_t a2, uint32_t a3,
                                         uint32_t b0, uint32_t b1) {
    asm volatile(
        "mma.sync.aligned.m16n8k8.row.col.f32.tf32.tf32.f32 "
        "{%0,%1,%2,%3}, {%4,%5,%6,%7}, {%8,%9}, {%0,%1,%2,%3};"
        : "+f"(c[0]), "+f"(c[1]), "+f"(c[2]), "+f"(c[3])
        : "r"(a0), "r"(a1), "r"(a2), "r"(a3), "r"(b0), "r"(b1));
}

template <bool RELU, bool WF, bool WT>
__global__ __launch_bounds__(256, 1) void tc_gemm_kernel(
        const uint32_t* __restrict__ A, const uint32_t* __restrict__ W,
        const float* __restrict__ bias, float* __restrict__ C,
        uint32_t* __restrict__ C32, int M, int N, int K) {
    extern __shared__ __align__(16) uint32_t sm[];
    uint32_t smb = (uint32_t)__cvta_generic_to_shared(sm);

    int tid = threadIdx.x;
    int bx = blockIdx.x, by = blockIdx.y;
    int wid = tid >> 5, lane = tid & 31;
    int warp_m = wid >> 2;          // 0..1
    int warp_n = wid & 3;           // 0..3
    int g = lane >> 2, t4 = lane & 3;

    const uint32_t* Ag = A + (size_t)by * BM * K;
    const uint32_t* Wg = W + (size_t)bx * BN;

    // copy-issue lambda: one k-tile into stage s
    auto issue = [&](int s, int kt) {
        uint32_t base = smb + (uint32_t)(s * STAGE_WORDS) * 4u;
#pragma unroll
        for (int r = 0; r < 2; r++) {           // A: 512 chunks / 256 thr
            int c = tid + r * 256;
            int row = c >> 2, u = c & 3;
            cp16(base + (uint32_t)(row * A_STRIDE + u * 4) * 4u,
                 Ag + (size_t)row * K + kt + u * 4);
        }
        uint32_t baseB = base + (uint32_t)A_WORDS * 4u;
#pragma unroll
        for (int r = 0; r < 4; r++) {           // B: 1024 chunks / 256 thr
            int c = tid + r * 256;
            int k = c >> 6, u = c & 63;
            cp16(baseB + (uint32_t)(k * B_STRIDE + u * 4) * 4u,
                 Wg + (size_t)(kt + k) * N + u * 4);
        }
        asm volatile("cp.async.commit_group;\n" ::);
    };

    float acc[4][8][4];
#pragma unroll
    for (int mi = 0; mi < 4; mi++)
#pragma unroll
        for (int nj = 0; nj < 8; nj++)
#pragma unroll
            for (int e = 0; e < 4; e++) acc[mi][nj][e] = 0.f;

    int nk = K / BK;
#pragma unroll
    for (int s = 0; s < STAGES - 1; s++) issue(s, s * BK);
    asm volatile("cp.async.wait_group %0;\n" :: "n"(STAGES - 2));
    __syncthreads();

    for (int t = 0; t < nk; t++) {
        int pf = t + STAGES - 1;
        if (pf < nk) issue(pf % STAGES, pf * BK);

        const uint32_t* As = sm + (t % STAGES) * STAGE_WORDS;
        const uint32_t* Bs = As + A_WORDS;
#pragma unroll
        for (int k8 = 0; k8 < 2; k8++) {
            uint32_t af[4][4], bf[8][2];
            int acol = k8 * 8 + t4;
#pragma unroll
            for (int mi = 0; mi < 4; mi++) {
                int r = warp_m * 64 + mi * 16 + g;
                af[mi][0] = As[r * A_STRIDE + acol];
                af[mi][1] = As[(r + 8) * A_STRIDE + acol];
                af[mi][2] = As[r * A_STRIDE + acol + 4];
                af[mi][3] = As[(r + 8) * A_STRIDE + acol + 4];
            }
            int brow = acol * B_STRIDE;
            int bcol0 = warp_n * 64 + g;
#pragma unroll
            for (int nj = 0; nj < 8; nj++) {
                bf[nj][0] = Bs[brow + bcol0 + nj * 8];
                bf[nj][1] = Bs[brow + 4 * B_STRIDE + bcol0 + nj * 8];
            }
#pragma unroll
            for (int mi = 0; mi < 4; mi++)
#pragma unroll
                for (int nj = 0; nj < 8; nj++)
                    mma_tf32(acc[mi][nj], af[mi][0], af[mi][1], af[mi][2], af[mi][3],
                             bf[nj][0], bf[nj][1]);
        }

        asm volatile("cp.async.wait_group %0;\n" :: "n"(STAGES - 2));
        __syncthreads();
    }

    // epilogue
    int row0 = by * BM + warp_m * 64;
    int col0 = bx * BN + warp_n * 64;
#pragma unroll
    for (int nj = 0; nj < 8; nj++) {
        int cc = col0 + nj * 8 + t4 * 2;
        float b0 = bias[cc], b1 = bias[cc + 1];
#pragma unroll
        for (int mi = 0; mi < 4; mi++) {
            int r = row0 + mi * 16 + g;
            float v00 = acc[mi][nj][0] + b0, v01 = acc[mi][nj][1] + b1;
            float v10 = acc[mi][nj][2] + b0, v11 = acc[mi][nj][3] + b1;
            if (RELU) {
                v00 = fmaxf(v00, 0.f); v01 = fmaxf(v01, 0.f);
                v10 = fmaxf(v10, 0.f); v11 = fmaxf(v11, 0.f);
            }
            if (WF) {
                *(float2*)(C + (size_t)r * N + cc) = make_float2(v00, v01);
                *(float2*)(C + (size_t)(r + 8) * N + cc) = make_float2(v10, v11);
            }
            if (WT) {
                uint2 u0 = make_uint2(f2tf32(v00), f2tf32(v01));
                uint2 u1 = make_uint2(f2tf32(v10), f2tf32(v11));
                *(uint2*)(C32 + (size_t)r * N + cc) = u0;
                *(uint2*)(C32 + (size_t)(r + 8) * N + cc) = u1;
            }
        }
    }
}

// ---------------------------------------------------------------------------
// Flash attention, fp32 math; output written as tf32 (feeds Wo GEMM only).
// Grid: (B*H, S/64), 256 threads.
// ---------------------------------------------------------------------------
#define ATTN_STRIDE 65
#define ATTN_SMEM_FLOATS (3 * 64 * ATTN_STRIDE + 3 * 64)

__device__ __forceinline__ void attn_load_tile(const float* __restrict__ src, size_t base,
                                               float* __restrict__ dst, int tid) {
#pragma unroll
    for (int r = 0; r < 4; r++) {
        int idx = tid + r * 256;
        int row = idx >> 4;
        int col = (idx & 15) << 2;
        float4 v = *(const float4*)(src + base + (size_t)row * D_ + col);
        float* d = dst + row * ATTN_STRIDE + col;
        d[0] = v.x; d[1] = v.y; d[2] = v.z; d[3] = v.w;
    }
}

__global__ __launch_bounds__(256) void attn_kernel(const float* __restrict__ Q,
                                                   const float* __restrict__ Kp,
                                                   const float* __restrict__ Vp,
                                                   uint32_t* __restrict__ O32) {
    extern __shared__ float smf[];
    float* Qs  = smf;
    float* KVs = smf + 64 * ATTN_STRIDE;
    float* Ps  = smf + 2 * 64 * ATTN_STRIDE;
    float* m_s = smf + 3 * 64 * ATTN_STRIDE;
    float* l_s = m_s + 64;
    float* a_s = l_s + 64;

    int tid = threadIdx.x;
    int b = blockIdx.x >> 4;
    int h = blockIdx.x & 15;
    int q0 = blockIdx.y * 64;

    size_t base_q = ((size_t)(b * S_ + q0)) * D_ + h * HD_;
    attn_load_tile(Q, base_q, Qs, tid);
    if (tid < 64) { m_s[tid] = -1e30f; l_s[tid] = 0.f; }

    int ty = tid >> 4, tx = tid & 15;
    int i0 = ty * 4, j0 = tx * 4;
    float o[4][4];
#pragma unroll
    for (int i = 0; i < 4; i++)
#pragma unroll
        for (int j = 0; j < 4; j++) o[i][j] = 0.f;

    for (int kt = 0; kt < 16; kt++) {
        size_t base_kv = ((size_t)(b * S_ + kt * 64)) * D_ + h * HD_;
        attn_load_tile(Kp, base_kv, KVs, tid);
        __syncthreads();

        float s4[4][4];
#pragma unroll
        for (int i = 0; i < 4; i++)
#pragma unroll
            for (int j = 0; j < 4; j++) s4[i][j] = 0.f;
#pragma unroll
        for (int k = 0; k < 64; k++) {
            float ra[4], rb[4];
#pragma unroll
            for (int i = 0; i < 4; i++) ra[i] = Qs[(i0 + i) * ATTN_STRIDE + k];
#pragma unroll
            for (int j = 0; j < 4; j++) rb[j] = KVs[(j0 + j) * ATTN_STRIDE + k];
#pragma unroll
            for (int i = 0; i < 4; i++)
#pragma unroll
                for (int j = 0; j < 4; j++) s4[i][j] += ra[i] * rb[j];
        }
#pragma unroll
        for (int i = 0; i < 4; i++)
#pragma unroll
            for (int j = 0; j < 4; j++)
                Ps[(i0 + i) * ATTN_STRIDE + j0 + j] = s4[i][j] * 0.125f;
        __syncthreads();

        attn_load_tile(Vp, base_kv, KVs, tid);
        // parallel softmax: 4 lanes per row, 16 cols each
        {
            int r = tid >> 2;
            int qd = tid & 3;
            float* Pr = Ps + r * ATTN_STRIDE + qd * 16;
            float mx = -1e30f;
#pragma unroll
            for (int j = 0; j < 16; j++) mx = fmaxf(mx, Pr[j]);
            mx = fmaxf(mx, __shfl_xor_sync(0xffffffffu, mx, 1));
            mx = fmaxf(mx, __shfl_xor_sync(0xffffffffu, mx, 2));
            float mold = m_s[r];
            mx = fmaxf(mx, mold);
            float sum = 0.f;
#pragma unroll
            for (int j = 0; j < 16; j++) {
                float e = __expf(Pr[j] - mx);
                Pr[j] = e;
                sum += e;
            }
            sum += __shfl_xor_sync(0xffffffffu, sum, 1);
            sum += __shfl_xor_sync(0xffffffffu, sum, 2);
            if (qd == 0) {
                float al = __expf(mold - mx);
                l_s[r] = l_s[r] * al + sum;
                m_s[r] = mx;
                a_s[r] = al;
            }
        }
        __syncthreads();

        float al_i[4];
#pragma unroll
        for (int i = 0; i < 4; i++) al_i[i] = a_s[i0 + i];
#pragma unroll
        for (int i = 0; i < 4; i++)
#pragma unroll
            for (int j = 0; j < 4; j++) o[i][j] *= al_i[i];
#pragma unroll
        for (int k = 0; k < 64; k++) {
            float ra[4], rb[4];
#pragma unroll
            for (int i = 0; i < 4; i++) ra[i] = Ps[(i0 + i) * ATTN_STRIDE + k];
#pragma unroll
            for (int j = 0; j < 4; j++) rb[j] = KVs[k * ATTN_STRIDE + j0 + j];
#pragma unroll
            for (int i = 0; i < 4; i++)
#pragma unroll
                for (int j = 0; j < 4; j++) o[i][j] += ra[i] * rb[j];
        }
        __syncthreads();
    }

    float inv[4];
#pragma unroll
    for (int i = 0; i < 4; i++) inv[i] = 1.f / l_s[i0 + i];
#pragma unroll
    for (int i = 0; i < 4; i++)
#pragma unroll
        for (int j = 0; j < 4; j++)
            O32[base_q + (size_t)(i0 + i) * D_ + j0 + j] = f2tf32(o[i][j] * inv[i]);
}

// ---------------------------------------------------------------------------
// Fused residual + LayerNorm: out = LN(res + delta)*gamma + beta; optional tf32 shadow
// ---------------------------------------------------------------------------
template <bool WT>
__global__ __launch_bounds__(256) void ln_kernel(const float* __restrict__ res,
                                                 const float* __restrict__ delta,
                                                 const float* __restrict__ gamma,
                                                 const float* __restrict__ beta,
                                                 float* __restrict__ out,
                                                 uint32_t* __restrict__ out32) {
    int row = blockIdx.x, tid = threadIdx.x;
    size_t base = (size_t)row * D_;
    float4 rv = *(const float4*)(res + base + tid * 4);
    float4 dv = *(const float4*)(delta + base + tid * 4);
    float v0 = rv.x + dv.x, v1 = rv.y + dv.y, v2 = rv.z + dv.z, v3 = rv.w + dv.w;
    float s = v0 + v1 + v2 + v3;
    float q = v0 * v0 + v1 * v1 + v2 * v2 + v3 * v3;
#pragma unroll
    for (int o2 = 16; o2 > 0; o2 >>= 1) {
        s += __shfl_xor_sync(0xffffffffu, s, o2);
        q += __shfl_xor_sync(0xffffffffu, q, o2);
    }
    __shared__ float ss[8], qs[8];
    __shared__ float mean_s, rstd_s;
    if ((tid & 31) == 0) { ss[tid >> 5] = s; qs[tid >> 5] = q; }
    __syncthreads();
    if (tid == 0) {
        float S2 = 0.f, Q2 = 0.f;
#pragma unroll
        for (int w = 0; w < 8; w++) { S2 += ss[w]; Q2 += qs[w]; }
        float mean = S2 * (1.0f / D_);
        float var = Q2 * (1.0f / D_) - mean * mean;
        mean_s = mean;
        rstd_s = rsqrtf(var + 1e-5f);
    }
    __syncthreads();
    float mean = mean_s, rstd = rstd_s;
    float4 gv = *(const float4*)(gamma + tid * 4);
    float4 bv = *(const float4*)(beta + tid * 4);
    float4 ov;
    ov.x = (v0 - mean) * rstd * gv.x + bv.x;
    ov.y = (v1 - mean) * rstd * gv.y + bv.y;
    ov.z = (v2 - mean) * rstd * gv.z + bv.z;
    ov.w = (v3 - mean) * rstd * gv.w + bv.w;
    *(float4*)(out + base + tid * 4) = ov;
    if (WT) {
        uint4 u;
        u.x = f2tf32(ov.x); u.y = f2tf32(ov.y); u.z = f2tf32(ov.z); u.w = f2tf32(ov.w);
        *(uint4*)(out32 + base + tid * 4) = u;
    }
}

// ---------------------------------------------------------------------------
__global__ __launch_bounds__(256) void gather_kernel(const float* __restrict__ x,
                                                     float* __restrict__ xs,
                                                     uint32_t* __restrict__ xs32, int st) {
    int i = blockIdx.x * 256 + threadIdx.x;
    int row = i >> 8;
    int c = i & 255;
    int b = row / st, sl = row % st;
    size_t src = ((size_t)(b * S_ + (S_ - st) + sl) << 8) + c;
    float4 v = ((const float4*)x)[src];
    ((float4*)xs)[i] = v;
    uint4 u;
    u.x = f2tf32(v.x); u.y = f2tf32(v.y); u.z = f2tf32(v.z); u.w = f2tf32(v.w);
    ((uint4*)xs32)[i] = u;
}

__global__ __launch_bounds__(256) void combine_kernel(const float* __restrict__ g,
                                                      const float* __restrict__ y2,
                                                      const float* __restrict__ y4,
                                                      float* __restrict__ out,
                                                      uint32_t* __restrict__ out32) {
    int i = blockIdx.x * 256 + threadIdx.x;
    int row = i >> 8;
    int c = i & 255;
    int b = row >> 10;
    int s = row & 1023;
    float4 v = ((const float4*)g)[i];
    if (s >= 512) {
        float4 a = ((const float4*)y2)[((size_t)(b * 512 + (s - 512)) << 8) + c];
        v.x += a.x; v.y += a.y; v.z += a.z; v.w += a.w;
    }
    if (s >= 768) {
        float4 a = ((const float4*)y4)[((size_t)(b * 256 + (s - 768)) << 8) + c];
        v.x += a.x; v.y += a.y; v.z += a.z; v.w += a.w;
    }
    ((float4*)out)[i] = v;
    uint4 u;
    u.x = f2tf32(v.x); u.y = f2tf32(v.y); u.z = f2tf32(v.z); u.w = f2tf32(v.w);
    ((uint4*)out32)[i] = u;
}

// ---------------------------------------------------------------------------
// Host orchestration
// ---------------------------------------------------------------------------
enum GemmOut { OUT_F32, OUT_TF32 };

static void launch_gemm(const uint32_t* A, const uint32_t* W, const float* bias,
                        float* C, uint32_t* C32, int M, int N, int K,
                        bool relu, GemmOut mode) {
    dim3 grid(N / BN, M / BM);
    if (mode == OUT_F32) {
        tc_gemm_kernel<false, true, false><<<grid, 256, GEMM_SMEM_BYTES>>>(A, W, bias, C, C32, M, N, K);
    } else if (relu) {
        tc_gemm_kernel<true, false, true><<<grid, 256, GEMM_SMEM_BYTES>>>(A, W, bias, C, C32, M, N, K);
    } else {
        tc_gemm_kernel<false, false, true><<<grid, 256, GEMM_SMEM_BYTES>>>(A, W, bias, C, C32, M, N, K);
    }
}

static void launch_cvt(const float* src, uint32_t* dst, int n) {
    cvtw_kernel<<<n / 1024, 256>>>((const float4*)src, (uint4*)dst, n / 4);
}

extern "C" void kernel_launch(void* const* d_in, const int* in_sizes, int n_in,
                              void* d_out, int out_size) {
    (void)in_sizes; (void)n_in; (void)out_size;
    const float* x    = (const float*)d_in[0];
    const float* Wq   = (const float*)d_in[1];
    const float* bq   = (const float*)d_in[2];
    const float* Wk   = (const float*)d_in[3];
    const float* bk   = (const float*)d_in[4];
    const float* Wv   = (const float*)d_in[5];
    const float* bv   = (const float*)d_in[6];
    const float* Wo   = (const float*)d_in[7];
    const float* bo   = (const float*)d_in[8];
    const float* W1   = (const float*)d_in[9];
    const float* b1   = (const float*)d_in[10];
    const float* W2   = (const float*)d_in[11];
    const float* b2   = (const float*)d_in[12];
    const float* n1s  = (const float*)d_in[13];
    const float* n1b  = (const float*)d_in[14];
    const float* n2s  = (const float*)d_in[15];
    const float* n2b  = (const float*)d_in[16];
    const float* ln1s = (const float*)d_in[17];
    const float* ln1b = (const float*)d_in[18];
    const float* ln2s = (const float*)d_in[19];
    const float* ln2b = (const float*)d_in[20];
    const float* ln3s = (const float*)d_in[21];
    const float* ln3b = (const float*)d_in[22];
    const float* Wb   = (const float*)d_in[23];
    const float* bb   = (const float*)d_in[24];
    const float* Wm   = (const float*)d_in[25];
    const float* bm   = (const float*)d_in[26];
    const float* Wf1  = (const float*)d_in[27];
    const float* bf1  = (const float*)d_in[28];
    const float* Wf2  = (const float*)d_in[29];
    const float* bf2  = (const float*)d_in[30];
    float* out = (float*)d_out;

    float *g, *q, *k, *v, *xs, *mo, *y2, *y4, *os, *h;
    uint32_t *tg, *tos, *tao, *txs, *tmid, *tff;
    uint32_t *twq, *twk, *twv, *two, *tw1, *tw2, *twb, *twm, *twf1, *twf2;
    cudaGetSymbolAddress((void**)&g,  g_g);
    cudaGetSymbolAddress((void**)&q,  g_q);
    cudaGetSymbolAddress((void**)&k,  g_k);
    cudaGetSymbolAddress((void**)&v,  g_v);
    cudaGetSymbolAddress((void**)&xs, g_xs);
    cudaGetSymbolAddress((void**)&mo, g_mo);
    cudaGetSymbolAddress((void**)&y2, g_y2);
    cudaGetSymbolAddress((void**)&y4, g_y4);
    cudaGetSymbolAddress((void**)&os, g_os);
    cudaGetSymbolAddress((void**)&h,  g_h);
    cudaGetSymbolAddress((void**)&tg,  t_g);
    cudaGetSymbolAddress((void**)&tos, t_os);
    cudaGetSymbolAddress((void**)&tao, t_ao);
    cudaGetSymbolAddress((void**)&txs, t_xs);
    cudaGetSymbolAddress((void**)&tmid, t_mid);
    cudaGetSymbolAddress((void**)&tff, t_ff);
    cudaGetSymbolAddress((void**)&twq, t_Wq);
    cudaGetSymbolAddress((void**)&twk, t_Wk);
    cudaGetSymbolAddress((void**)&twv, t_Wv);
    cudaGetSymbolAddress((void**)&two, t_Wo);
    cudaGetSymbolAddress((void**)&tw1, t_W1);
    cudaGetSymbolAddress((void**)&tw2, t_W2);
    cudaGetSymbolAddress((void**)&twb, t_Wb);
    cudaGetSymbolAddress((void**)&twm, t_Wm);
    cudaGetSymbolAddress((void**)&twf1, t_Wf1);
    cudaGetSymbolAddress((void**)&twf2, t_Wf2);

    const int ATTN_SMEM = ATTN_SMEM_FLOATS * (int)sizeof(float);
    cudaFuncSetAttribute(attn_kernel, cudaFuncAttributeMaxDynamicSharedMemorySize, ATTN_SMEM);
    cudaFuncSetAttribute(tc_gemm_kernel<false, true, false>,
                         cudaFuncAttributeMaxDynamicSharedMemorySize, GEMM_SMEM_BYTES);
    cudaFuncSetAttribute(tc_gemm_kernel<true, false, true>,
                         cudaFuncAttributeMaxDynamicSharedMemorySize, GEMM_SMEM_BYTES);
    cudaFuncSetAttribute(tc_gemm_kernel<false, false, true>,
                         cudaFuncAttributeMaxDynamicSharedMemorySize, GEMM_SMEM_BYTES);

    // ---- weight conversions (once per launch) ----
    launch_cvt(Wq, twq, L_ * D_ * D_);
    launch_cvt(Wk, twk, L_ * D_ * D_);
    launch_cvt(Wv, twv, L_ * D_ * D_);
    launch_cvt(Wo, two, L_ * D_ * D_);
    launch_cvt(W1, tw1, L_ * D_ * F_);
    launch_cvt(W2, tw2, L_ * F_ * D_);
    launch_cvt(Wb, twb, D_ * M_);
    launch_cvt(Wm, twm, M_ * D_);
    launch_cvt(Wf1, twf1, D_ * F_);
    launch_cvt(Wf2, twf2, F_ * D_);

    // g = x (+ shadow)
    copyx_kernel<<<N_ * D_ / 4 / 256, 256>>>((const float4*)x, (float4*)g, (uint4*)tg, N_ * D_ / 4);

    const int DD = D_ * D_;
    const int DF = D_ * F_;
    for (int i = 0; i < L_; i++) {
        launch_gemm(tg, twq + (size_t)i * DD, bq + i * D_, q, nullptr, N_, D_, D_, false, OUT_F32);
        launch_gemm(tg, twk + (size_t)i * DD, bk + i * D_, k, nullptr, N_, D_, D_, false, OUT_F32);
        launch_gemm(tg, twv + (size_t)i * DD, bv + i * D_, v, nullptr, N_, D_, D_, false, OUT_F32);
        attn_kernel<<<dim3(B_ * H_, S_ / 64), 256, ATTN_SMEM>>>(q, k, v, tao);
        launch_gemm(tao, two + (size_t)i * DD, bo + i * D_, q, nullptr, N_, D_, D_, false, OUT_F32);
        ln_kernel<true><<<N_, 256>>>(g, q, n1s + i * D_, n1b + i * D_, g, tg);
        launch_gemm(tg, tw1 + (size_t)i * DF, b1 + i * F_, nullptr, tff, N_, F_, D_, true, OUT_TF32);
        launch_gemm(tff, tw2 + (size_t)i * DF, b2 + i * D_, q, nullptr, N_, D_, F_, false, OUT_F32);
        ln_kernel<true><<<N_, 256>>>(g, q, n2s + i * D_, n2b + i * D_, g, tg);
    }

    // local(2): st = 512
    {
        const int st = 512, R = B_ * st;
        gather_kernel<<<R, 256>>>(x, xs, txs, st);
        launch_gemm(txs, twb, bb, nullptr, tmid, R, M_, D_, false, OUT_TF32);
        launch_gemm(tmid, twm, bm, mo, nullptr, R, D_, M_, false, OUT_F32);
        ln_kernel<false><<<R, 256>>>(xs, mo, ln1s, ln1b, y2, nullptr);
    }
    // local(4): st = 256
    {
        const int st = 256, R = B_ * st;
        gather_kernel<<<R, 256>>>(x, xs, txs, st);
        launch_gemm(txs, twb, bb, nullptr, tmid, R, M_, D_, false, OUT_TF32);
        launch_gemm(tmid, twm, bm, mo, nullptr, R, D_, M_, false, OUT_F32);
        ln_kernel<false><<<R, 256>>>(xs, mo, ln1s, ln1b, y4, nullptr);
    }

    combine_kernel<<<N_ * D_ / 4 / 256, 256>>>(g, y2, y4, os, tos);
    ln_kernel<false><<<N_, 256>>>(os, x, ln2s, ln2b, h, nullptr);
    launch_gemm(tos, twf1, bf1, nullptr, tff, N_, F_, D_, true, OUT_TF32);
    launch_gemm(tff, twf2, bf2, q, nullptr, N_, D_, F_, false, OUT_F32);
    ln_kernel<false><<<N_, 256>>>(h, q, ln3s, ln3b, out, nullptr);
}

// round 8
// speedup vs baseline: 2.9439x; 1.2337x over previous
#include <cuda_runtime.h>
#include <cstdint>
#include <cstddef>

// Problem constants
#define B_  4
#define S_  1024
#define D_  1024
#define F_  4096
#define M_  512
#define H_  16
#define HD_ 64
#define L_  2
#define N_  (B_ * S_)   // 4096 tokens

// ---------------------------------------------------------------------------
// Scratch buffers (static device globals; no runtime allocation)
// ---------------------------------------------------------------------------
__device__ float g_g [N_ * D_];
__device__ float g_q [N_ * D_];        // generic fp32 delta scratch
__device__ float g_xs[(N_/2) * D_];
__device__ float g_mo[(N_/2) * D_];
__device__ float g_y2[(N_/2) * D_];
__device__ float g_y4[(N_/4) * D_];
__device__ float g_os[N_ * D_];
__device__ float g_h [N_ * D_];
// tf32 shadow buffers
__device__ uint32_t t_g  [N_ * D_];
__device__ uint32_t t_os [N_ * D_];
__device__ uint32_t t_ao [N_ * D_];
__device__ uint32_t t_qkv[N_ * 3 * D_];
__device__ uint32_t t_xs [(N_/2) * D_];
__device__ uint32_t t_mid[(N_/2) * M_];
__device__ uint32_t t_ff [N_ * F_];
// tf32 weight copies
__device__ uint32_t t_Wqkv[L_ * D_ * 3 * D_];
__device__ float    b_qkv [L_ * 3 * D_];
__device__ uint32_t t_Wo [L_ * D_ * D_];
__device__ uint32_t t_W1 [L_ * D_ * F_];
__device__ uint32_t t_W2 [L_ * F_ * D_];
__device__ uint32_t t_Wb [D_ * M_];
__device__ uint32_t t_Wm [M_ * D_];
__device__ uint32_t t_Wf1[D_ * F_];
__device__ uint32_t t_Wf2[F_ * D_];

// ---------------------------------------------------------------------------
__device__ __forceinline__ uint32_t f2tf32(float f) {
    uint32_t r;
    asm("cvt.rna.tf32.f32 %0, %1;" : "=r"(r) : "f"(f));
    return r;
}

__global__ __launch_bounds__(256) void cvtw_kernel(const float4* __restrict__ in,
                                                   uint4* __restrict__ out, int n4) {
    int i = blockIdx.x * 256 + threadIdx.x;
    if (i < n4) {
        float4 v = in[i];
        uint4 o;
        o.x = f2tf32(v.x); o.y = f2tf32(v.y); o.z = f2tf32(v.z); o.w = f2tf32(v.w);
        out[i] = o;
    }
}

// Pack Wq|Wk|Wv into [L][D][3D] tf32
__global__ __launch_bounds__(256) void cvtw_qkv_kernel(const float4* __restrict__ wq,
                                                       const float4* __restrict__ wk,
                                                       const float4* __restrict__ wv,
                                                       uint4* __restrict__ out) {
    int i = blockIdx.x * 256 + threadIdx.x;      // over L_*D_*D_/4
    if (i >= L_ * D_ * D_ / 4) return;
    int c4 = i & (D_ / 4 - 1);                   // 0..255
    int row = i >> 8;                            // l*D + k
    float4 vq = wq[i], vk = wk[i], vv = wv[i];
    uint4 oq, ok, ov;
    oq.x = f2tf32(vq.x); oq.y = f2tf32(vq.y); oq.z = f2tf32(vq.z); oq.w = f2tf32(vq.w);
    ok.x = f2tf32(vk.x); ok.y = f2tf32(vk.y); ok.z = f2tf32(vk.z); ok.w = f2tf32(vk.w);
    ov.x = f2tf32(vv.x); ov.y = f2tf32(vv.y); ov.z = f2tf32(vv.z); ov.w = f2tf32(vv.w);
    size_t ob = (size_t)row * (3 * D_ / 4);
    out[ob + c4]       = oq;
    out[ob + 256 + c4] = ok;
    out[ob + 512 + c4] = ov;
}

__global__ __launch_bounds__(256) void pack_bqkv_kernel(const float* __restrict__ bq,
                                                        const float* __restrict__ bk,
                                                        const float* __restrict__ bv,
                                                        float* __restrict__ o) {
    int i = blockIdx.x * 256 + threadIdx.x;      // over L_*3*D_
    if (i >= L_ * 3 * D_) return;
    int l = i / (3 * D_), j = i % (3 * D_);
    float v;
    if (j < D_)           v = bq[l * D_ + j];
    else if (j < 2 * D_)  v = bk[l * D_ + j - D_];
    else                  v = bv[l * D_ + j - 2 * D_];
    o[i] = v;
}

// x -> g (fp32) + t_g (tf32)
__global__ __launch_bounds__(256) void copyx_kernel(const float4* __restrict__ in,
                                                    float4* __restrict__ out,
                                                    uint4* __restrict__ out32, int n4) {
    int i = blockIdx.x * 256 + threadIdx.x;
    if (i < n4) {
        float4 v = in[i];
        out[i] = v;
        uint4 o;
        o.x = f2tf32(v.x); o.y = f2tf32(v.y); o.z = f2tf32(v.z); o.w = f2tf32(v.w);
        out32[i] = o;
    }
}

// ---------------------------------------------------------------------------
// TF32 tensor-core GEMM with cp.async pipeline (unchanged from R7).
// ---------------------------------------------------------------------------
#define BM 128
#define BN 256
#define BK 16
#define STAGES 3
#define A_STRIDE 20
#define B_STRIDE 264
#define A_WORDS (BM * A_STRIDE)
#define B_WORDS (BK * B_STRIDE)
#define STAGE_WORDS (A_WORDS + B_WORDS)
#define GEMM_SMEM_BYTES (STAGES * STAGE_WORDS * 4)

__device__ __forceinline__ void cp16(uint32_t dst_smem, const void* src) {
    asm volatile("cp.async.cg.shared.global [%0], [%1], 16;\n" :: "r"(dst_smem), "l"(src));
}

__device__ __forceinline__ void mma_tf32(float* c, uint32_t a0, uint32_t a1,
                                         uint32_t a2, uint32_t a3,
                                         uint32_t b0, uint32_t b1) {
    asm volatile(
        "mma.sync.aligned.m16n8k8.row.col.f32.tf32.tf32.f32 "
        "{%0,%1,%2,%3}, {%4,%5,%6,%7}, {%8,%9}, {%0,%1,%2,%3};"
        : "+f"(c[0]), "+f"(c[1]), "+f"(c[2]), "+f"(c[3])
        : "r"(a0), "r"(a1), "r"(a2), "r"(a3), "r"(b0), "r"(b1));
}

template <bool RELU, bool WF, bool WT>
__global__ __launch_bounds__(256, 1) void tc_gemm_kernel(
        const uint32_t* __restrict__ A, const uint32_t* __restrict__ W,
        const float* __restrict__ bias, float* __restrict__ C,
        uint32_t* __restrict__ C32, int M, int N, int K) {
    extern __shared__ __align__(16) uint32_t sm[];
    uint32_t smb = (uint32_t)__cvta_generic_to_shared(sm);

    int tid = threadIdx.x;
    int bx = blockIdx.x, by = blockIdx.y;
    int wid = tid >> 5, lane = tid & 31;
    int warp_m = wid >> 2;
    int warp_n = wid & 3;
    int g = lane >> 2, t4 = lane & 3;

    const uint32_t* Ag = A + (size_t)by * BM * K;
    const uint32_t* Wg = W + (size_t)bx * BN;

    auto issue = [&](int s, int kt) {
        uint32_t base = smb + (uint32_t)(s * STAGE_WORDS) * 4u;
#pragma unroll
        for (int r = 0; r < 2; r++) {
            int c = tid + r * 256;
            int row = c >> 2, u = c & 3;
            cp16(base + (uint32_t)(row * A_STRIDE + u * 4) * 4u,
                 Ag + (size_t)row * K + kt + u * 4);
        }
        uint32_t baseB = base + (uint32_t)A_WORDS * 4u;
#pragma unroll
        for (int r = 0; r < 4; r++) {
            int c = tid + r * 256;
            int k = c >> 6, u = c & 63;
            cp16(baseB + (uint32_t)(k * B_STRIDE + u * 4) * 4u,
                 Wg + (size_t)(kt + k) * N + u * 4);
        }
        asm volatile("cp.async.commit_group;\n" ::);
    };

    float acc[4][8][4];
#pragma unroll
    for (int mi = 0; mi < 4; mi++)
#pragma unroll
        for (int nj = 0; nj < 8; nj++)
#pragma unroll
            for (int e = 0; e < 4; e++) acc[mi][nj][e] = 0.f;

    int nk = K / BK;
#pragma unroll
    for (int s = 0; s < STAGES - 1; s++) issue(s, s * BK);
    asm volatile("cp.async.wait_group %0;\n" :: "n"(STAGES - 2));
    __syncthreads();

    for (int t = 0; t < nk; t++) {
        int pf = t + STAGES - 1;
        if (pf < nk) issue(pf % STAGES, pf * BK);

        const uint32_t* As = sm + (t % STAGES) * STAGE_WORDS;
        const uint32_t* Bs = As + A_WORDS;
#pragma unroll
        for (int k8 = 0; k8 < 2; k8++) {
            uint32_t af[4][4], bf[8][2];
            int acol = k8 * 8 + t4;
#pragma unroll
            for (int mi = 0; mi < 4; mi++) {
                int r = warp_m * 64 + mi * 16 + g;
                af[mi][0] = As[r * A_STRIDE + acol];
                af[mi][1] = As[(r + 8) * A_STRIDE + acol];
                af[mi][2] = As[r * A_STRIDE + acol + 4];
                af[mi][3] = As[(r + 8) * A_STRIDE + acol + 4];
            }
            int brow = acol * B_STRIDE;
            int bcol0 = warp_n * 64 + g;
#pragma unroll
            for (int nj = 0; nj < 8; nj++) {
                bf[nj][0] = Bs[brow + bcol0 + nj * 8];
                bf[nj][1] = Bs[brow + 4 * B_STRIDE + bcol0 + nj * 8];
            }
#pragma unroll
            for (int mi = 0; mi < 4; mi++)
#pragma unroll
                for (int nj = 0; nj < 8; nj++)
                    mma_tf32(acc[mi][nj], af[mi][0], af[mi][1], af[mi][2], af[mi][3],
                             bf[nj][0], bf[nj][1]);
        }

        asm volatile("cp.async.wait_group %0;\n" :: "n"(STAGES - 2));
        __syncthreads();
    }

    int row0 = by * BM + warp_m * 64;
    int col0 = bx * BN + warp_n * 64;
#pragma unroll
    for (int nj = 0; nj < 8; nj++) {
        int cc = col0 + nj * 8 + t4 * 2;
        float b0 = bias[cc], b1 = bias[cc + 1];
#pragma unroll
        for (int mi = 0; mi < 4; mi++) {
            int r = row0 + mi * 16 + g;
            float v00 = acc[mi][nj][0] + b0, v01 = acc[mi][nj][1] + b1;
            float v10 = acc[mi][nj][2] + b0, v11 = acc[mi][nj][3] + b1;
            if (RELU) {
                v00 = fmaxf(v00, 0.f); v01 = fmaxf(v01, 0.f);
                v10 = fmaxf(v10, 0.f); v11 = fmaxf(v11, 0.f);
            }
            if (WF) {
                *(float2*)(C + (size_t)r * N + cc) = make_float2(v00, v01);
                *(float2*)(C + (size_t)(r + 8) * N + cc) = make_float2(v10, v11);
            }
            if (WT) {
                uint2 u0 = make_uint2(f2tf32(v00), f2tf32(v01));
                uint2 u1 = make_uint2(f2tf32(v10), f2tf32(v11));
                *(uint2*)(C32 + (size_t)r * N + cc) = u0;
                *(uint2*)(C32 + (size_t)(r + 8) * N + cc) = u1;
            }
        }
    }
}

// ---------------------------------------------------------------------------
// TF32 tensor-core flash attention.
// Input: packed tf32 QKV [N_][3072] (q|k|v, head h at col h*64 within each D block).
// Output: tf32 attention output [N_][1024].
// Grid (B*H, S/64), 256 threads = 8 warps; warp tile 16x32 of the 64x64 score tile.
// Smem strides: Q/P 68 (=4 mod 32), K 68, V 72 (=8 mod 32) -> conflict-free fragments.
// ---------------------------------------------------------------------------
#define AT_Q_OFF   0
#define AT_KV_OFF  4352                 // 64*68
#define AT_P_OFF   (4352 + 4608)        // + 64*72
#define AT_AUX_OFF 13312                // + 64*68
#define AT_SMEM_WORDS (13312 + 192)
#define AT_SMEM_BYTES (AT_SMEM_WORDS * 4)

__global__ __launch_bounds__(256) void attn_tc_kernel(const uint32_t* __restrict__ QKV,
                                                      uint32_t* __restrict__ O32) {
    extern __shared__ __align__(16) uint32_t smu[];
    uint32_t* Qs  = smu + AT_Q_OFF;
    uint32_t* KVs = smu + AT_KV_OFF;
    uint32_t* Pu  = smu + AT_P_OFF;
    float*    Pf  = (float*)Pu;
    float*    m_s = (float*)(smu + AT_AUX_OFF);
    float*    l_s = m_s + 64;
    float*    a_s = l_s + 64;

    int tid = threadIdx.x;
    int b = blockIdx.x >> 4, h = blockIdx.x & 15;
    int q0 = blockIdx.y * 64;
    int wid = tid >> 5, lane = tid & 31;
    int m0 = (wid >> 1) * 16;
    int n0 = (wid & 1) * 32;
    int g = lane >> 2, t4 = lane & 3;

    size_t base_q = ((size_t)(b * S_ + q0)) * 3072 + h * 64;
    // load Q tile [64 q][64 hd], stride 68
#pragma unroll
    for (int r = 0; r < 4; r++) {
        int idx = tid + r * 256;
        int row = idx >> 4, c = (idx & 15) * 4;
        *(uint4*)&Qs[row * 68 + c] = *(const uint4*)(QKV + base_q + (size_t)row * 3072 + c);
    }
    if (tid < 64) { m_s[tid] = -1e30f; l_s[tid] = 0.f; }

    float acc_o[4][4];
#pragma unroll
    for (int nj = 0; nj < 4; nj++)
#pragma unroll
        for (int e = 0; e < 4; e++) acc_o[nj][e] = 0.f;

    for (int kt = 0; kt < 16; kt++) {
        size_t base_kv = ((size_t)(b * S_ + kt * 64)) * 3072 + h * 64;
        // load K tile [64 key][64 hd], stride 68  (cols D_..2D_)
#pragma unroll
        for (int r = 0; r < 4; r++) {
            int idx = tid + r * 256;
            int row = idx >> 4, c = (idx & 15) * 4;
            *(uint4*)&KVs[row * 68 + c] =
                *(const uint4*)(QKV + base_kv + D_ + (size_t)row * 3072 + c);
        }
        __syncthreads();

        // S = Q K^T : A = Q [m][k], B-frag read from natural K tile via swapped index
        float acc_s[4][4];
#pragma unroll
        for (int nj = 0; nj < 4; nj++)
#pragma unroll
            for (int e = 0; e < 4; e++) acc_s[nj][e] = 0.f;
#pragma unroll
        for (int k8 = 0; k8 < 8; k8++) {
            int kc = k8 * 8 + t4;
            uint32_t a0 = Qs[(m0 + g) * 68 + kc];
            uint32_t a1 = Qs[(m0 + 8 + g) * 68 + kc];
            uint32_t a2 = Qs[(m0 + g) * 68 + kc + 4];
            uint32_t a3 = Qs[(m0 + 8 + g) * 68 + kc + 4];
#pragma unroll
            for (int nj = 0; nj < 4; nj++) {
                int key = n0 + nj * 8 + g;
                uint32_t b0 = KVs[key * 68 + kc];
                uint32_t b1 = KVs[key * 68 + kc + 4];
                mma_tf32(acc_s[nj], a0, a1, a2, a3, b0, b1);
            }
        }
        // write scaled scores (fp32) to P
#pragma unroll
        for (int nj = 0; nj < 4; nj++) {
            int cc = n0 + nj * 8 + t4 * 2;
            *(float2*)&Pf[(m0 + g) * 68 + cc] =
                make_float2(acc_s[nj][0] * 0.125f, acc_s[nj][1] * 0.125f);
            *(float2*)&Pf[(m0 + 8 + g) * 68 + cc] =
                make_float2(acc_s[nj][2] * 0.125f, acc_s[nj][3] * 0.125f);
        }
        __syncthreads();

        // load V tile [64 key][64 hd], stride 72 (cols 2D_..3D_); overwrites K
#pragma unroll
        for (int r = 0; r < 4; r++) {
            int idx = tid + r * 256;
            int row = idx >> 4, c = (idx & 15) * 4;
            *(uint4*)&KVs[row * 72 + c] =
                *(const uint4*)(QKV + base_kv + 2 * D_ + (size_t)row * 3072 + c);
        }
        // softmax: 4 lanes per row, 16 cols each; in-place fp32 -> tf32
        {
            int r = tid >> 2;
            int qd = tid & 3;
            float* Pr = Pf + r * 68 + qd * 16;
            uint32_t* Pru = Pu + r * 68 + qd * 16;
            float vals[16];
#pragma unroll
            for (int j = 0; j < 16; j++) vals[j] = Pr[j];
            float mx = -1e30f;
#pragma unroll
            for (int j = 0; j < 16; j++) mx = fmaxf(mx, vals[j]);
            mx = fmaxf(mx, __shfl_xor_sync(0xffffffffu, mx, 1));
            mx = fmaxf(mx, __shfl_xor_sync(0xffffffffu, mx, 2));
            float mold = m_s[r];
            mx = fmaxf(mx, mold);
            float sum = 0.f;
#pragma unroll
            for (int j = 0; j < 16; j++) {
                float e = __expf(vals[j] - mx);
                Pru[j] = f2tf32(e);
                sum += e;
            }
            sum += __shfl_xor_sync(0xffffffffu, sum, 1);
            sum += __shfl_xor_sync(0xffffffffu, sum, 2);
            if (qd == 0) {
                float al = __expf(mold - mx);
                l_s[r] = l_s[r] * al + sum;
                m_s[r] = mx;
                a_s[r] = al;
            }
        }
        __syncthreads();

        // O = O*alpha + P V
        float al0 = a_s[m0 + g], al1 = a_s[m0 + 8 + g];
#pragma unroll
        for (int nj = 0; nj < 4; nj++) {
            acc_o[nj][0] *= al0; acc_o[nj][1] *= al0;
            acc_o[nj][2] *= al1; acc_o[nj][3] *= al1;
        }
#pragma unroll
        for (int k8 = 0; k8 < 8; k8++) {
            int kc = k8 * 8 + t4;
            uint32_t a0 = Pu[(m0 + g) * 68 + kc];
            uint32_t a1 = Pu[(m0 + 8 + g) * 68 + kc];
            uint32_t a2 = Pu[(m0 + g) * 68 + kc + 4];
            uint32_t a3 = Pu[(m0 + 8 + g) * 68 + kc + 4];
#pragma unroll
            for (int nj = 0; nj < 4; nj++) {
                int hc = n0 + nj * 8 + g;
                uint32_t b0 = KVs[kc * 72 + hc];
                uint32_t b1 = KVs[(kc + 4) * 72 + hc];
                mma_tf32(acc_o[nj], a0, a1, a2, a3, b0, b1);
            }
        }
        __syncthreads();
    }

    float inv0 = 1.f / l_s[m0 + g];
    float inv1 = 1.f / l_s[m0 + 8 + g];
    size_t base_o = ((size_t)(b * S_ + q0)) * D_ + h * 64;
#pragma unroll
    for (int nj = 0; nj < 4; nj++) {
        int cc = n0 + nj * 8 + t4 * 2;
        uint2 u0 = make_uint2(f2tf32(acc_o[nj][0] * inv0), f2tf32(acc_o[nj][1] * inv0));
        uint2 u1 = make_uint2(f2tf32(acc_o[nj][2] * inv1), f2tf32(acc_o[nj][3] * inv1));
        *(uint2*)(O32 + base_o + (size_t)(m0 + g) * D_ + cc) = u0;
        *(uint2*)(O32 + base_o + (size_t)(m0 + 8 + g) * D_ + cc) = u1;
    }
}

// ---------------------------------------------------------------------------
// Fused residual + LayerNorm
// ---------------------------------------------------------------------------
template <bool WT>
__global__ __launch_bounds__(256) void ln_kernel(const float* __restrict__ res,
                                                 const float* __restrict__ delta,
                                                 const float* __restrict__ gamma,
                                                 const float* __restrict__ beta,
                                                 float* __restrict__ out,
                                                 uint32_t* __restrict__ out32) {
    int row = blockIdx.x, tid = threadIdx.x;
    size_t base = (size_t)row * D_;
    float4 rv = *(const float4*)(res + base + tid * 4);
    float4 dv = *(const float4*)(delta + base + tid * 4);
    float v0 = rv.x + dv.x, v1 = rv.y + dv.y, v2 = rv.z + dv.z, v3 = rv.w + dv.w;
    float s = v0 + v1 + v2 + v3;
    float q = v0 * v0 + v1 * v1 + v2 * v2 + v3 * v3;
#pragma unroll
    for (int o2 = 16; o2 > 0; o2 >>= 1) {
        s += __shfl_xor_sync(0xffffffffu, s, o2);
        q += __shfl_xor_sync(0xffffffffu, q, o2);
    }
    __shared__ float ss[8], qs[8];
    __shared__ float mean_s, rstd_s;
    if ((tid & 31) == 0) { ss[tid >> 5] = s; qs[tid >> 5] = q; }
    __syncthreads();
    if (tid == 0) {
        float S2 = 0.f, Q2 = 0.f;
#pragma unroll
        for (int w = 0; w < 8; w++) { S2 += ss[w]; Q2 += qs[w]; }
        float mean = S2 * (1.0f / D_);
        float var = Q2 * (1.0f / D_) - mean * mean;
        mean_s = mean;
        rstd_s = rsqrtf(var + 1e-5f);
    }
    __syncthreads();
    float mean = mean_s, rstd = rstd_s;
    float4 gv = *(const float4*)(gamma + tid * 4);
    float4 bv = *(const float4*)(beta + tid * 4);
    float4 ov;
    ov.x = (v0 - mean) * rstd * gv.x + bv.x;
    ov.y = (v1 - mean) * rstd * gv.y + bv.y;
    ov.z = (v2 - mean) * rstd * gv.z + bv.z;
    ov.w = (v3 - mean) * rstd * gv.w + bv.w;
    *(float4*)(out + base + tid * 4) = ov;
    if (WT) {
        uint4 u;
        u.x = f2tf32(ov.x); u.y = f2tf32(ov.y); u.z = f2tf32(ov.z); u.w = f2tf32(ov.w);
        *(uint4*)(out32 + base + tid * 4) = u;
    }
}

// ---------------------------------------------------------------------------
__global__ __launch_bounds__(256) void gather_kernel(const float* __restrict__ x,
                                                     float* __restrict__ xs,
                                                     uint32_t* __restrict__ xs32, int st) {
    int i = blockIdx.x * 256 + threadIdx.x;
    int row = i >> 8;
    int c = i & 255;
    int b = row / st, sl = row % st;
    size_t src = ((size_t)(b * S_ + (S_ - st) + sl) << 8) + c;
    float4 v = ((const float4*)x)[src];
    ((float4*)xs)[i] = v;
    uint4 u;
    u.x = f2tf32(v.x); u.y = f2tf32(v.y); u.z = f2tf32(v.z); u.w = f2tf32(v.w);
    ((uint4*)xs32)[i] = u;
}

__global__ __launch_bounds__(256) void combine_kernel(const float* __restrict__ g,
                                                      const float* __restrict__ y2,
                                                      const float* __restrict__ y4,
                                                      float* __restrict__ out,
                                                      uint32_t* __restrict__ out32) {
    int i = blockIdx.x * 256 + threadIdx.x;
    int row = i >> 8;
    int c = i & 255;
    int b = row >> 10;
    int s = row & 1023;
    float4 v = ((const float4*)g)[i];
    if (s >= 512) {
        float4 a = ((const float4*)y2)[((size_t)(b * 512 + (s - 512)) << 8) + c];
        v.x += a.x; v.y += a.y; v.z += a.z; v.w += a.w;
    }
    if (s >= 768) {
        float4 a = ((const float4*)y4)[((size_t)(b * 256 + (s - 768)) << 8) + c];
        v.x += a.x; v.y += a.y; v.z += a.z; v.w += a.w;
    }
    ((float4*)out)[i] = v;
    uint4 u;
    u.x = f2tf32(v.x); u.y = f2tf32(v.y); u.z = f2tf32(v.z); u.w = f2tf32(v.w);
    ((uint4*)out32)[i] = u;
}

// ---------------------------------------------------------------------------
// Host orchestration
// ---------------------------------------------------------------------------
enum GemmOut { OUT_F32, OUT_TF32 };

static void launch_gemm(const uint32_t* A, const uint32_t* W, const float* bias,
                        float* C, uint32_t* C32, int M, int N, int K,
                        bool relu, GemmOut mode) {
    dim3 grid(N / BN, M / BM);
    if (mode == OUT_F32) {
        tc_gemm_kernel<false, true, false><<<grid, 256, GEMM_SMEM_BYTES>>>(A, W, bias, C, C32, M, N, K);
    } else if (relu) {
        tc_gemm_kernel<true, false, true><<<grid, 256, GEMM_SMEM_BYTES>>>(A, W, bias, C, C32, M, N, K);
    } else {
        tc_gemm_kernel<false, false, true><<<grid, 256, GEMM_SMEM_BYTES>>>(A, W, bias, C, C32, M, N, K);
    }
}

static void launch_cvt(const float* src, uint32_t* dst, int n) {
    cvtw_kernel<<<n / 1024, 256>>>((const float4*)src, (uint4*)dst, n / 4);
}

extern "C" void kernel_launch(void* const* d_in, const int* in_sizes, int n_in,
                              void* d_out, int out_size) {
    (void)in_sizes; (void)n_in; (void)out_size;
    const float* x    = (const float*)d_in[0];
    const float* Wq   = (const float*)d_in[1];
    const float* bq   = (const float*)d_in[2];
    const float* Wk   = (const float*)d_in[3];
    const float* bk   = (const float*)d_in[4];
    const float* Wv   = (const float*)d_in[5];
    const float* bv   = (const float*)d_in[6];
    const float* Wo   = (const float*)d_in[7];
    const float* bo   = (const float*)d_in[8];
    const float* W1   = (const float*)d_in[9];
    const float* b1   = (const float*)d_in[10];
    const float* W2   = (const float*)d_in[11];
    const float* b2   = (const float*)d_in[12];
    const float* n1s  = (const float*)d_in[13];
    const float* n1b  = (const float*)d_in[14];
    const float* n2s  = (const float*)d_in[15];
    const float* n2b  = (const float*)d_in[16];
    const float* ln1s = (const float*)d_in[17];
    const float* ln1b = (const float*)d_in[18];
    const float* ln2s = (const float*)d_in[19];
    const float* ln2b = (const float*)d_in[20];
    const float* ln3s = (const float*)d_in[21];
    const float* ln3b = (const float*)d_in[22];
    const float* Wb   = (const float*)d_in[23];
    const float* bb   = (const float*)d_in[24];
    const float* Wm   = (const float*)d_in[25];
    const float* bm   = (const float*)d_in[26];
    const float* Wf1  = (const float*)d_in[27];
    const float* bf1  = (const float*)d_in[28];
    const float* Wf2  = (const float*)d_in[29];
    const float* bf2  = (const float*)d_in[30];
    float* out = (float*)d_out;

    float *g, *q, *xs, *mo, *y2, *y4, *os, *h, *bqkv;
    uint32_t *tg, *tos, *tao, *tqkv, *txs, *tmid, *tff;
    uint32_t *twqkv, *two, *tw1, *tw2, *twb, *twm, *twf1, *twf2;
    cudaGetSymbolAddress((void**)&g,  g_g);
    cudaGetSymbolAddress((void**)&q,  g_q);
    cudaGetSymbolAddress((void**)&xs, g_xs);
    cudaGetSymbolAddress((void**)&mo, g_mo);
    cudaGetSymbolAddress((void**)&y2, g_y2);
    cudaGetSymbolAddress((void**)&y4, g_y4);
    cudaGetSymbolAddress((void**)&os, g_os);
    cudaGetSymbolAddress((void**)&h,  g_h);
    cudaGetSymbolAddress((void**)&tg,  t_g);
    cudaGetSymbolAddress((void**)&tos, t_os);
    cudaGetSymbolAddress((void**)&tao, t_ao);
    cudaGetSymbolAddress((void**)&tqkv, t_qkv);
    cudaGetSymbolAddress((void**)&txs, t_xs);
    cudaGetSymbolAddress((void**)&tmid, t_mid);
    cudaGetSymbolAddress((void**)&tff, t_ff);
    cudaGetSymbolAddress((void**)&twqkv, t_Wqkv);
    cudaGetSymbolAddress((void**)&bqkv, b_qkv);
    cudaGetSymbolAddress((void**)&two, t_Wo);
    cudaGetSymbolAddress((void**)&tw1, t_W1);
    cudaGetSymbolAddress((void**)&tw2, t_W2);
    cudaGetSymbolAddress((void**)&twb, t_Wb);
    cudaGetSymbolAddress((void**)&twm, t_Wm);
    cudaGetSymbolAddress((void**)&twf1, t_Wf1);
    cudaGetSymbolAddress((void**)&twf2, t_Wf2);

    cudaFuncSetAttribute(attn_tc_kernel, cudaFuncAttributeMaxDynamicSharedMemorySize, AT_SMEM_BYTES);
    cudaFuncSetAttribute(tc_gemm_kernel<false, true, false>,
                         cudaFuncAttributeMaxDynamicSharedMemorySize, GEMM_SMEM_BYTES);
    cudaFuncSetAttribute(tc_gemm_kernel<true, false, true>,
                         cudaFuncAttributeMaxDynamicSharedMemorySize, GEMM_SMEM_BYTES);
    cudaFuncSetAttribute(tc_gemm_kernel<false, false, true>,
                         cudaFuncAttributeMaxDynamicSharedMemorySize, GEMM_SMEM_BYTES);

    // ---- weight conversions (once per launch) ----
    cvtw_qkv_kernel<<<(L_ * D_ * D_ / 4) / 256, 256>>>(
        (const float4*)Wq, (const float4*)Wk, (const float4*)Wv, (uint4*)twqkv);
    pack_bqkv_kernel<<<(L_ * 3 * D_ + 255) / 256, 256>>>(bq, bk, bv, bqkv);
    launch_cvt(Wo, two, L_ * D_ * D_);
    launch_cvt(W1, tw1, L_ * D_ * F_);
    launch_cvt(W2, tw2, L_ * F_ * D_);
    launch_cvt(Wb, twb, D_ * M_);
    launch_cvt(Wm, twm, M_ * D_);
    launch_cvt(Wf1, twf1, D_ * F_);
    launch_cvt(Wf2, twf2, F_ * D_);

    // g = x (+ shadow)
    copyx_kernel<<<N_ * D_ / 4 / 256, 256>>>((const float4*)x, (float4*)g, (uint4*)tg, N_ * D_ / 4);

    const int DD = D_ * D_;
    const int DF = D_ * F_;
    for (int i = 0; i < L_; i++) {
        // fused QKV projection (tf32 out)
        launch_gemm(tg, twqkv + (size_t)i * D_ * 3 * D_, bqkv + i * 3 * D_,
                    nullptr, tqkv, N_, 3 * D_, D_, false, OUT_TF32);
        // tensor-core flash attention
        attn_tc_kernel<<<dim3(B_ * H_, S_ / 64), 256, AT_SMEM_BYTES>>>(tqkv, tao);
        // output projection (fp32 out, delta for LN)
        launch_gemm(tao, two + (size_t)i * DD, bo + i * D_, q, nullptr, N_, D_, D_, false, OUT_F32);
        ln_kernel<true><<<N_, 256>>>(g, q, n1s + i * D_, n1b + i * D_, g, tg);
        // FFN
        launch_gemm(tg, tw1 + (size_t)i * DF, b1 + i * F_, nullptr, tff, N_, F_, D_, true, OUT_TF32);
        launch_gemm(tff, tw2 + (size_t)i * DF, b2 + i * D_, q, nullptr, N_, D_, F_, false, OUT_F32);
        ln_kernel<true><<<N_, 256>>>(g, q, n2s + i * D_, n2b + i * D_, g, tg);
    }

    // local(2): st = 512
    {
        const int st = 512, R = B_ * st;
        gather_kernel<<<R, 256>>>(x, xs, txs, st);
        launch_gemm(txs, twb, bb, nullptr, tmid, R, M_, D_, false, OUT_TF32);
        launch_gemm(tmid, twm, bm, mo, nullptr, R, D_, M_, false, OUT_F32);
        ln_kernel<false><<<R, 256>>>(xs, mo, ln1s, ln1b, y2, nullptr);
    }
    // local(4): st = 256
    {
        const int st = 256, R = B_ * st;
        gather_kernel<<<R, 256>>>(x, xs, txs, st);
        launch_gemm(txs, twb, bb, nullptr, tmid, R, M_, D_, false, OUT_TF32);
        launch_gemm(tmid, twm, bm, mo, nullptr, R, D_, M_, false, OUT_F32);
        ln_kernel<false><<<R, 256>>>(xs, mo, ln1s, ln1b, y4, nullptr);
    }

    combine_kernel<<<N_ * D_ / 4 / 256, 256>>>(g, y2, y4, os, tos);
    ln_kernel<false><<<N_, 256>>>(os, x, ln2s, ln2b, h, nullptr);
    launch_gemm(tos, twf1, bf1, nullptr, tff, N_, F_, D_, true, OUT_TF32);
    launch_gemm(tff, twf2, bf2, q, nullptr, N_, D_, F_, false, OUT_F32);
    ln_kernel<false><<<N_, 256>>>(h, q, ln3s, ln3b, out, nullptr);
}

// round 9
// speedup vs baseline: 3.0565x; 1.0382x over previous
#include <cuda_runtime.h>
#include <cstdint>
#include <cstddef>

// Problem constants
#define B_  4
#define S_  1024
#define D_  1024
#define F_  4096
#define M_  512
#define H_  16
#define HD_ 64
#define L_  2
#define N_  (B_ * S_)   // 4096 tokens
#define RL_ 3072        // fused local rows (2048 + 1024)

// ---------------------------------------------------------------------------
// Scratch buffers (static device globals; no runtime allocation)
// ---------------------------------------------------------------------------
__device__ float g_g [N_ * D_];
__device__ float g_q [N_ * D_];        // generic fp32 delta scratch
__device__ float g_xs [RL_ * D_];
__device__ float g_mo [RL_ * D_];
__device__ float g_y24[RL_ * D_];
__device__ float g_os[N_ * D_];
__device__ float g_h [N_ * D_];
// tf32 shadow buffers
__device__ uint32_t t_g  [N_ * D_];
__device__ uint32_t t_os [N_ * D_];
__device__ uint32_t t_ao [N_ * D_];
__device__ uint32_t t_qkv[N_ * 3 * D_];
__device__ uint32_t t_xs [RL_ * D_];
__device__ uint32_t t_mid[RL_ * M_];
__device__ uint32_t t_ff [N_ * F_];
// tf32 weight copies
__device__ uint32_t t_Wqkv[L_ * D_ * 3 * D_];
__device__ float    b_qkv [L_ * 3 * D_];
__device__ uint32_t t_Wo [L_ * D_ * D_];
__device__ uint32_t t_W1 [L_ * D_ * F_];
__device__ uint32_t t_W2 [L_ * F_ * D_];
__device__ uint32_t t_Wb [D_ * M_];
__device__ uint32_t t_Wm [M_ * D_];
__device__ uint32_t t_Wf1[D_ * F_];
__device__ uint32_t t_Wf2[F_ * D_];

// ---------------------------------------------------------------------------
__device__ __forceinline__ uint32_t f2tf32(float f) {
    uint32_t r;
    asm("cvt.rna.tf32.f32 %0, %1;" : "=r"(r) : "f"(f));
    return r;
}

__global__ __launch_bounds__(256) void cvtw_kernel(const float4* __restrict__ in,
                                                   uint4* __restrict__ out, int n4) {
    int i = blockIdx.x * 256 + threadIdx.x;
    if (i < n4) {
        float4 v = in[i];
        uint4 o;
        o.x = f2tf32(v.x); o.y = f2tf32(v.y); o.z = f2tf32(v.z); o.w = f2tf32(v.w);
        out[i] = o;
    }
}

// Pack Wq|Wk|Wv into [L][D][3D] tf32
__global__ __launch_bounds__(256) void cvtw_qkv_kernel(const float4* __restrict__ wq,
                                                       const float4* __restrict__ wk,
                                                       const float4* __restrict__ wv,
                                                       uint4* __restrict__ out) {
    int i = blockIdx.x * 256 + threadIdx.x;
    if (i >= L_ * D_ * D_ / 4) return;
    int c4 = i & (D_ / 4 - 1);
    int row = i >> 8;
    float4 vq = wq[i], vk = wk[i], vv = wv[i];
    uint4 oq, ok, ov;
    oq.x = f2tf32(vq.x); oq.y = f2tf32(vq.y); oq.z = f2tf32(vq.z); oq.w = f2tf32(vq.w);
    ok.x = f2tf32(vk.x); ok.y = f2tf32(vk.y); ok.z = f2tf32(vk.z); ok.w = f2tf32(vk.w);
    ov.x = f2tf32(vv.x); ov.y = f2tf32(vv.y); ov.z = f2tf32(vv.z); ov.w = f2tf32(vv.w);
    size_t ob = (size_t)row * (3 * D_ / 4);
    out[ob + c4]       = oq;
    out[ob + 256 + c4] = ok;
    out[ob + 512 + c4] = ov;
}

__global__ __launch_bounds__(256) void pack_bqkv_kernel(const float* __restrict__ bq,
                                                        const float* __restrict__ bk,
                                                        const float* __restrict__ bv,
                                                        float* __restrict__ o) {
    int i = blockIdx.x * 256 + threadIdx.x;
    if (i >= L_ * 3 * D_) return;
    int l = i / (3 * D_), j = i % (3 * D_);
    float v;
    if (j < D_)           v = bq[l * D_ + j];
    else if (j < 2 * D_)  v = bk[l * D_ + j - D_];
    else                  v = bv[l * D_ + j - 2 * D_];
    o[i] = v;
}

// x -> g (fp32) + t_g (tf32)
__global__ __launch_bounds__(256) void copyx_kernel(const float4* __restrict__ in,
                                                    float4* __restrict__ out,
                                                    uint4* __restrict__ out32, int n4) {
    int i = blockIdx.x * 256 + threadIdx.x;
    if (i < n4) {
        float4 v = in[i];
        out[i] = v;
        uint4 o;
        o.x = f2tf32(v.x); o.y = f2tf32(v.y); o.z = f2tf32(v.z); o.w = f2tf32(v.w);
        out32[i] = o;
    }
}

// ---------------------------------------------------------------------------
// TF32 tensor-core GEMM with cp.async pipeline.
// Mainloop: batched fragment LDS for the full k-tile, then pure MMA stretch.
// ---------------------------------------------------------------------------
#define BM 128
#define BN 256
#define BK 16
#define STAGES 3
#define A_STRIDE 20
#define B_STRIDE 264
#define A_WORDS (BM * A_STRIDE)
#define B_WORDS (BK * B_STRIDE)
#define STAGE_WORDS (A_WORDS + B_WORDS)
#define GEMM_SMEM_BYTES (STAGES * STAGE_WORDS * 4)

__device__ __forceinline__ void cp16(uint32_t dst_smem, const void* src) {
    asm volatile("cp.async.cg.shared.global [%0], [%1], 16;\n" :: "r"(dst_smem), "l"(src));
}

__device__ __forceinline__ void mma_tf32(float* c, uint32_t a0, uint32_t a1,
                                         uint32_t a2, uint32_t a3,
                                         uint32_t b0, uint32_t b1) {
    asm volatile(
        "mma.sync.aligned.m16n8k8.row.col.f32.tf32.tf32.f32 "
        "{%0,%1,%2,%3}, {%4,%5,%6,%7}, {%8,%9}, {%0,%1,%2,%3};"
        : "+f"(c[0]), "+f"(c[1]), "+f"(c[2]), "+f"(c[3])
        : "r"(a0), "r"(a1), "r"(a2), "r"(a3), "r"(b0), "r"(b1));
}

template <bool RELU, bool WF, bool WT>
__global__ __launch_bounds__(256, 1) void tc_gemm_kernel(
        const uint32_t* __restrict__ A, const uint32_t* __restrict__ W,
        const float* __restrict__ bias, float* __restrict__ C,
        uint32_t* __restrict__ C32, int M, int N, int K) {
    extern __shared__ __align__(16) uint32_t sm[];
    uint32_t smb = (uint32_t)__cvta_generic_to_shared(sm);

    int tid = threadIdx.x;
    int bx = blockIdx.x, by = blockIdx.y;
    int wid = tid >> 5, lane = tid & 31;
    int warp_m = wid >> 2;
    int warp_n = wid & 3;
    int g = lane >> 2, t4 = lane & 3;

    const uint32_t* Ag = A + (size_t)by * BM * K;
    const uint32_t* Wg = W + (size_t)bx * BN;

    auto issue = [&](int s, int kt) {
        uint32_t base = smb + (uint32_t)(s * STAGE_WORDS) * 4u;
#pragma unroll
        for (int r = 0; r < 2; r++) {
            int c = tid + r * 256;
            int row = c >> 2, u = c & 3;
            cp16(base + (uint32_t)(row * A_STRIDE + u * 4) * 4u,
                 Ag + (size_t)row * K + kt + u * 4);
        }
        uint32_t baseB = base + (uint32_t)A_WORDS * 4u;
#pragma unroll
        for (int r = 0; r < 4; r++) {
            int c = tid + r * 256;
            int k = c >> 6, u = c & 63;
            cp16(baseB + (uint32_t)(k * B_STRIDE + u * 4) * 4u,
                 Wg + (size_t)(kt + k) * N + u * 4);
        }
        asm volatile("cp.async.commit_group;\n" ::);
    };

    float acc[4][8][4];
#pragma unroll
    for (int mi = 0; mi < 4; mi++)
#pragma unroll
        for (int nj = 0; nj < 8; nj++)
#pragma unroll
            for (int e = 0; e < 4; e++) acc[mi][nj][e] = 0.f;

    int nk = K / BK;
#pragma unroll
    for (int s = 0; s < STAGES - 1; s++) issue(s, s * BK);
    asm volatile("cp.async.wait_group %0;\n" :: "n"(STAGES - 2));
    __syncthreads();

    for (int t = 0; t < nk; t++) {
        int pf = t + STAGES - 1;
        if (pf < nk) issue(pf % STAGES, pf * BK);

        const uint32_t* As = sm + (t % STAGES) * STAGE_WORDS;
        const uint32_t* Bs = As + A_WORDS;

        // --- batched fragment loads for the full k-tile (both k8 halves) ---
        uint32_t af[2][4][4], bf[2][8][2];
#pragma unroll
        for (int k8 = 0; k8 < 2; k8++) {
            int acol = k8 * 8 + t4;
#pragma unroll
            for (int mi = 0; mi < 4; mi++) {
                int r = warp_m * 64 + mi * 16 + g;
                af[k8][mi][0] = As[r * A_STRIDE + acol];
                af[k8][mi][1] = As[(r + 8) * A_STRIDE + acol];
                af[k8][mi][2] = As[r * A_STRIDE + acol + 4];
                af[k8][mi][3] = As[(r + 8) * A_STRIDE + acol + 4];
            }
            int brow = acol * B_STRIDE;
            int bcol0 = warp_n * 64 + g;
#pragma unroll
            for (int nj = 0; nj < 8; nj++) {
                bf[k8][nj][0] = Bs[brow + bcol0 + nj * 8];
                bf[k8][nj][1] = Bs[brow + 4 * B_STRIDE + bcol0 + nj * 8];
            }
        }
        // --- pure MMA stretch ---
#pragma unroll
        for (int k8 = 0; k8 < 2; k8++)
#pragma unroll
            for (int mi = 0; mi < 4; mi++)
#pragma unroll
                for (int nj = 0; nj < 8; nj++)
                    mma_tf32(acc[mi][nj], af[k8][mi][0], af[k8][mi][1],
                             af[k8][mi][2], af[k8][mi][3],
                             bf[k8][nj][0], bf[k8][nj][1]);

        asm volatile("cp.async.wait_group %0;\n" :: "n"(STAGES - 2));
        __syncthreads();
    }

    int row0 = by * BM + warp_m * 64;
    int col0 = bx * BN + warp_n * 64;
#pragma unroll
    for (int nj = 0; nj < 8; nj++) {
        int cc = col0 + nj * 8 + t4 * 2;
        float b0 = bias[cc], b1 = bias[cc + 1];
#pragma unroll
        for (int mi = 0; mi < 4; mi++) {
            int r = row0 + mi * 16 + g;
            float v00 = acc[mi][nj][0] + b0, v01 = acc[mi][nj][1] + b1;
            float v10 = acc[mi][nj][2] + b0, v11 = acc[mi][nj][3] + b1;
            if (RELU) {
                v00 = fmaxf(v00, 0.f); v01 = fmaxf(v01, 0.f);
                v10 = fmaxf(v10, 0.f); v11 = fmaxf(v11, 0.f);
            }
            if (WF) {
                *(float2*)(C + (size_t)r * N + cc) = make_float2(v00, v01);
                *(float2*)(C + (size_t)(r + 8) * N + cc) = make_float2(v10, v11);
            }
            if (WT) {
                uint2 u0 = make_uint2(f2tf32(v00), f2tf32(v01));
                uint2 u1 = make_uint2(f2tf32(v10), f2tf32(v11));
                *(uint2*)(C32 + (size_t)r * N + cc) = u0;
                *(uint2*)(C32 + (size_t)(r + 8) * N + cc) = u1;
            }
        }
    }
}

// ---------------------------------------------------------------------------
// TF32 tensor-core flash attention (unchanged from R8).
// ---------------------------------------------------------------------------
#define AT_Q_OFF   0
#define AT_KV_OFF  4352
#define AT_P_OFF   (4352 + 4608)
#define AT_AUX_OFF 13312
#define AT_SMEM_WORDS (13312 + 192)
#define AT_SMEM_BYTES (AT_SMEM_WORDS * 4)

__global__ __launch_bounds__(256) void attn_tc_kernel(const uint32_t* __restrict__ QKV,
                                                      uint32_t* __restrict__ O32) {
    extern __shared__ __align__(16) uint32_t smu[];
    uint32_t* Qs  = smu + AT_Q_OFF;
    uint32_t* KVs = smu + AT_KV_OFF;
    uint32_t* Pu  = smu + AT_P_OFF;
    float*    Pf  = (float*)Pu;
    float*    m_s = (float*)(smu + AT_AUX_OFF);
    float*    l_s = m_s + 64;
    float*    a_s = l_s + 64;

    int tid = threadIdx.x;
    int b = blockIdx.x >> 4, h = blockIdx.x & 15;
    int q0 = blockIdx.y * 64;
    int wid = tid >> 5, lane = tid & 31;
    int m0 = (wid >> 1) * 16;
    int n0 = (wid & 1) * 32;
    int g = lane >> 2, t4 = lane & 3;

    size_t base_q = ((size_t)(b * S_ + q0)) * 3072 + h * 64;
#pragma unroll
    for (int r = 0; r < 4; r++) {
        int idx = tid + r * 256;
        int row = idx >> 4, c = (idx & 15) * 4;
        *(uint4*)&Qs[row * 68 + c] = *(const uint4*)(QKV + base_q + (size_t)row * 3072 + c);
    }
    if (tid < 64) { m_s[tid] = -1e30f; l_s[tid] = 0.f; }

    float acc_o[4][4];
#pragma unroll
    for (int nj = 0; nj < 4; nj++)
#pragma unroll
        for (int e = 0; e < 4; e++) acc_o[nj][e] = 0.f;

    for (int kt = 0; kt < 16; kt++) {
        size_t base_kv = ((size_t)(b * S_ + kt * 64)) * 3072 + h * 64;
#pragma unroll
        for (int r = 0; r < 4; r++) {
            int idx = tid + r * 256;
            int row = idx >> 4, c = (idx & 15) * 4;
            *(uint4*)&KVs[row * 68 + c] =
                *(const uint4*)(QKV + base_kv + D_ + (size_t)row * 3072 + c);
        }
        __syncthreads();

        float acc_s[4][4];
#pragma unroll
        for (int nj = 0; nj < 4; nj++)
#pragma unroll
            for (int e = 0; e < 4; e++) acc_s[nj][e] = 0.f;
#pragma unroll
        for (int k8 = 0; k8 < 8; k8++) {
            int kc = k8 * 8 + t4;
            uint32_t a0 = Qs[(m0 + g) * 68 + kc];
            uint32_t a1 = Qs[(m0 + 8 + g) * 68 + kc];
            uint32_t a2 = Qs[(m0 + g) * 68 + kc + 4];
            uint32_t a3 = Qs[(m0 + 8 + g) * 68 + kc + 4];
#pragma unroll
            for (int nj = 0; nj < 4; nj++) {
                int key = n0 + nj * 8 + g;
                uint32_t b0 = KVs[key * 68 + kc];
                uint32_t b1 = KVs[key * 68 + kc + 4];
                mma_tf32(acc_s[nj], a0, a1, a2, a3, b0, b1);
            }
        }
#pragma unroll
        for (int nj = 0; nj < 4; nj++) {
            int cc = n0 + nj * 8 + t4 * 2;
            *(float2*)&Pf[(m0 + g) * 68 + cc] =
                make_float2(acc_s[nj][0] * 0.125f, acc_s[nj][1] * 0.125f);
            *(float2*)&Pf[(m0 + 8 + g) * 68 + cc] =
                make_float2(acc_s[nj][2] * 0.125f, acc_s[nj][3] * 0.125f);
        }
        __syncthreads();

#pragma unroll
        for (int r = 0; r < 4; r++) {
            int idx = tid + r * 256;
            int row = idx >> 4, c = (idx & 15) * 4;
            *(uint4*)&KVs[row * 72 + c] =
                *(const uint4*)(QKV + base_kv + 2 * D_ + (size_t)row * 3072 + c);
        }
        {
            int r = tid >> 2;
            int qd = tid & 3;
            float* Pr = Pf + r * 68 + qd * 16;
            uint32_t* Pru = Pu + r * 68 + qd * 16;
            float vals[16];
#pragma unroll
            for (int j = 0; j < 16; j++) vals[j] = Pr[j];
            float mx = -1e30f;
#pragma unroll
            for (int j = 0; j < 16; j++) mx = fmaxf(mx, vals[j]);
            mx = fmaxf(mx, __shfl_xor_sync(0xffffffffu, mx, 1));
            mx = fmaxf(mx, __shfl_xor_sync(0xffffffffu, mx, 2));
            float mold = m_s[r];
            mx = fmaxf(mx, mold);
            float sum = 0.f;
#pragma unroll
            for (int j = 0; j < 16; j++) {
                float e = __expf(vals[j] - mx);
                Pru[j] = f2tf32(e);
                sum += e;
            }
            sum += __shfl_xor_sync(0xffffffffu, sum, 1);
            sum += __shfl_xor_sync(0xffffffffu, sum, 2);
            if (qd == 0) {
                float al = __expf(mold - mx);
                l_s[r] = l_s[r] * al + sum;
                m_s[r] = mx;
                a_s[r] = al;
            }
        }
        __syncthreads();

        float al0 = a_s[m0 + g], al1 = a_s[m0 + 8 + g];
#pragma unroll
        for (int nj = 0; nj < 4; nj++) {
            acc_o[nj][0] *= al0; acc_o[nj][1] *= al0;
            acc_o[nj][2] *= al1; acc_o[nj][3] *= al1;
        }
#pragma unroll
        for (int k8 = 0; k8 < 8; k8++) {
            int kc = k8 * 8 + t4;
            uint32_t a0 = Pu[(m0 + g) * 68 + kc];
            uint32_t a1 = Pu[(m0 + 8 + g) * 68 + kc];
            uint32_t a2 = Pu[(m0 + g) * 68 + kc + 4];
            uint32_t a3 = Pu[(m0 + 8 + g) * 68 + kc + 4];
#pragma unroll
            for (int nj = 0; nj < 4; nj++) {
                int hc = n0 + nj * 8 + g;
                uint32_t b0 = KVs[kc * 72 + hc];
                uint32_t b1 = KVs[(kc + 4) * 72 + hc];
                mma_tf32(acc_o[nj], a0, a1, a2, a3, b0, b1);
            }
        }
        __syncthreads();
    }

    float inv0 = 1.f / l_s[m0 + g];
    float inv1 = 1.f / l_s[m0 + 8 + g];
    size_t base_o = ((size_t)(b * S_ + q0)) * D_ + h * 64;
#pragma unroll
    for (int nj = 0; nj < 4; nj++) {
        int cc = n0 + nj * 8 + t4 * 2;
        uint2 u0 = make_uint2(f2tf32(acc_o[nj][0] * inv0), f2tf32(acc_o[nj][1] * inv0));
        uint2 u1 = make_uint2(f2tf32(acc_o[nj][2] * inv1), f2tf32(acc_o[nj][3] * inv1));
        *(uint2*)(O32 + base_o + (size_t)(m0 + g) * D_ + cc) = u0;
        *(uint2*)(O32 + base_o + (size_t)(m0 + 8 + g) * D_ + cc) = u1;
    }
}

// ---------------------------------------------------------------------------
// Fused residual + LayerNorm
// ---------------------------------------------------------------------------
template <bool WT>
__global__ __launch_bounds__(256) void ln_kernel(const float* __restrict__ res,
                                                 const float* __restrict__ delta,
                                                 const float* __restrict__ gamma,
                                                 const float* __restrict__ beta,
                                                 float* __restrict__ out,
                                                 uint32_t* __restrict__ out32) {
    int row = blockIdx.x, tid = threadIdx.x;
    size_t base = (size_t)row * D_;
    float4 rv = *(const float4*)(res + base + tid * 4);
    float4 dv = *(const float4*)(delta + base + tid * 4);
    float v0 = rv.x + dv.x, v1 = rv.y + dv.y, v2 = rv.z + dv.z, v3 = rv.w + dv.w;
    float s = v0 + v1 + v2 + v3;
    float q = v0 * v0 + v1 * v1 + v2 * v2 + v3 * v3;
#pragma unroll
    for (int o2 = 16; o2 > 0; o2 >>= 1) {
        s += __shfl_xor_sync(0xffffffffu, s, o2);
        q += __shfl_xor_sync(0xffffffffu, q, o2);
    }
    __shared__ float ss[8], qs[8];
    __shared__ float mean_s, rstd_s;
    if ((tid & 31) == 0) { ss[tid >> 5] = s; qs[tid >> 5] = q; }
    __syncthreads();
    if (tid == 0) {
        float S2 = 0.f, Q2 = 0.f;
#pragma unroll
        for (int w = 0; w < 8; w++) { S2 += ss[w]; Q2 += qs[w]; }
        float mean = S2 * (1.0f / D_);
        float var = Q2 * (1.0f / D_) - mean * mean;
        mean_s = mean;
        rstd_s = rsqrtf(var + 1e-5f);
    }
    __syncthreads();
    float mean = mean_s, rstd = rstd_s;
    float4 gv = *(const float4*)(gamma + tid * 4);
    float4 bv = *(const float4*)(beta + tid * 4);
    float4 ov;
    ov.x = (v0 - mean) * rstd * gv.x + bv.x;
    ov.y = (v1 - mean) * rstd * gv.y + bv.y;
    ov.z = (v2 - mean) * rstd * gv.z + bv.z;
    ov.w = (v3 - mean) * rstd * gv.w + bv.w;
    *(float4*)(out + base + tid * 4) = ov;
    if (WT) {
        uint4 u;
        u.x = f2tf32(ov.x); u.y = f2tf32(ov.y); u.z = f2tf32(ov.z); u.w = f2tf32(ov.w);
        *(uint4*)(out32 + base + tid * 4) = u;
    }
}

// ---------------------------------------------------------------------------
// Fused gather for both local branches into one 3072-row buffer:
// rows [0,2048):   local2 row b*512+sl  <- x token b*1024 + 512 + sl
// rows [2048,3072): local4 row b*256+sl <- x token b*1024 + 768 + sl
// ---------------------------------------------------------------------------
__global__ __launch_bounds__(256) void gather_fused_kernel(const float* __restrict__ x,
                                                           float* __restrict__ xs,
                                                           uint32_t* __restrict__ xs32) {
    int row = blockIdx.x;          // 0..3071
    int c = threadIdx.x;           // 0..255 float4
    int tok;
    if (row < 2048) {
        int b = row >> 9, sl = row & 511;
        tok = b * S_ + 512 + sl;
    } else {
        int r2 = row - 2048;
        int b = r2 >> 8, sl = r2 & 255;
        tok = b * S_ + 768 + sl;
    }
    float4 v = ((const float4*)x)[((size_t)tok << 8) + c];
    size_t di = ((size_t)row << 8) + c;
    ((float4*)xs)[di] = v;
    uint4 u;
    u.x = f2tf32(v.x); u.y = f2tf32(v.y); u.z = f2tf32(v.z); u.w = f2tf32(v.w);
    ((uint4*)xs32)[di] = u;
}

// output = g + pad(local2) + pad(local4), reading fused y24 buffer
__global__ __launch_bounds__(256) void combine_kernel(const float* __restrict__ g,
                                                      const float* __restrict__ y24,
                                                      float* __restrict__ out,
                                                      uint32_t* __restrict__ out32) {
    int i = blockIdx.x * 256 + threadIdx.x;
    int row = i >> 8;
    int c = i & 255;
    int b = row >> 10;
    int s = row & 1023;
    float4 v = ((const float4*)g)[i];
    if (s >= 512) {
        float4 a = ((const float4*)y24)[((size_t)(b * 512 + (s - 512)) << 8) + c];
        v.x += a.x; v.y += a.y; v.z += a.z; v.w += a.w;
    }
    if (s >= 768) {
        float4 a = ((const float4*)y24)[((size_t)(2048 + b * 256 + (s - 768)) << 8) + c];
        v.x += a.x; v.y += a.y; v.z += a.z; v.w += a.w;
    }
    ((float4*)out)[i] = v;
    uint4 u;
    u.x = f2tf32(v.x); u.y = f2tf32(v.y); u.z = f2tf32(v.z); u.w = f2tf32(v.w);
    ((uint4*)out32)[i] = u;
}

// ---------------------------------------------------------------------------
// Host orchestration
// ---------------------------------------------------------------------------
enum GemmOut { OUT_F32, OUT_TF32 };

static void launch_gemm(const uint32_t* A, const uint32_t* W, const float* bias,
                        float* C, uint32_t* C32, int M, int N, int K,
                        bool relu, GemmOut mode) {
    dim3 grid(N / BN, M / BM);
    if (mode == OUT_F32) {
        tc_gemm_kernel<false, true, false><<<grid, 256, GEMM_SMEM_BYTES>>>(A, W, bias, C, C32, M, N, K);
    } else if (relu) {
        tc_gemm_kernel<true, false, true><<<grid, 256, GEMM_SMEM_BYTES>>>(A, W, bias, C, C32, M, N, K);
    } else {
        tc_gemm_kernel<false, false, true><<<grid, 256, GEMM_SMEM_BYTES>>>(A, W, bias, C, C32, M, N, K);
    }
}

static void launch_cvt(const float* src, uint32_t* dst, int n) {
    cvtw_kernel<<<n / 1024, 256>>>((const float4*)src, (uint4*)dst, n / 4);
}

extern "C" void kernel_launch(void* const* d_in, const int* in_sizes, int n_in,
                              void* d_out, int out_size) {
    (void)in_sizes; (void)n_in; (void)out_size;
    const float* x    = (const float*)d_in[0];
    const float* Wq   = (const float*)d_in[1];
    const float* bq   = (const float*)d_in[2];
    const float* Wk   = (const float*)d_in[3];
    const float* bk   = (const float*)d_in[4];
    const float* Wv   = (const float*)d_in[5];
    const float* bv   = (const float*)d_in[6];
    const float* Wo   = (const float*)d_in[7];
    const float* bo   = (const float*)d_in[8];
    const float* W1   = (const float*)d_in[9];
    const float* b1   = (const float*)d_in[10];
    const float* W2   = (const float*)d_in[11];
    const float* b2   = (const float*)d_in[12];
    const float* n1s  = (const float*)d_in[13];
    const float* n1b  = (const float*)d_in[14];
    const float* n2s  = (const float*)d_in[15];
    const float* n2b  = (const float*)d_in[16];
    const float* ln1s = (const float*)d_in[17];
    const float* ln1b = (const float*)d_in[18];
    const float* ln2s = (const float*)d_in[19];
    const float* ln2b = (const float*)d_in[20];
    const float* ln3s = (const float*)d_in[21];
    const float* ln3b = (const float*)d_in[22];
    const float* Wb   = (const float*)d_in[23];
    const float* bb   = (const float*)d_in[24];
    const float* Wm   = (const float*)d_in[25];
    const float* bm   = (const float*)d_in[26];
    const float* Wf1  = (const float*)d_in[27];
    const float* bf1  = (const float*)d_in[28];
    const float* Wf2  = (const float*)d_in[29];
    const float* bf2  = (const float*)d_in[30];
    float* out = (float*)d_out;

    float *g, *q, *xs, *mo, *y24, *os, *h, *bqkv;
    uint32_t *tg, *tos, *tao, *tqkv, *txs, *tmid, *tff;
    uint32_t *twqkv, *two, *tw1, *tw2, *twb, *twm, *twf1, *twf2;
    cudaGetSymbolAddress((void**)&g,  g_g);
    cudaGetSymbolAddress((void**)&q,  g_q);
    cudaGetSymbolAddress((void**)&xs, g_xs);
    cudaGetSymbolAddress((void**)&mo, g_mo);
    cudaGetSymbolAddress((void**)&y24, g_y24);
    cudaGetSymbolAddress((void**)&os, g_os);
    cudaGetSymbolAddress((void**)&h,  g_h);
    cudaGetSymbolAddress((void**)&tg,  t_g);
    cudaGetSymbolAddress((void**)&tos, t_os);
    cudaGetSymbolAddress((void**)&tao, t_ao);
    cudaGetSymbolAddress((void**)&tqkv, t_qkv);
    cudaGetSymbolAddress((void**)&txs, t_xs);
    cudaGetSymbolAddress((void**)&tmid, t_mid);
    cudaGetSymbolAddress((void**)&tff, t_ff);
    cudaGetSymbolAddress((void**)&twqkv, t_Wqkv);
    cudaGetSymbolAddress((void**)&bqkv, b_qkv);
    cudaGetSymbolAddress((void**)&two, t_Wo);
    cudaGetSymbolAddress((void**)&tw1, t_W1);
    cudaGetSymbolAddress((void**)&tw2, t_W2);
    cudaGetSymbolAddress((void**)&twb, t_Wb);
    cudaGetSymbolAddress((void**)&twm, t_Wm);
    cudaGetSymbolAddress((void**)&twf1, t_Wf1);
    cudaGetSymbolAddress((void**)&twf2, t_Wf2);

    cudaFuncSetAttribute(attn_tc_kernel, cudaFuncAttributeMaxDynamicSharedMemorySize, AT_SMEM_BYTES);
    cudaFuncSetAttribute(tc_gemm_kernel<false, true, false>,
                         cudaFuncAttributeMaxDynamicSharedMemorySize, GEMM_SMEM_BYTES);
    cudaFuncSetAttribute(tc_gemm_kernel<true, false, true>,
                         cudaFuncAttributeMaxDynamicSharedMemorySize, GEMM_SMEM_BYTES);
    cudaFuncSetAttribute(tc_gemm_kernel<false, false, true>,
                         cudaFuncAttributeMaxDynamicSharedMemorySize, GEMM_SMEM_BYTES);

    // ---- weight conversions (once per launch) ----
    cvtw_qkv_kernel<<<(L_ * D_ * D_ / 4) / 256, 256>>>(
        (const float4*)Wq, (const float4*)Wk, (const float4*)Wv, (uint4*)twqkv);
    pack_bqkv_kernel<<<(L_ * 3 * D_ + 255) / 256, 256>>>(bq, bk, bv, bqkv);
    launch_cvt(Wo, two, L_ * D_ * D_);
    launch_cvt(W1, tw1, L_ * D_ * F_);
    launch_cvt(W2, tw2, L_ * F_ * D_);
    launch_cvt(Wb, twb, D_ * M_);
    launch_cvt(Wm, twm, M_ * D_);
    launch_cvt(Wf1, twf1, D_ * F_);
    launch_cvt(Wf2, twf2, F_ * D_);

    // g = x (+ shadow)
    copyx_kernel<<<N_ * D_ / 4 / 256, 256>>>((const float4*)x, (float4*)g, (uint4*)tg, N_ * D_ / 4);

    const int DD = D_ * D_;
    const int DF = D_ * F_;
    for (int i = 0; i < L_; i++) {
        launch_gemm(tg, twqkv + (size_t)i * D_ * 3 * D_, bqkv + i * 3 * D_,
                    nullptr, tqkv, N_, 3 * D_, D_, false, OUT_TF32);
        attn_tc_kernel<<<dim3(B_ * H_, S_ / 64), 256, AT_SMEM_BYTES>>>(tqkv, tao);
        launch_gemm(tao, two + (size_t)i * DD, bo + i * D_, q, nullptr, N_, D_, D_, false, OUT_F32);
        ln_kernel<true><<<N_, 256>>>(g, q, n1s + i * D_, n1b + i * D_, g, tg);
        launch_gemm(tg, tw1 + (size_t)i * DF, b1 + i * F_, nullptr, tff, N_, F_, D_, true, OUT_TF32);
        launch_gemm(tff, tw2 + (size_t)i * DF, b2 + i * D_, q, nullptr, N_, D_, F_, false, OUT_F32);
        ln_kernel<true><<<N_, 256>>>(g, q, n2s + i * D_, n2b + i * D_, g, tg);
    }

    // fused local(2) + local(4): one 3072-row chain
    gather_fused_kernel<<<RL_, 256>>>(x, xs, txs);
    launch_gemm(txs, twb, bb, nullptr, tmid, RL_, M_, D_, false, OUT_TF32);
    launch_gemm(tmid, twm, bm, mo, nullptr, RL_, D_, M_, false, OUT_F32);
    ln_kernel<false><<<RL_, 256>>>(xs, mo, ln1s, ln1b, y24, nullptr);

    combine_kernel<<<N_ * D_ / 4 / 256, 256>>>(g, y24, os, tos);
    ln_kernel<false><<<N_, 256>>>(os, x, ln2s, ln2b, h, nullptr);
    launch_gemm(tos, twf1, bf1, nullptr, tff, N_, F_, D_, true, OUT_TF32);
    launch_gemm(tff, twf2, bf2, q, nullptr, N_, D_, F_, false, OUT_F32);
    ln_kernel<false><<<N_, 256>>>(h, q, ln3s, ln3b, out, nullptr);
}

// round 10
// speedup vs baseline: 3.2662x; 1.0686x over previous
#include <cuda_runtime.h>
#include <cstdint>
#include <cstddef>

// Problem constants
#define B_  4
#define S_  1024
#define D_  1024
#define F_  4096
#define M_  512
#define H_  16
#define HD_ 64
#define L_  2
#define N_  (B_ * S_)   // 4096 tokens
#define RL_ 3072        // fused local rows (2048 + 1024)

// ---------------------------------------------------------------------------
// Scratch buffers (static device globals; no runtime allocation)
// ---------------------------------------------------------------------------
__device__ float g_g [N_ * D_];
__device__ float g_q [N_ * D_];        // generic fp32 delta scratch
__device__ float g_xs [RL_ * D_];
__device__ float g_mo [RL_ * D_];
__device__ float g_y24[RL_ * D_];
__device__ float g_os[N_ * D_];
__device__ float g_h [N_ * D_];
// tf32 shadow buffers (row-major activations)
__device__ uint32_t t_g  [N_ * D_];
__device__ uint32_t t_os [N_ * D_];
__device__ uint32_t t_ao [N_ * D_];
__device__ uint32_t t_qkv[N_ * 3 * D_];
__device__ uint32_t t_xs [RL_ * D_];
__device__ uint32_t t_mid[RL_ * M_];
__device__ uint32_t t_ff [N_ * F_];
// tf32 weight copies (PERMUTED block layout, see cvtwp_kernel)
__device__ uint32_t t_Wqkv[L_ * D_ * 3 * D_];
__device__ float    b_qkv [L_ * 3 * D_];
__device__ uint32_t t_Wo [L_ * D_ * D_];
__device__ uint32_t t_W1 [L_ * D_ * F_];
__device__ uint32_t t_W2 [L_ * F_ * D_];
__device__ uint32_t t_Wb [D_ * M_];
__device__ uint32_t t_Wm [M_ * D_];
__device__ uint32_t t_Wf1[D_ * F_];
__device__ uint32_t t_Wf2[F_ * D_];

// ---------------------------------------------------------------------------
__device__ __forceinline__ uint32_t f2tf32(float f) {
    uint32_t r;
    asm("cvt.rna.tf32.f32 %0, %1;" : "=r"(r) : "f"(f));
    return r;
}

// Permuted block layout for weight W[K][N]:
// blocks of [16 k][256 n]; block (kt, bx) stored contiguously (4096 words) at
// base = (bx * (K/16) + kt) * 4096. Within a block, element (kl, nl):
//   k8=kl>>3, t4=kl&3, hik=(kl>>2)&1; ng=nl>>4, cc=nl&15, jj2=cc>>3, gg=cc&7
//   word = ((k8*16 + ng)*32 + gg*4 + t4)*4 + hik + 2*jj2
// Reader (per lane g,t4): uint4 at ((k8*16 + ng)*32 + g*4 + t4)*4 gives
// {b0,b1} for n-col ng*16+g and {b0,b1} for ng*16+8+g -> conflict-free LDS.128.
__device__ __forceinline__ int wperm_addr(int kl, int nl) {
    int k8 = kl >> 3, t4 = kl & 3, hik = (kl >> 2) & 1;
    int ng = nl >> 4, cc = nl & 15, jj2 = cc >> 3, gg = cc & 7;
    return (((k8 * 16 + ng) * 32) + gg * 4 + t4) * 4 + hik + 2 * jj2;
}

// fp32 [K][N] row-major -> permuted tf32 blocks
__global__ __launch_bounds__(256) void cvtwp_kernel(const float4* __restrict__ in,
                                                    uint32_t* __restrict__ out,
                                                    int K, int N) {
    int i = blockIdx.x * 256 + threadIdx.x;
    if (i >= K * (N >> 2)) return;
    int n0 = (i % (N >> 2)) << 2;
    int k  = i / (N >> 2);
    float4 v = in[i];
    int kt = k >> 4, kl = k & 15;
    int bx = n0 >> 8;
    int nkt = K >> 4;
    uint32_t* blk = out + ((size_t)bx * nkt + kt) * 4096;
    float vv[4] = {v.x, v.y, v.z, v.w};
#pragma unroll
    for (int j = 0; j < 4; j++)
        blk[wperm_addr(kl, (n0 & 255) + j)] = f2tf32(vv[j]);
}

// Pack Wq|Wk|Wv into per-layer [1024][3072] permuted blocks
__global__ __launch_bounds__(256) void cvtwp_qkv_kernel(const float4* __restrict__ wq,
                                                        const float4* __restrict__ wk,
                                                        const float4* __restrict__ wv,
                                                        uint32_t* __restrict__ out) {
    int i = blockIdx.x * 256 + threadIdx.x;      // over L*D*D/4
    if (i >= L_ * D_ * D_ / 4) return;
    int n0 = (i & 255) << 2;                     // 0..1020 within section
    int row = i >> 8;                            // l*1024 + k
    int l = row >> 10, k = row & 1023;
    int kt = k >> 4, kl = k & 15;
    const int nkt = 64;                          // K=1024
    uint32_t* outL = out + (size_t)l * D_ * 3 * D_;
    float4 vs[3] = {wq[i], wk[i], wv[i]};
#pragma unroll
    for (int s = 0; s < 3; s++) {
        int n_glob = s * 1024 + n0;
        int bx = n_glob >> 8;
        uint32_t* blk = outL + ((size_t)bx * nkt + kt) * 4096;
        float vv[4] = {vs[s].x, vs[s].y, vs[s].z, vs[s].w};
#pragma unroll
        for (int j = 0; j < 4; j++)
            blk[wperm_addr(kl, (n_glob & 255) + j)] = f2tf32(vv[j]);
    }
}

__global__ __launch_bounds__(256) void pack_bqkv_kernel(const float* __restrict__ bq,
                                                        const float* __restrict__ bk,
                                                        const float* __restrict__ bv,
                                                        float* __restrict__ o) {
    int i = blockIdx.x * 256 + threadIdx.x;
    if (i >= L_ * 3 * D_) return;
    int l = i / (3 * D_), j = i % (3 * D_);
    float v;
    if (j < D_)           v = bq[l * D_ + j];
    else if (j < 2 * D_)  v = bk[l * D_ + j - D_];
    else                  v = bv[l * D_ + j - 2 * D_];
    o[i] = v;
}

// x -> g (fp32) + t_g (tf32)
__global__ __launch_bounds__(256) void copyx_kernel(const float4* __restrict__ in,
                                                    float4* __restrict__ out,
                                                    uint4* __restrict__ out32, int n4) {
    int i = blockIdx.x * 256 + threadIdx.x;
    if (i < n4) {
        float4 v = in[i];
        out[i] = v;
        uint4 o;
        o.x = f2tf32(v.x); o.y = f2tf32(v.y); o.z = f2tf32(v.z); o.w = f2tf32(v.w);
        out32[i] = o;
    }
}

// ---------------------------------------------------------------------------
// TF32 tensor-core GEMM, cp.async pipeline, permuted-B weights.
// ---------------------------------------------------------------------------
#define BM 128
#define BN 256
#define BK 16
#define STAGES 3
#define A_STRIDE 20
#define A_WORDS (BM * A_STRIDE)             // 2560
#define B_WORDS 4096                        // one permuted block
#define STAGE_WORDS (A_WORDS + B_WORDS)     // 6656
#define GEMM_SMEM_BYTES (STAGES * STAGE_WORDS * 4)   // 79872

__device__ __forceinline__ void cp16(uint32_t dst_smem, const void* src) {
    asm volatile("cp.async.cg.shared.global [%0], [%1], 16;\n" :: "r"(dst_smem), "l"(src));
}

__device__ __forceinline__ void mma_tf32(float* c, uint32_t a0, uint32_t a1,
                                         uint32_t a2, uint32_t a3,
                                         uint32_t b0, uint32_t b1) {
    asm volatile(
        "mma.sync.aligned.m16n8k8.row.col.f32.tf32.tf32.f32 "
        "{%0,%1,%2,%3}, {%4,%5,%6,%7}, {%8,%9}, {%0,%1,%2,%3};"
        : "+f"(c[0]), "+f"(c[1]), "+f"(c[2]), "+f"(c[3])
        : "r"(a0), "r"(a1), "r"(a2), "r"(a3), "r"(b0), "r"(b1));
}

template <bool RELU, bool WF, bool WT>
__global__ __launch_bounds__(256, 1) void tc_gemm_kernel(
        const uint32_t* __restrict__ A, const uint32_t* __restrict__ W,
        const float* __restrict__ bias, float* __restrict__ C,
        uint32_t* __restrict__ C32, int M, int N, int K) {
    extern __shared__ __align__(16) uint32_t sm[];
    uint32_t smb = (uint32_t)__cvta_generic_to_shared(sm);

    int tid = threadIdx.x;
    int bx = blockIdx.x, by = blockIdx.y;
    int wid = tid >> 5, lane = tid & 31;
    int warp_m = wid >> 2;
    int warp_n = wid & 3;
    int g = lane >> 2, t4 = lane & 3;

    const uint32_t* Ag = A + (size_t)by * BM * K;
    const uint32_t* Wg = W + (size_t)bx * (K >> 4) * 4096;   // permuted blocks

    auto issue = [&](int s, int kt) {
        uint32_t base = smb + (uint32_t)(s * STAGE_WORDS) * 4u;
#pragma unroll
        for (int r = 0; r < 2; r++) {
            int c = tid + r * 256;
            int row = c >> 2, u = c & 3;
            cp16(base + (uint32_t)(row * A_STRIDE + u * 4) * 4u,
                 Ag + (size_t)row * K + kt + u * 4);
        }
        uint32_t baseB = base + (uint32_t)A_WORDS * 4u;
        const uint32_t* Wsrc = Wg + (size_t)(kt >> 4) * 4096;
#pragma unroll
        for (int r = 0; r < 4; r++) {           // contiguous 16KB block copy
            int c = tid + r * 256;
            cp16(baseB + (uint32_t)c * 16u, Wsrc + c * 4);
        }
        asm volatile("cp.async.commit_group;\n" ::);
    };

    float acc[4][8][4];
#pragma unroll
    for (int mi = 0; mi < 4; mi++)
#pragma unroll
        for (int nj = 0; nj < 8; nj++)
#pragma unroll
            for (int e = 0; e < 4; e++) acc[mi][nj][e] = 0.f;

    int nk = K / BK;
#pragma unroll
    for (int s = 0; s < STAGES - 1; s++) issue(s, s * BK);
    asm volatile("cp.async.wait_group %0;\n" :: "n"(STAGES - 2));
    __syncthreads();

    for (int t = 0; t < nk; t++) {
        int pf = t + STAGES - 1;
        if (pf < nk) issue(pf % STAGES, pf * BK);

        const uint32_t* As = sm + (t % STAGES) * STAGE_WORDS;
        const uint32_t* Bs = As + A_WORDS;

        // batched fragment loads for the full k-tile
        uint32_t af[2][4][4];
        uint4 bq[2][4];
#pragma unroll
        for (int k8 = 0; k8 < 2; k8++) {
            int acol = k8 * 8 + t4;
#pragma unroll
            for (int mi = 0; mi < 4; mi++) {
                int r = warp_m * 64 + mi * 16 + g;
                af[k8][mi][0] = As[r * A_STRIDE + acol];
                af[k8][mi][1] = As[(r + 8) * A_STRIDE + acol];
                af[k8][mi][2] = As[r * A_STRIDE + acol + 4];
                af[k8][mi][3] = As[(r + 8) * A_STRIDE + acol + 4];
            }
#pragma unroll
            for (int nq = 0; nq < 4; nq++)
                bq[k8][nq] = *(const uint4*)&Bs[(((k8 * 16) + warp_n * 4 + nq) * 32
                                                + g * 4 + t4) * 4];
        }
        // pure MMA stretch
#pragma unroll
        for (int k8 = 0; k8 < 2; k8++)
#pragma unroll
            for (int mi = 0; mi < 4; mi++)
#pragma unroll
                for (int nq = 0; nq < 4; nq++) {
                    mma_tf32(acc[mi][2 * nq],     af[k8][mi][0], af[k8][mi][1],
                             af[k8][mi][2], af[k8][mi][3], bq[k8][nq].x, bq[k8][nq].y);
                    mma_tf32(acc[mi][2 * nq + 1], af[k8][mi][0], af[k8][mi][1],
                             af[k8][mi][2], af[k8][mi][3], bq[k8][nq].z, bq[k8][nq].w);
                }

        asm volatile("cp.async.wait_group %0;\n" :: "n"(STAGES - 2));
        __syncthreads();
    }

    int row0 = by * BM + warp_m * 64;
    int col0 = bx * BN + warp_n * 64;
#pragma unroll
    for (int nj = 0; nj < 8; nj++) {
        int cc = col0 + nj * 8 + t4 * 2;
        float b0 = bias[cc], b1 = bias[cc + 1];
#pragma unroll
        for (int mi = 0; mi < 4; mi++) {
            int r = row0 + mi * 16 + g;
            float v00 = acc[mi][nj][0] + b0, v01 = acc[mi][nj][1] + b1;
            float v10 = acc[mi][nj][2] + b0, v11 = acc[mi][nj][3] + b1;
            if (RELU) {
                v00 = fmaxf(v00, 0.f); v01 = fmaxf(v01, 0.f);
                v10 = fmaxf(v10, 0.f); v11 = fmaxf(v11, 0.f);
            }
            if (WF) {
                *(float2*)(C + (size_t)r * N + cc) = make_float2(v00, v01);
                *(float2*)(C + (size_t)(r + 8) * N + cc) = make_float2(v10, v11);
            }
            if (WT) {
                uint2 u0 = make_uint2(f2tf32(v00), f2tf32(v01));
                uint2 u1 = make_uint2(f2tf32(v10), f2tf32(v11));
                *(uint2*)(C32 + (size_t)r * N + cc) = u0;
                *(uint2*)(C32 + (size_t)(r + 8) * N + cc) = u1;
            }
        }
    }
}

// ---------------------------------------------------------------------------
// TF32 tensor-core flash attention (unchanged from R9).
// ---------------------------------------------------------------------------
#define AT_Q_OFF   0
#define AT_KV_OFF  4352
#define AT_P_OFF   (4352 + 4608)
#define AT_AUX_OFF 13312
#define AT_SMEM_WORDS (13312 + 192)
#define AT_SMEM_BYTES (AT_SMEM_WORDS * 4)

__global__ __launch_bounds__(256) void attn_tc_kernel(const uint32_t* __restrict__ QKV,
                                                      uint32_t* __restrict__ O32) {
    extern __shared__ __align__(16) uint32_t smu[];
    uint32_t* Qs  = smu + AT_Q_OFF;
    uint32_t* KVs = smu + AT_KV_OFF;
    uint32_t* Pu  = smu + AT_P_OFF;
    float*    Pf  = (float*)Pu;
    float*    m_s = (float*)(smu + AT_AUX_OFF);
    float*    l_s = m_s + 64;
    float*    a_s = l_s + 64;

    int tid = threadIdx.x;
    int b = blockIdx.x >> 4, h = blockIdx.x & 15;
    int q0 = blockIdx.y * 64;
    int wid = tid >> 5, lane = tid & 31;
    int m0 = (wid >> 1) * 16;
    int n0 = (wid & 1) * 32;
    int g = lane >> 2, t4 = lane & 3;

    size_t base_q = ((size_t)(b * S_ + q0)) * 3072 + h * 64;
#pragma unroll
    for (int r = 0; r < 4; r++) {
        int idx = tid + r * 256;
        int row = idx >> 4, c = (idx & 15) * 4;
        *(uint4*)&Qs[row * 68 + c] = *(const uint4*)(QKV + base_q + (size_t)row * 3072 + c);
    }
    if (tid < 64) { m_s[tid] = -1e30f; l_s[tid] = 0.f; }

    float acc_o[4][4];
#pragma unroll
    for (int nj = 0; nj < 4; nj++)
#pragma unroll
        for (int e = 0; e < 4; e++) acc_o[nj][e] = 0.f;

    for (int kt = 0; kt < 16; kt++) {
        size_t base_kv = ((size_t)(b * S_ + kt * 64)) * 3072 + h * 64;
#pragma unroll
        for (int r = 0; r < 4; r++) {
            int idx = tid + r * 256;
            int row = idx >> 4, c = (idx & 15) * 4;
            *(uint4*)&KVs[row * 68 + c] =
                *(const uint4*)(QKV + base_kv + D_ + (size_t)row * 3072 + c);
        }
        __syncthreads();

        float acc_s[4][4];
#pragma unroll
        for (int nj = 0; nj < 4; nj++)
#pragma unroll
            for (int e = 0; e < 4; e++) acc_s[nj][e] = 0.f;
#pragma unroll
        for (int k8 = 0; k8 < 8; k8++) {
            int kc = k8 * 8 + t4;
            uint32_t a0 = Qs[(m0 + g) * 68 + kc];
            uint32_t a1 = Qs[(m0 + 8 + g) * 68 + kc];
            uint32_t a2 = Qs[(m0 + g) * 68 + kc + 4];
            uint32_t a3 = Qs[(m0 + 8 + g) * 68 + kc + 4];
#pragma unroll
            for (int nj = 0; nj < 4; nj++) {
                int key = n0 + nj * 8 + g;
                uint32_t b0 = KVs[key * 68 + kc];
                uint32_t b1 = KVs[key * 68 + kc + 4];
                mma_tf32(acc_s[nj], a0, a1, a2, a3, b0, b1);
            }
        }
#pragma unroll
        for (int nj = 0; nj < 4; nj++) {
            int cc = n0 + nj * 8 + t4 * 2;
            *(float2*)&Pf[(m0 + g) * 68 + cc] =
                make_float2(acc_s[nj][0] * 0.125f, acc_s[nj][1] * 0.125f);
            *(float2*)&Pf[(m0 + 8 + g) * 68 + cc] =
                make_float2(acc_s[nj][2] * 0.125f, acc_s[nj][3] * 0.125f);
        }
        __syncthreads();

#pragma unroll
        for (int r = 0; r < 4; r++) {
            int idx = tid + r * 256;
            int row = idx >> 4, c = (idx & 15) * 4;
            *(uint4*)&KVs[row * 72 + c] =
                *(const uint4*)(QKV + base_kv + 2 * D_ + (size_t)row * 3072 + c);
        }
        {
            int r = tid >> 2;
            int qd = tid & 3;
            float* Pr = Pf + r * 68 + qd * 16;
            uint32_t* Pru = Pu + r * 68 + qd * 16;
            float vals[16];
#pragma unroll
            for (int j = 0; j < 16; j++) vals[j] = Pr[j];
            float mx = -1e30f;
#pragma unroll
            for (int j = 0; j < 16; j++) mx = fmaxf(mx, vals[j]);
            mx = fmaxf(mx, __shfl_xor_sync(0xffffffffu, mx, 1));
            mx = fmaxf(mx, __shfl_xor_sync(0xffffffffu, mx, 2));
            float mold = m_s[r];
            mx = fmaxf(mx, mold);
            float sum = 0.f;
#pragma unroll
            for (int j = 0; j < 16; j++) {
                float e = __expf(vals[j] - mx);
                Pru[j] = f2tf32(e);
                sum += e;
            }
            sum += __shfl_xor_sync(0xffffffffu, sum, 1);
            sum += __shfl_xor_sync(0xffffffffu, sum, 2);
            if (qd == 0) {
                float al = __expf(mold - mx);
                l_s[r] = l_s[r] * al + sum;
                m_s[r] = mx;
                a_s[r] = al;
            }
        }
        __syncthreads();

        float al0 = a_s[m0 + g], al1 = a_s[m0 + 8 + g];
#pragma unroll
        for (int nj = 0; nj < 4; nj++) {
            acc_o[nj][0] *= al0; acc_o[nj][1] *= al0;
            acc_o[nj][2] *= al1; acc_o[nj][3] *= al1;
        }
#pragma unroll
        for (int k8 = 0; k8 < 8; k8++) {
            int kc = k8 * 8 + t4;
            uint32_t a0 = Pu[(m0 + g) * 68 + kc];
            uint32_t a1 = Pu[(m0 + 8 + g) * 68 + kc];
            uint32_t a2 = Pu[(m0 + g) * 68 + kc + 4];
            uint32_t a3 = Pu[(m0 + 8 + g) * 68 + kc + 4];
#pragma unroll
            for (int nj = 0; nj < 4; nj++) {
                int hc = n0 + nj * 8 + g;
                uint32_t b0 = KVs[kc * 72 + hc];
                uint32_t b1 = KVs[(kc + 4) * 72 + hc];
                mma_tf32(acc_o[nj], a0, a1, a2, a3, b0, b1);
            }
        }
        __syncthreads();
    }

    float inv0 = 1.f / l_s[m0 + g];
    float inv1 = 1.f / l_s[m0 + 8 + g];
    size_t base_o = ((size_t)(b * S_ + q0)) * D_ + h * 64;
#pragma unroll
    for (int nj = 0; nj < 4; nj++) {
        int cc = n0 + nj * 8 + t4 * 2;
        uint2 u0 = make_uint2(f2tf32(acc_o[nj][0] * inv0), f2tf32(acc_o[nj][1] * inv0));
        uint2 u1 = make_uint2(f2tf32(acc_o[nj][2] * inv1), f2tf32(acc_o[nj][3] * inv1));
        *(uint2*)(O32 + base_o + (size_t)(m0 + g) * D_ + cc) = u0;
        *(uint2*)(O32 + base_o + (size_t)(m0 + 8 + g) * D_ + cc) = u1;
    }
}

// ---------------------------------------------------------------------------
// Fused residual + LayerNorm
// ---------------------------------------------------------------------------
template <bool WT>
__global__ __launch_bounds__(256) void ln_kernel(const float* __restrict__ res,
                                                 const float* __restrict__ delta,
                                                 const float* __restrict__ gamma,
                                                 const float* __restrict__ beta,
                                                 float* __restrict__ out,
                                                 uint32_t* __restrict__ out32) {
    int row = blockIdx.x, tid = threadIdx.x;
    size_t base = (size_t)row * D_;
    float4 rv = *(const float4*)(res + base + tid * 4);
    float4 dv = *(const float4*)(delta + base + tid * 4);
    float v0 = rv.x + dv.x, v1 = rv.y + dv.y, v2 = rv.z + dv.z, v3 = rv.w + dv.w;
    float s = v0 + v1 + v2 + v3;
    float q = v0 * v0 + v1 * v1 + v2 * v2 + v3 * v3;
#pragma unroll
    for (int o2 = 16; o2 > 0; o2 >>= 1) {
        s += __shfl_xor_sync(0xffffffffu, s, o2);
        q += __shfl_xor_sync(0xffffffffu, q, o2);
    }
    __shared__ float ss[8], qs[8];
    __shared__ float mean_s, rstd_s;
    if ((tid & 31) == 0) { ss[tid >> 5] = s; qs[tid >> 5] = q; }
    __syncthreads();
    if (tid == 0) {
        float S2 = 0.f, Q2 = 0.f;
#pragma unroll
        for (int w = 0; w < 8; w++) { S2 += ss[w]; Q2 += qs[w]; }
        float mean = S2 * (1.0f / D_);
        float var = Q2 * (1.0f / D_) - mean * mean;
        mean_s = mean;
        rstd_s = rsqrtf(var + 1e-5f);
    }
    __syncthreads();
    float mean = mean_s, rstd = rstd_s;
    float4 gv = *(const float4*)(gamma + tid * 4);
    float4 bv = *(const float4*)(beta + tid * 4);
    float4 ov;
    ov.x = (v0 - mean) * rstd * gv.x + bv.x;
    ov.y = (v1 - mean) * rstd * gv.y + bv.y;
    ov.z = (v2 - mean) * rstd * gv.z + bv.z;
    ov.w = (v3 - mean) * rstd * gv.w + bv.w;
    *(float4*)(out + base + tid * 4) = ov;
    if (WT) {
        uint4 u;
        u.x = f2tf32(ov.x); u.y = f2tf32(ov.y); u.z = f2tf32(ov.z); u.w = f2tf32(ov.w);
        *(uint4*)(out32 + base + tid * 4) = u;
    }
}

// ---------------------------------------------------------------------------
// Fused gather for both local branches (rows [0,2048) = local2, [2048,3072) = local4)
// ---------------------------------------------------------------------------
__global__ __launch_bounds__(256) void gather_fused_kernel(const float* __restrict__ x,
                                                           float* __restrict__ xs,
                                                           uint32_t* __restrict__ xs32) {
    int row = blockIdx.x;
    int c = threadIdx.x;
    int tok;
    if (row < 2048) {
        int b = row >> 9, sl = row & 511;
        tok = b * S_ + 512 + sl;
    } else {
        int r2 = row - 2048;
        int b = r2 >> 8, sl = r2 & 255;
        tok = b * S_ + 768 + sl;
    }
    float4 v = ((const float4*)x)[((size_t)tok << 8) + c];
    size_t di = ((size_t)row << 8) + c;
    ((float4*)xs)[di] = v;
    uint4 u;
    u.x = f2tf32(v.x); u.y = f2tf32(v.y); u.z = f2tf32(v.z); u.w = f2tf32(v.w);
    ((uint4*)xs32)[di] = u;
}

// output = g + pad(local2) + pad(local4)
__global__ __launch_bounds__(256) void combine_kernel(const float* __restrict__ g,
                                                      const float* __restrict__ y24,
                                                      float* __restrict__ out,
                                                      uint32_t* __restrict__ out32) {
    int i = blockIdx.x * 256 + threadIdx.x;
    int row = i >> 8;
    int c = i & 255;
    int b = row >> 10;
    int s = row & 1023;
    float4 v = ((const float4*)g)[i];
    if (s >= 512) {
        float4 a = ((const float4*)y24)[((size_t)(b * 512 + (s - 512)) << 8) + c];
        v.x += a.x; v.y += a.y; v.z += a.z; v.w += a.w;
    }
    if (s >= 768) {
        float4 a = ((const float4*)y24)[((size_t)(2048 + b * 256 + (s - 768)) << 8) + c];
        v.x += a.x; v.y += a.y; v.z += a.z; v.w += a.w;
    }
    ((float4*)out)[i] = v;
    uint4 u;
    u.x = f2tf32(v.x); u.y = f2tf32(v.y); u.z = f2tf32(v.z); u.w = f2tf32(v.w);
    ((uint4*)out32)[i] = u;
}

// ---------------------------------------------------------------------------
// Host orchestration
// ---------------------------------------------------------------------------
enum GemmOut { OUT_F32, OUT_TF32 };

static void launch_gemm(const uint32_t* A, const uint32_t* W, const float* bias,
                        float* C, uint32_t* C32, int M, int N, int K,
                        bool relu, GemmOut mode, cudaStream_t st) {
    dim3 grid(N / BN, M / BM);
    if (mode == OUT_F32) {
        tc_gemm_kernel<false, true, false><<<grid, 256, GEMM_SMEM_BYTES, st>>>(A, W, bias, C, C32, M, N, K);
    } else if (relu) {
        tc_gemm_kernel<true, false, true><<<grid, 256, GEMM_SMEM_BYTES, st>>>(A, W, bias, C, C32, M, N, K);
    } else {
        tc_gemm_kernel<false, false, true><<<grid, 256, GEMM_SMEM_BYTES, st>>>(A, W, bias, C, C32, M, N, K);
    }
}

static void launch_cvtp(const float* src, uint32_t* dst, int K, int N, cudaStream_t st) {
    int n4 = K * N / 4;
    cvtwp_kernel<<<(n4 + 255) / 256, 256, 0, st>>>((const float4*)src, dst, K, N);
}

extern "C" void kernel_launch(void* const* d_in, const int* in_sizes, int n_in,
                              void* d_out, int out_size) {
    (void)in_sizes; (void)n_in; (void)out_size;
    const float* x    = (const float*)d_in[0];
    const float* Wq   = (const float*)d_in[1];
    const float* bq   = (const float*)d_in[2];
    const float* Wk   = (const float*)d_in[3];
    const float* bk   = (const float*)d_in[4];
    const float* Wv   = (const float*)d_in[5];
    const float* bv   = (const float*)d_in[6];
    const float* Wo   = (const float*)d_in[7];
    const float* bo   = (const float*)d_in[8];
    const float* W1   = (const float*)d_in[9];
    const float* b1   = (const float*)d_in[10];
    const float* W2   = (const float*)d_in[11];
    const float* b2   = (const float*)d_in[12];
    const float* n1s  = (const float*)d_in[13];
    const float* n1b  = (const float*)d_in[14];
    const float* n2s  = (const float*)d_in[15];
    const float* n2b  = (const float*)d_in[16];
    const float* ln1s = (const float*)d_in[17];
    const float* ln1b = (const float*)d_in[18];
    const float* ln2s = (const float*)d_in[19];
    const float* ln2b = (const float*)d_in[20];
    const float* ln3s = (const float*)d_in[21];
    const float* ln3b = (const float*)d_in[22];
    const float* Wb   = (const float*)d_in[23];
    const float* bb   = (const float*)d_in[24];
    const float* Wm   = (const float*)d_in[25];
    const float* bm   = (const float*)d_in[26];
    const float* Wf1  = (const float*)d_in[27];
    const float* bf1  = (const float*)d_in[28];
    const float* Wf2  = (const float*)d_in[29];
    const float* bf2  = (const float*)d_in[30];
    float* out = (float*)d_out;

    float *g, *q, *xs, *mo, *y24, *os, *h, *bqkv;
    uint32_t *tg, *tos, *tao, *tqkv, *txs, *tmid, *tff;
    uint32_t *twqkv, *two, *tw1, *tw2, *twb, *twm, *twf1, *twf2;
    cudaGetSymbolAddress((void**)&g,  g_g);
    cudaGetSymbolAddress((void**)&q,  g_q);
    cudaGetSymbolAddress((void**)&xs, g_xs);
    cudaGetSymbolAddress((void**)&mo, g_mo);
    cudaGetSymbolAddress((void**)&y24, g_y24);
    cudaGetSymbolAddress((void**)&os, g_os);
    cudaGetSymbolAddress((void**)&h,  g_h);
    cudaGetSymbolAddress((void**)&tg,  t_g);
    cudaGetSymbolAddress((void**)&tos, t_os);
    cudaGetSymbolAddress((void**)&tao, t_ao);
    cudaGetSymbolAddress((void**)&tqkv, t_qkv);
    cudaGetSymbolAddress((void**)&txs, t_xs);
    cudaGetSymbolAddress((void**)&tmid, t_mid);
    cudaGetSymbolAddress((void**)&tff, t_ff);
    cudaGetSymbolAddress((void**)&twqkv, t_Wqkv);
    cudaGetSymbolAddress((void**)&bqkv, b_qkv);
    cudaGetSymbolAddress((void**)&two, t_Wo);
    cudaGetSymbolAddress((void**)&tw1, t_W1);
    cudaGetSymbolAddress((void**)&tw2, t_W2);
    cudaGetSymbolAddress((void**)&twb, t_Wb);
    cudaGetSymbolAddress((void**)&twm, t_Wm);
    cudaGetSymbolAddress((void**)&twf1, t_Wf1);
    cudaGetSymbolAddress((void**)&twf2, t_Wf2);

    cudaFuncSetAttribute(attn_tc_kernel, cudaFuncAttributeMaxDynamicSharedMemorySize, AT_SMEM_BYTES);
    cudaFuncSetAttribute(tc_gemm_kernel<false, true, false>,
                         cudaFuncAttributeMaxDynamicSharedMemorySize, GEMM_SMEM_BYTES);
    cudaFuncSetAttribute(tc_gemm_kernel<true, false, true>,
                         cudaFuncAttributeMaxDynamicSharedMemorySize, GEMM_SMEM_BYTES);
    cudaFuncSetAttribute(tc_gemm_kernel<false, false, true>,
                         cudaFuncAttributeMaxDynamicSharedMemorySize, GEMM_SMEM_BYTES);

    // ---- fork a side stream inside capture (event-based, capture-legal) ----
    cudaStream_t side;
    cudaStreamCreateWithFlags(&side, cudaStreamNonBlocking);
    cudaEvent_t evFork, evCvt, evJoin;
    cudaEventCreateWithFlags(&evFork, cudaEventDisableTiming);
    cudaEventCreateWithFlags(&evCvt,  cudaEventDisableTiming);
    cudaEventCreateWithFlags(&evJoin, cudaEventDisableTiming);
    cudaEventRecord(evFork, 0);
    cudaStreamWaitEvent(side, evFork, 0);

    // ---- side stream: weight cvts (layer weights first), then locals chain ----
    launch_cvtp(Wo, two, D_, D_, side);           // layer 0 Wo... (both layers: K=L*D? no)
    launch_cvtp(Wo + D_ * D_, two + D_ * D_, D_, D_, side);
    launch_cvtp(W1, tw1, D_, F_, side);
    launch_cvtp(W1 + D_ * F_, tw1 + D_ * F_, D_, F_, side);
    launch_cvtp(W2, tw2, F_, D_, side);
    launch_cvtp(W2 + F_ * D_, tw2 + F_ * D_, F_, D_, side);
    cudaEventRecord(evCvt, side);
    launch_cvtp(Wf1, twf1, D_, F_, side);
    launch_cvtp(Wf2, twf2, F_, D_, side);
    launch_cvtp(Wb, twb, D_, M_, side);
    launch_cvtp(Wm, twm, M_, D_, side);
    // fused local(2)+local(4) chain entirely on side stream
    gather_fused_kernel<<<RL_, 256, 0, side>>>(x, xs, txs);
    launch_gemm(txs, twb, bb, nullptr, tmid, RL_, M_, D_, false, OUT_TF32, side);
    launch_gemm(tmid, twm, bm, mo, nullptr, RL_, D_, M_, false, OUT_F32, side);
    ln_kernel<false><<<RL_, 256, 0, side>>>(xs, mo, ln1s, ln1b, y24, nullptr);
    cudaEventRecord(evJoin, side);

    // ---- main stream ----
    cvtwp_qkv_kernel<<<(L_ * D_ * D_ / 4) / 256, 256>>>(
        (const float4*)Wq, (const float4*)Wk, (const float4*)Wv, twqkv);
    pack_bqkv_kernel<<<(L_ * 3 * D_ + 255) / 256, 256>>>(bq, bk, bv, bqkv);
    copyx_kernel<<<N_ * D_ / 4 / 256, 256>>>((const float4*)x, (float4*)g, (uint4*)tg, N_ * D_ / 4);

    const int DD = D_ * D_;
    const int DF = D_ * F_;
    for (int i = 0; i < L_; i++) {
        launch_gemm(tg, twqkv + (size_t)i * D_ * 3 * D_, bqkv + i * 3 * D_,
                    nullptr, tqkv, N_, 3 * D_, D_, false, OUT_TF32, 0);
        attn_tc_kernel<<<dim3(B_ * H_, S_ / 64), 256, AT_SMEM_BYTES>>>(tqkv, tao);
        if (i == 0) cudaStreamWaitEvent(0, evCvt, 0);   // Wo/W1/W2 cvts done
        launch_gemm(tao, two + (size_t)i * DD, bo + i * D_, q, nullptr, N_, D_, D_, false, OUT_F32, 0);
        ln_kernel<true><<<N_, 256>>>(g, q, n1s + i * D_, n1b + i * D_, g, tg);
        launch_gemm(tg, tw1 + (size_t)i * DF, b1 + i * F_, nullptr, tff, N_, F_, D_, true, OUT_TF32, 0);
        launch_gemm(tff, tw2 + (size_t)i * DF, b2 + i * D_, q, nullptr, N_, D_, F_, false, OUT_F32, 0);
        ln_kernel<true><<<N_, 256>>>(g, q, n2s + i * D_, n2b + i * D_, g, tg);
    }

    // join: locals result needed by combine
    cudaStreamWaitEvent(0, evJoin, 0);
    combine_kernel<<<N_ * D_ / 4 / 256, 256>>>(g, y24, os, tos);
    ln_kernel<false><<<N_, 256>>>(os, x, ln2s, ln2b, h, nullptr);
    launch_gemm(tos, twf1, bf1, nullptr, tff, N_, F_, D_, true, OUT_TF32, 0);
    launch_gemm(tff, twf2, bf2, q, nullptr, N_, D_, F_, false, OUT_F32, 0);
    ln_kernel<false><<<N_, 256>>>(h, q, ln3s, ln3b, out, nullptr);
}